// round 2
// baseline (speedup 1.0000x reference)
#include <cuda_runtime.h>
#include <math.h>
#include <stdint.h>

#define NN 20000
#define EE 320000
#define GG 64
#define INF_ 256
#define H1 512
#define H2C 256
#define HEADS 2
#define CC 16
#define NSTEPS 4
#define KT 4

// ---------------- scratch layout (floats) ----------------
constexpr size_t SZ_AH   = (size_t)NN * 1024;   // [a | h] per node
constexpr size_t SZ_SAGG = (size_t)NN * 2048;   // interleaved per-etype agg
constexpr size_t SZ_P    = (size_t)NN * 1024;   // r/z gate sums
constexpr size_t SZ_Q    = (size_t)NN * 512;

constexpr size_t OFF_AH    = 0;
constexpr size_t OFF_SAGG  = OFF_AH + SZ_AH;
constexpr size_t OFF_P     = OFF_SAGG + SZ_SAGG;
constexpr size_t OFF_QI    = OFF_P + SZ_P;
constexpr size_t OFF_QH    = OFF_QI + SZ_Q;
constexpr size_t OFF_W1    = OFF_QH + SZ_Q;                   // 1024x1024
constexpr size_t OFF_WNI   = OFF_W1 + 1024 * 1024;            // 512x512
constexpr size_t OFF_WNH   = OFF_WNI + 512 * 512;
constexpr size_t OFF_FCWT  = OFF_WNH + 512 * 512;
constexpr size_t OFF_FEAT  = OFF_FCWT + 512 * 512;            // NN x 512
constexpr size_t OFF_EL    = OFF_FEAT + SZ_Q;
constexpr size_t OFF_ER    = OFF_EL + (size_t)NN * HEADS;
constexpr size_t OFF_EEDGE = OFF_ER + (size_t)NN * HEADS;
constexpr size_t OFF_EEXP  = OFF_EEDGE + (size_t)EE * HEADS;
constexpr size_t OFF_EMAX  = OFF_EEXP + (size_t)EE * HEADS;   // uint storage
constexpr size_t OFF_DEN   = OFF_EMAX + (size_t)NN * HEADS;
constexpr size_t OFF_RST   = OFF_DEN + (size_t)NN * HEADS;    // NN x 512
constexpr size_t OFF_HG    = OFF_RST + SZ_Q;
constexpr size_t OFF_GCNT  = OFF_HG + (size_t)GG * H1;
constexpr size_t OFF_CNT   = OFF_GCNT + GG;                   // int storage NN*KT
constexpr size_t TOTAL_F   = OFF_CNT + (size_t)NN * KT;

__device__ __align__(16) float g_buf[TOTAL_F];

// ---------------- helpers ----------------
__device__ __forceinline__ float sigm(float x) { return 1.f / (1.f + expf(-x)); }

__device__ __forceinline__ unsigned fenc(float f) {
    unsigned u = __float_as_uint(f);
    return (u >> 31) ? ~u : (u | 0x80000000u);
}
__device__ __forceinline__ float fdec(unsigned u) {
    return (u >> 31) ? __uint_as_float(u & 0x7fffffffu) : __uint_as_float(~u);
}

__device__ __forceinline__ float to_tf32(float x) {
    float r;
    asm("cvt.rna.tf32.f32 %0, %1;" : "=f"(r) : "f"(x));
    return r;
}

// ---------------- generic kernels ----------------
__global__ void zero_f4(float4* p, size_t n4) {
    size_t i = (size_t)blockIdx.x * blockDim.x + threadIdx.x;
    size_t st = (size_t)gridDim.x * blockDim.x;
    for (; i < n4; i += st) p[i] = make_float4(0.f, 0.f, 0.f, 0.f);
}

__global__ void transpose_kernel(const float* __restrict__ in, float* __restrict__ out,
                                 int R, int C) {
    int i = blockIdx.x * blockDim.x + threadIdx.x;
    int tot = R * C;
    int st = gridDim.x * blockDim.x;
    for (; i < tot; i += st) {
        int r = i / C, c = i % C;
        out[(size_t)c * R + r] = in[i];
    }
}

__global__ void pad_kernel(const float* __restrict__ x, float* __restrict__ ah) {
    int i = blockIdx.x * blockDim.x + threadIdx.x;
    int st = gridDim.x * blockDim.x;
    int tot = NN * H1;
    for (; i < tot; i += st) {
        int c = i & (H1 - 1);
        int n = i >> 9;
        ah[(size_t)n * 1024 + 512 + c] = (c < INF_) ? x[(size_t)n * INF_ + c] : 0.f;
    }
}

// ---------------- tf32 split GEMM ----------------
// C[M,N] (+)= A[M,K] @ B[K,N]; A row stride lda, C row stride ldc, B row stride N.
// BM=128, BN=128, BK=16, 256 threads (8 warps, 2m x 4n), warp tile 64x32.
// Split each fp32 into tf32 hi+lo; 3-term mma for ~fp32 accuracy.
#define MMA_TF32(c, a, b)                                                        \
    asm volatile(                                                                \
        "mma.sync.aligned.m16n8k8.row.col.f32.tf32.tf32.f32 "                    \
        "{%0,%1,%2,%3}, {%4,%5,%6,%7}, {%8,%9}, {%0,%1,%2,%3};\n"                \
        : "+f"((c)[0]), "+f"((c)[1]), "+f"((c)[2]), "+f"((c)[3])                 \
        : "r"((a)[0]), "r"((a)[1]), "r"((a)[2]), "r"((a)[3]),                    \
          "r"((b)[0]), "r"((b)[1]))

__global__ __launch_bounds__(256, 1)
void gemm_tf32(const float* __restrict__ A, int lda, const float* __restrict__ B,
               float* __restrict__ C, int ldc, int M, int Kd, int Nd, int accum) {
    __shared__ float As_hi[128 * 20];
    __shared__ float As_lo[128 * 20];
    __shared__ float Bs_hi[16 * 136];
    __shared__ float Bs_lo[16 * 136];

    const int tid = threadIdx.x;
    const int lane = tid & 31;
    const int warp = tid >> 5;
    const int wm = warp >> 2;        // 0..1
    const int wn = warp & 3;         // 0..3
    const int gID = lane >> 2;       // 0..7
    const int tig = lane & 3;        // 0..3

    const int blockM = blockIdx.y * 128;
    const int blockN = blockIdx.x * 128;

    // global load mapping
    const int aRow = tid >> 1;              // 0..127
    const int aCol = (tid & 1) * 8;         // 0 or 8
    const int bRow = tid >> 4;              // 0..15
    const int bCol = (tid & 15) * 8;        // 0..120

    const int gARow = blockM + aRow;
    const float* Aptr = A + (size_t)gARow * lda + aCol;
    const float* Bptr = B + (size_t)bRow * Nd + blockN + bCol;

    float acc[4][4][4];
#pragma unroll
    for (int mi = 0; mi < 4; mi++)
#pragma unroll
        for (int ni = 0; ni < 4; ni++)
#pragma unroll
            for (int q = 0; q < 4; q++) acc[mi][ni][q] = 0.f;

    const int kIters = Kd >> 4;

    float4 rA0, rA1, rB0, rB1;
    // preload iter 0
    {
        if (gARow < M) {
            rA0 = *(const float4*)(Aptr);
            rA1 = *(const float4*)(Aptr + 4);
        } else {
            rA0 = make_float4(0.f, 0.f, 0.f, 0.f);
            rA1 = rA0;
        }
        rB0 = *(const float4*)(Bptr);
        rB1 = *(const float4*)(Bptr + 4);
    }

    for (int it = 0; it < kIters; it++) {
        // ---- STS with hi/lo split ----
        {
            float va[8] = {rA0.x, rA0.y, rA0.z, rA0.w, rA1.x, rA1.y, rA1.z, rA1.w};
            float hi[8], lo[8];
#pragma unroll
            for (int j = 0; j < 8; j++) {
                hi[j] = to_tf32(va[j]);
                lo[j] = to_tf32(va[j] - hi[j]);
            }
            float* ph = &As_hi[aRow * 20 + aCol];
            float* pl = &As_lo[aRow * 20 + aCol];
            *(float4*)ph = make_float4(hi[0], hi[1], hi[2], hi[3]);
            *(float4*)(ph + 4) = make_float4(hi[4], hi[5], hi[6], hi[7]);
            *(float4*)pl = make_float4(lo[0], lo[1], lo[2], lo[3]);
            *(float4*)(pl + 4) = make_float4(lo[4], lo[5], lo[6], lo[7]);

            float vb[8] = {rB0.x, rB0.y, rB0.z, rB0.w, rB1.x, rB1.y, rB1.z, rB1.w};
#pragma unroll
            for (int j = 0; j < 8; j++) {
                hi[j] = to_tf32(vb[j]);
                lo[j] = to_tf32(vb[j] - hi[j]);
            }
            ph = &Bs_hi[bRow * 136 + bCol];
            pl = &Bs_lo[bRow * 136 + bCol];
            *(float4*)ph = make_float4(hi[0], hi[1], hi[2], hi[3]);
            *(float4*)(ph + 4) = make_float4(hi[4], hi[5], hi[6], hi[7]);
            *(float4*)pl = make_float4(lo[0], lo[1], lo[2], lo[3]);
            *(float4*)(pl + 4) = make_float4(lo[4], lo[5], lo[6], lo[7]);
        }
        __syncthreads();

        // ---- prefetch next tile ----
        if (it + 1 < kIters) {
            int k0 = (it + 1) << 4;
            if (gARow < M) {
                rA0 = *(const float4*)(Aptr + k0);
                rA1 = *(const float4*)(Aptr + k0 + 4);
            }
            rB0 = *(const float4*)(Bptr + (size_t)k0 * Nd);
            rB1 = *(const float4*)(Bptr + (size_t)k0 * Nd + 4);
        }

        // ---- compute: 2 k8 sub-steps ----
#pragma unroll
        for (int k8 = 0; k8 < 16; k8 += 8) {
            uint32_t a_hi[4][4], a_lo[4][4], b_hi[4][2], b_lo[4][2];
#pragma unroll
            for (int mi = 0; mi < 4; mi++) {
                int r0 = (wm * 64 + mi * 16 + gID) * 20 + k8 + tig;
                a_hi[mi][0] = __float_as_uint(As_hi[r0]);
                a_hi[mi][1] = __float_as_uint(As_hi[r0 + 8 * 20]);
                a_hi[mi][2] = __float_as_uint(As_hi[r0 + 4]);
                a_hi[mi][3] = __float_as_uint(As_hi[r0 + 8 * 20 + 4]);
                a_lo[mi][0] = __float_as_uint(As_lo[r0]);
                a_lo[mi][1] = __float_as_uint(As_lo[r0 + 8 * 20]);
                a_lo[mi][2] = __float_as_uint(As_lo[r0 + 4]);
                a_lo[mi][3] = __float_as_uint(As_lo[r0 + 8 * 20 + 4]);
            }
#pragma unroll
            for (int ni = 0; ni < 4; ni++) {
                int c0 = (k8 + tig) * 136 + wn * 32 + ni * 8 + gID;
                b_hi[ni][0] = __float_as_uint(Bs_hi[c0]);
                b_hi[ni][1] = __float_as_uint(Bs_hi[c0 + 4 * 136]);
                b_lo[ni][0] = __float_as_uint(Bs_lo[c0]);
                b_lo[ni][1] = __float_as_uint(Bs_lo[c0 + 4 * 136]);
            }
#pragma unroll
            for (int mi = 0; mi < 4; mi++)
#pragma unroll
                for (int ni = 0; ni < 4; ni++) {
                    MMA_TF32(acc[mi][ni], a_hi[mi], b_hi[ni]);
                    MMA_TF32(acc[mi][ni], a_hi[mi], b_lo[ni]);
                    MMA_TF32(acc[mi][ni], a_lo[mi], b_hi[ni]);
                }
        }
        __syncthreads();
    }

    // ---- epilogue ----
#pragma unroll
    for (int mi = 0; mi < 4; mi++) {
        int r0 = blockM + wm * 64 + mi * 16 + gID;
        int r1 = r0 + 8;
#pragma unroll
        for (int ni = 0; ni < 4; ni++) {
            int cbase = blockN + wn * 32 + ni * 8 + 2 * tig;
            if (r0 < M) {
                float* cp = C + (size_t)r0 * ldc + cbase;
                if (accum) {
                    cp[0] += acc[mi][ni][0];
                    cp[1] += acc[mi][ni][1];
                } else {
                    cp[0] = acc[mi][ni][0];
                    cp[1] = acc[mi][ni][1];
                }
            }
            if (r1 < M) {
                float* cp = C + (size_t)r1 * ldc + cbase;
                if (accum) {
                    cp[0] += acc[mi][ni][2];
                    cp[1] += acc[mi][ni][3];
                } else {
                    cp[0] = acc[mi][ni][2];
                    cp[1] = acc[mi][ni][3];
                }
            }
        }
    }
}

// ---------------- message aggregation: sagg[dst][k*512+c] += h[src][c] ----------------
__global__ void aggregate_kernel(const float* __restrict__ ah,
                                 const int* __restrict__ src, const int* __restrict__ dst,
                                 const int* __restrict__ et,
                                 float* __restrict__ sagg, int* __restrict__ cnt) {
    int e = blockIdx.x;
    int s = src[e], d = dst[e], k = et[e];
    if (threadIdx.x == 0) atomicAdd(&cnt[d * KT + k], 1);
    const float* hv = ah + (size_t)s * 1024 + 512;
    float* out = sagg + (size_t)d * 2048 + k * 512;
    int c = threadIdx.x * 4;  // 128 threads * 4 = 512
    float4 v = *(const float4*)(hv + c);
    atomicAdd(&out[c + 0], v.x);
    atomicAdd(&out[c + 1], v.y);
    atomicAdd(&out[c + 2], v.z);
    atomicAdd(&out[c + 3], v.w);
}

// a[n][c] = sum_k cnt[n][k] * bmsg[k][c]   (writes the 'a' half of ah)
__global__ void bias_a_kernel(const float* __restrict__ bmsg, const int* __restrict__ cnt,
                              float* __restrict__ ah) {
    int n = blockIdx.x;
    __shared__ float bm[KT * H1];
    for (int i = threadIdx.x; i < KT * H1; i += blockDim.x) bm[i] = bmsg[i];
    __shared__ int cn[KT];
    if (threadIdx.x < KT) cn[threadIdx.x] = cnt[n * KT + threadIdx.x];
    __syncthreads();
    float c0 = (float)cn[0], c1 = (float)cn[1], c2 = (float)cn[2], c3 = (float)cn[3];
    for (int c = threadIdx.x; c < H1; c += blockDim.x)
        ah[(size_t)n * 1024 + c] =
            c0 * bm[c] + c1 * bm[H1 + c] + c2 * bm[2 * H1 + c] + c3 * bm[3 * H1 + c];
}

// ---------------- GRU pointwise ----------------
__global__ void gru_kernel(const float* __restrict__ P, const float* __restrict__ Qi,
                           const float* __restrict__ Qh,
                           const float* __restrict__ b_ih, const float* __restrict__ b_hh,
                           float* __restrict__ ah) {
    int i = blockIdx.x * blockDim.x + threadIdx.x;
    int st = gridDim.x * blockDim.x;
    int tot = NN * H1;
    for (; i < tot; i += st) {
        int n = i >> 9, c = i & (H1 - 1);
        float r = sigm(P[(size_t)n * 1024 + c] + b_ih[c] + b_hh[c]);
        float z = sigm(P[(size_t)n * 1024 + 512 + c] + b_ih[512 + c] + b_hh[512 + c]);
        float nn = tanhf(Qi[(size_t)n * 512 + c] + b_ih[1024 + c] +
                         r * (Qh[(size_t)n * 512 + c] + b_hh[1024 + c]));
        float* hp = &ah[(size_t)n * 1024 + 512 + c];
        *hp = (1.f - z) * nn + z * *hp;
    }
}

// ---------------- L2 normalize + sigmoid (per node, on h part of ah) ----------------
__global__ void norm_sig_kernel(float* __restrict__ ah) {
    int n = blockIdx.x;
    int t = threadIdx.x;
    float* row = ah + (size_t)n * 1024 + 512;
    float s = 0.f;
    for (int c = t; c < H1; c += 128) {
        float v = row[c];
        s += v * v;
    }
    __shared__ float sm[128];
    sm[t] = s;
    __syncthreads();
    for (int o = 64; o > 0; o >>= 1) {
        if (t < o) sm[t] += sm[t + o];
        __syncthreads();
    }
    float inv = 1.f / fmaxf(sqrtf(sm[0]), 1e-12f);
    for (int c = t; c < H1; c += 128) row[c] = sigm(row[c] * inv);
}

// ---------------- el/er per node per head ----------------
__global__ void elr_kernel(const float* __restrict__ feat, const float* __restrict__ attn_l,
                           const float* __restrict__ attn_r,
                           float* __restrict__ el, float* __restrict__ er) {
    int n = blockIdx.x;
    int t = threadIdx.x;  // 256
    float f0 = feat[(size_t)n * H1 + t];
    float f1 = feat[(size_t)n * H1 + H2C + t];
    float vals[4] = {f0 * attn_l[t], f0 * attn_r[t], f1 * attn_l[H2C + t], f1 * attn_r[H2C + t]};
    float outp[4];
    __shared__ float sm[256];
#pragma unroll
    for (int q = 0; q < 4; q++) {
        sm[t] = vals[q];
        __syncthreads();
        for (int o = 128; o > 0; o >>= 1) {
            if (t < o) sm[t] += sm[t + o];
            __syncthreads();
        }
        outp[q] = sm[0];
        __syncthreads();
    }
    if (t == 0) {
        el[n * 2] = outp[0];
        er[n * 2] = outp[1];
        el[n * 2 + 1] = outp[2];
        er[n * 2 + 1] = outp[3];
    }
}

// ---------------- edge softmax passes ----------------
__global__ void edge_max_kernel(const int* __restrict__ src, const int* __restrict__ dst,
                                const float* __restrict__ el, const float* __restrict__ er,
                                float* __restrict__ eedge, unsigned* __restrict__ emax) {
    int e = blockIdx.x * blockDim.x + threadIdx.x;
    if (e >= EE) return;
    int s = src[e], d = dst[e];
#pragma unroll
    for (int hd = 0; hd < HEADS; hd++) {
        float v = el[s * 2 + hd] + er[d * 2 + hd];
        v = v > 0.f ? v : 0.2f * v;
        eedge[e * 2 + hd] = v;
        atomicMax(&emax[d * 2 + hd], fenc(v));
    }
}

__global__ void edge_exp_kernel(const int* __restrict__ dst, const float* __restrict__ eedge,
                                const unsigned* __restrict__ emax,
                                float* __restrict__ eexp, float* __restrict__ den) {
    int e = blockIdx.x * blockDim.x + threadIdx.x;
    if (e >= EE) return;
    int d = dst[e];
#pragma unroll
    for (int hd = 0; hd < HEADS; hd++) {
        float ee = expf(eedge[e * 2 + hd] - fdec(emax[d * 2 + hd]));
        eexp[e * 2 + hd] = ee;
        atomicAdd(&den[d * 2 + hd], ee);
    }
}

__global__ void edge_scatter_kernel(const int* __restrict__ src, const int* __restrict__ dst,
                                    const float* __restrict__ eexp, const float* __restrict__ den,
                                    const float* __restrict__ feat, float* __restrict__ rst) {
    int e = blockIdx.x;
    int s = src[e], d = dst[e];
    float a0 = eexp[e * 2] / den[d * 2];
    float a1 = eexp[e * 2 + 1] / den[d * 2 + 1];
    const float* f = feat + (size_t)s * H1;
    float* r = rst + (size_t)d * H1;
    int c = threadIdx.x * 4;  // 128 * 4 = 512
    float al = (c < H2C) ? a0 : a1;
    float4 v = *(const float4*)(f + c);
    atomicAdd(&r[c + 0], al * v.x);
    atomicAdd(&r[c + 1], al * v.y);
    atomicAdd(&r[c + 2], al * v.z);
    atomicAdd(&r[c + 3], al * v.w);
}

// ---------------- graph mean + classify ----------------
__global__ void gcnt_kernel(const int* __restrict__ gid, float* __restrict__ gcnt) {
    int n = blockIdx.x * blockDim.x + threadIdx.x;
    if (n < NN) atomicAdd(&gcnt[gid[n]], 1.f);
}

__global__ void graph_accum_kernel(const int* __restrict__ gid, const float* __restrict__ rst,
                                   const float* __restrict__ gat_bias, float* __restrict__ hg) {
    int i = blockIdx.x * blockDim.x + threadIdx.x;
    int st = gridDim.x * blockDim.x;
    int tot = NN * H1;
    for (; i < tot; i += st) {
        int n = i >> 9, c = i & (H1 - 1);
        float v = rst[i] + gat_bias[c];
        v = fmaxf(v, 0.f);
        atomicAdd(&hg[(size_t)gid[n] * H1 + c], v);
    }
}

__global__ void final_kernel(const float* __restrict__ hg, const float* __restrict__ gcnt,
                             const float* __restrict__ cw, const float* __restrict__ cb,
                             float* __restrict__ out) {
    int g = blockIdx.x >> 1, hd = blockIdx.x & 1;
    int t = threadIdx.x;  // 256
    __shared__ float row[H2C];
    float inv = 1.f / fmaxf(gcnt[g], 1.f);
    row[t] = hg[(size_t)g * H1 + hd * H2C + t] * inv;
    __syncthreads();
    if (t < CC) {
        float s = cb[t];
        for (int j = 0; j < H2C; j++) s += row[j] * cw[t * H2C + j];
        out[((size_t)g * HEADS + hd) * CC + t] = s;
    }
}

// ---------------- launch ----------------
extern "C" void kernel_launch(void* const* d_in, const int* in_sizes, int n_in,
                              void* d_out, int out_size) {
    const float* in_feat  = (const float*)d_in[0];
    const int*   src      = (const int*)d_in[1];
    const int*   dst      = (const int*)d_in[2];
    const int*   etype    = (const int*)d_in[3];
    const int*   gid      = (const int*)d_in[4];
    const float* Wmsg     = (const float*)d_in[5];
    const float* bmsg     = (const float*)d_in[6];
    const float* w_ih     = (const float*)d_in[7];
    const float* w_hh     = (const float*)d_in[8];
    const float* b_ih     = (const float*)d_in[9];
    const float* b_hh     = (const float*)d_in[10];
    const float* fc_w     = (const float*)d_in[11];
    const float* attn_l   = (const float*)d_in[12];
    const float* attn_r   = (const float*)d_in[13];
    const float* gat_bias = (const float*)d_in[14];
    const float* cw       = (const float*)d_in[15];
    const float* cb       = (const float*)d_in[16];
    float* out = (float*)d_out;

    float* base = nullptr;
    cudaGetSymbolAddress((void**)&base, g_buf);

    float*    ah    = base + OFF_AH;
    float*    sagg  = base + OFF_SAGG;
    float*    P     = base + OFF_P;
    float*    Qi    = base + OFF_QI;
    float*    Qh    = base + OFF_QH;
    float*    W1    = base + OFF_W1;
    float*    WnI   = base + OFF_WNI;
    float*    WnH   = base + OFF_WNH;
    float*    fcwT  = base + OFF_FCWT;
    float*    feat  = base + OFF_FEAT;
    float*    el    = base + OFF_EL;
    float*    er    = base + OFF_ER;
    float*    eedge = base + OFF_EEDGE;
    float*    eexp  = base + OFF_EEXP;
    unsigned* emax  = (unsigned*)(base + OFF_EMAX);
    float*    den   = base + OFF_DEN;
    float*    rst   = base + OFF_RST;
    float*    hg    = base + OFF_HG;
    float*    gcnt  = base + OFF_GCNT;
    int*      cnt   = (int*)(base + OFF_CNT);

    // weight prep
    // W1 = [w_ih[:1024]^T ; w_hh[:1024]^T]  (1024 x 1024)
    transpose_kernel<<<512, 256>>>(w_ih, W1, 1024, 512);
    transpose_kernel<<<512, 256>>>(w_hh, W1 + (size_t)512 * 1024, 1024, 512);
    transpose_kernel<<<256, 256>>>(w_ih + (size_t)1024 * 512, WnI, 512, 512);
    transpose_kernel<<<256, 256>>>(w_hh + (size_t)1024 * 512, WnH, 512, 512);
    transpose_kernel<<<256, 256>>>(fc_w, fcwT, 512, 512);
    pad_kernel<<<4096, 256>>>(in_feat, ah);

    auto gemm = [](const float* A, int lda, const float* B, float* C, int ldc,
                   int M, int K, int N, int accum) {
        dim3 g(N / 128, (M + 127) / 128);
        gemm_tf32<<<g, 256>>>(A, lda, B, C, ldc, M, K, N, accum);
    };

    for (int step = 0; step < NSTEPS; step++) {
        zero_f4<<<4096, 256>>>((float4*)sagg, SZ_SAGG / 4);
        zero_f4<<<64, 256>>>((float4*)cnt, ((size_t)NN * KT) / 4);
        aggregate_kernel<<<EE, 128>>>(ah, src, dst, etype, sagg, cnt);
        bias_a_kernel<<<NN, 256>>>(bmsg, cnt, ah);
        // a += sagg @ Wmsg_cat   (Wmsg viewed as 2048 x 512 row-major)
        gemm(sagg, 2048, Wmsg, ah, 1024, NN, 2048, 512, 1);
        // P = [a|h] @ W1  (r,z gate sums)
        gemm(ah, 1024, W1, P, 1024, NN, 1024, 1024, 0);
        // Qi = a @ WnI ; Qh = h @ WnH   (n-gate parts)
        gemm(ah, 1024, WnI, Qi, 512, NN, 512, 512, 0);
        gemm(ah + 512, 1024, WnH, Qh, 512, NN, 512, 512, 0);
        gru_kernel<<<4096, 256>>>(P, Qi, Qh, b_ih, b_hh, ah);
    }

    norm_sig_kernel<<<NN, 128>>>(ah);
    // feat = h @ fc_w^T
    gemm(ah + 512, 1024, fcwT, feat, 512, NN, 512, 512, 0);
    elr_kernel<<<NN, 256>>>(feat, attn_l, attn_r, el, er);

    // emax + den contiguous: zero both (encoded 0 == -inf sentinel for emax)
    zero_f4<<<64, 256>>>((float4*)emax, (2 * (size_t)NN * HEADS) / 4);
    edge_max_kernel<<<(EE + 255) / 256, 256>>>(src, dst, el, er, eedge, emax);
    edge_exp_kernel<<<(EE + 255) / 256, 256>>>(dst, eedge, emax, eexp, den);

    zero_f4<<<2048, 256>>>((float4*)rst, ((size_t)NN * H1) / 4);
    edge_scatter_kernel<<<EE, 128>>>(src, dst, eexp, den, feat, rst);

    // hg + gcnt contiguous
    zero_f4<<<32, 256>>>((float4*)hg, ((size_t)GG * H1 + GG) / 4);
    gcnt_kernel<<<(NN + 255) / 256, 256>>>(gid, gcnt);
    graph_accum_kernel<<<4096, 256>>>(gid, rst, gat_bias, hg);
    final_kernel<<<GG * HEADS, 256>>>(hg, gcnt, cw, cb, out);
}

// round 4
// speedup vs baseline: 2.3999x; 2.3999x over previous
#include <cuda_runtime.h>
#include <cuda_fp16.h>
#include <math.h>
#include <stdint.h>

#define NN 20000
#define EE 320000
#define GG 64
#define INF_ 256
#define H1 512
#define H2C 256
#define HEADS 2
#define CC 16
#define NSTEPS 4
#define KT 4

// ================= scratch layout (floats) =================
constexpr size_t OFF_AH    = 0;                              // NN x 1024 ([a|h])
constexpr size_t OFF_SAGG  = OFF_AH + (size_t)NN * 1024;     // NN x 2048
constexpr size_t OFF_P     = OFF_SAGG + (size_t)NN * 2048;   // NN x 1024
constexpr size_t OFF_QI    = OFF_P + (size_t)NN * 1024;      // NN x 512
constexpr size_t OFF_QH    = OFF_QI + (size_t)NN * 512;      // NN x 512
constexpr size_t OFF_B1    = OFF_QH + (size_t)NN * 512;      // 1024 x 1024 [K][N]
constexpr size_t OFF_WNIT  = OFF_B1 + 1024 * 1024;           // 512 x 512
constexpr size_t OFF_WNHT  = OFF_WNIT + 512 * 512;
constexpr size_t OFF_FCWT  = OFF_WNHT + 512 * 512;
constexpr size_t OFF_FEAT  = OFF_FCWT + 512 * 512;           // NN x 512
constexpr size_t OFF_EL    = OFF_FEAT + (size_t)NN * 512;
constexpr size_t OFF_ER    = OFF_EL + (size_t)NN * HEADS;
constexpr size_t OFF_EEDGE = OFF_ER + (size_t)NN * HEADS;
constexpr size_t OFF_EEXP  = OFF_EEDGE + (size_t)EE * HEADS;
constexpr size_t OFF_EMAX  = OFF_EEXP + (size_t)EE * HEADS;
constexpr size_t OFF_DEN   = OFF_EMAX + (size_t)NN * HEADS;
constexpr size_t OFF_RST   = OFF_DEN + (size_t)NN * HEADS;
constexpr size_t OFF_HG    = OFF_RST + (size_t)NN * 512;
constexpr size_t OFF_GCNT  = OFF_HG + (size_t)GG * H1;
constexpr size_t OFF_CNT   = OFF_GCNT + GG;
constexpr size_t TOTAL_F   = OFF_CNT + (size_t)NN * KT;

__device__ __align__(16) float g_buf[TOTAL_F];

// ================= PTX helpers =================
__device__ __forceinline__ uint32_t smem_to_u32(const void* p) {
    uint32_t a;
    asm("{ .reg .u64 t; cvta.to.shared.u64 t, %1; cvt.u32.u64 %0, t; }" : "=r"(a) : "l"(p));
    return a;
}
__device__ __forceinline__ void ldsm_x4(uint32_t addr, uint32_t* r) {
    asm volatile("ldmatrix.sync.aligned.m8n8.x4.shared.b16 {%0,%1,%2,%3}, [%4];"
                 : "=r"(r[0]), "=r"(r[1]), "=r"(r[2]), "=r"(r[3]) : "r"(addr));
}
__device__ __forceinline__ void ldsm_x4_t(uint32_t addr, uint32_t* r) {
    asm volatile("ldmatrix.sync.aligned.m8n8.x4.trans.shared.b16 {%0,%1,%2,%3}, [%4];"
                 : "=r"(r[0]), "=r"(r[1]), "=r"(r[2]), "=r"(r[3]) : "r"(addr));
}
__device__ __forceinline__ void mma_f16(float* c, const uint32_t* a, const uint32_t* b) {
    asm volatile(
        "mma.sync.aligned.m16n8k16.row.col.f32.f16.f16.f32 "
        "{%0,%1,%2,%3},{%4,%5,%6,%7},{%8,%9},{%0,%1,%2,%3};"
        : "+f"(c[0]), "+f"(c[1]), "+f"(c[2]), "+f"(c[3])
        : "r"(a[0]), "r"(a[1]), "r"(a[2]), "r"(a[3]), "r"(b[0]), "r"(b[1]));
}

// ================= SMEM layout for gemm_hmma (half-element offsets) =================
#define AS_PITCH 40    // 32 used + 8 pad -> 80B rows, conflict-free ldmatrix
#define BS_PITCH 136   // 128 used + 8 pad -> 272B rows, conflict-free ldmatrix
#define SM_AHI(b) ((b) * 5120)             // 128*40 per buf
#define SM_ALO(b) (10240 + (b) * 5120)
#define SM_BHI(b) (20480 + (b) * 4352)     // 32*136 per buf
#define SM_BLO(b) (29184 + (b) * 4352)
#define SMEM_HALFS 37888
#define SMEM_BYTES (SMEM_HALFS * 2)

// ================= fp16-split HMMA GEMM =================
// C[M, n0:n0+128) (+)= A[M,K] @ B[K,N];  A row-major (stride lda), B row-major [K][N]
// (stride ldb), C row-major (stride ldc). grid: (ceil(M/128), N/128), 256 threads.
__global__ __launch_bounds__(256, 1)
void gemm_hmma(const float* __restrict__ A, int lda, const float* __restrict__ B, int ldb,
               float* __restrict__ C, int ldc, int M, int K, int accum) {
    extern __shared__ __half smh[];
    const uint32_t sbase = smem_to_u32(smh);

    const int tid = threadIdx.x;
    const int lane = tid & 31;
    const int wid = tid >> 5;
    const int wm = wid >> 2;     // 0..1
    const int wn = wid & 3;      // 0..3
    const int blockM = blockIdx.x * 128;
    const int n0 = blockIdx.y * 128;

    // staging mapping
    const int ar = tid >> 1;              // 0..127
    const int ac = (tid & 1) * 16;        // 0 / 16
    const int bk = tid >> 3;              // 0..31
    const int bn = (tid & 7) * 16;        // 0..112
    const bool aval = (blockM + ar) < M;
    const float* Ap = A + (size_t)(aval ? blockM + ar : 0) * lda + ac;
    const float* Bp = B + (size_t)bk * ldb + n0 + bn;

    const int nC = K >> 5;

    float acc[4][4][4];
#pragma unroll
    for (int mi = 0; mi < 4; mi++)
#pragma unroll
        for (int ni = 0; ni < 4; ni++)
#pragma unroll
            for (int q = 0; q < 4; q++) acc[mi][ni][q] = 0.f;

    float4 ra[4], rb[4];
    // prefetch chunk 0
    {
#pragma unroll
        for (int i = 0; i < 4; i++)
            ra[i] = aval ? *(const float4*)(Ap + i * 4) : make_float4(0.f, 0.f, 0.f, 0.f);
#pragma unroll
        for (int i = 0; i < 4; i++) rb[i] = *(const float4*)(Bp + i * 4);
    }

    // ldmatrix lane addressing (half-index)
    const int lrow = lane & 15;
    const int lhalf = (lane >> 4) * 8;

    for (int c = 0; c < nC; c++) {
        const int b = c & 1;
        // ---- stage regs -> SMEM (hi/lo split) ----
        {
            alignas(16) __half2 hi2[8], lo2[8];
            const float* v = (const float*)ra;
#pragma unroll
            for (int j = 0; j < 8; j++) {
                float x0 = v[2 * j], x1 = v[2 * j + 1];
                __half h0 = __float2half_rn(x0), h1 = __float2half_rn(x1);
                hi2[j] = __halves2half2(h0, h1);
                lo2[j] = __halves2half2(__float2half_rn(x0 - __half2float(h0)),
                                        __float2half_rn(x1 - __half2float(h1)));
            }
            __half* d0 = smh + SM_AHI(b) + ar * AS_PITCH + ac;
            *(uint4*)d0 = *(uint4*)&hi2[0];
            *(uint4*)(d0 + 8) = *(uint4*)&hi2[4];
            __half* d1 = smh + SM_ALO(b) + ar * AS_PITCH + ac;
            *(uint4*)d1 = *(uint4*)&lo2[0];
            *(uint4*)(d1 + 8) = *(uint4*)&lo2[4];

            v = (const float*)rb;
#pragma unroll
            for (int j = 0; j < 8; j++) {
                float x0 = v[2 * j], x1 = v[2 * j + 1];
                __half h0 = __float2half_rn(x0), h1 = __float2half_rn(x1);
                hi2[j] = __halves2half2(h0, h1);
                lo2[j] = __halves2half2(__float2half_rn(x0 - __half2float(h0)),
                                        __float2half_rn(x1 - __half2float(h1)));
            }
            d0 = smh + SM_BHI(b) + bk * BS_PITCH + bn;
            *(uint4*)d0 = *(uint4*)&hi2[0];
            *(uint4*)(d0 + 8) = *(uint4*)&hi2[4];
            d1 = smh + SM_BLO(b) + bk * BS_PITCH + bn;
            *(uint4*)d1 = *(uint4*)&lo2[0];
            *(uint4*)(d1 + 8) = *(uint4*)&lo2[4];
        }
        __syncthreads();

        // ---- prefetch next chunk ----
        if (c + 1 < nC) {
            const float* Apn = Ap + (c + 1) * 32;
            const float* Bpn = Bp + (size_t)(c + 1) * 32 * ldb;
#pragma unroll
            for (int i = 0; i < 4; i++)
                ra[i] = aval ? *(const float4*)(Apn + i * 4) : make_float4(0.f, 0.f, 0.f, 0.f);
#pragma unroll
            for (int i = 0; i < 4; i++) rb[i] = *(const float4*)(Bpn + i * 4);
        }

        // ---- compute 2 x k16 ----
#pragma unroll
        for (int s = 0; s < 2; s++) {
            uint32_t ahi[4][4], alo[4][4], bhi[4][2], blo[4][2];
#pragma unroll
            for (int mi = 0; mi < 4; mi++) {
                uint32_t off = (uint32_t)((wm * 64 + mi * 16 + lrow) * AS_PITCH + s * 16 + lhalf);
                ldsm_x4(sbase + 2 * (SM_AHI(b) + off), ahi[mi]);
                ldsm_x4(sbase + 2 * (SM_ALO(b) + off), alo[mi]);
            }
#pragma unroll
            for (int np = 0; np < 2; np++) {
                uint32_t off = (uint32_t)((s * 16 + lrow) * BS_PITCH + wn * 32 + np * 16 + lhalf);
                uint32_t t[4];
                ldsm_x4_t(sbase + 2 * (SM_BHI(b) + off), t);
                bhi[2 * np][0] = t[0]; bhi[2 * np][1] = t[1];
                bhi[2 * np + 1][0] = t[2]; bhi[2 * np + 1][1] = t[3];
                ldsm_x4_t(sbase + 2 * (SM_BLO(b) + off), t);
                blo[2 * np][0] = t[0]; blo[2 * np][1] = t[1];
                blo[2 * np + 1][0] = t[2]; blo[2 * np + 1][1] = t[3];
            }
#pragma unroll
            for (int mi = 0; mi < 4; mi++)
#pragma unroll
                for (int ni = 0; ni < 4; ni++) {
                    mma_f16(acc[mi][ni], ahi[mi], bhi[ni]);
                    mma_f16(acc[mi][ni], ahi[mi], blo[ni]);
                    mma_f16(acc[mi][ni], alo[mi], bhi[ni]);
                }
        }
        __syncthreads();
    }

    // ---- epilogue ----
    const int row0 = blockM + wm * 64;
    const int col0 = n0 + wn * 32;
#pragma unroll
    for (int mi = 0; mi < 4; mi++) {
        int r0 = row0 + mi * 16 + (lane >> 2);
        int r1 = r0 + 8;
#pragma unroll
        for (int ni = 0; ni < 4; ni++) {
            int cc = col0 + ni * 8 + (lane & 3) * 2;
            if (r0 < M) {
                float2* p = (float2*)(C + (size_t)r0 * ldc + cc);
                float2 v = make_float2(acc[mi][ni][0], acc[mi][ni][1]);
                if (accum) { float2 o = *p; v.x += o.x; v.y += o.y; }
                *p = v;
            }
            if (r1 < M) {
                float2* p = (float2*)(C + (size_t)r1 * ldc + cc);
                float2 v = make_float2(acc[mi][ni][2], acc[mi][ni][3]);
                if (accum) { float2 o = *p; v.x += o.x; v.y += o.y; }
                *p = v;
            }
        }
    }
}

// ================= misc helpers =================
__device__ __forceinline__ float sigm(float x) { return 1.f / (1.f + expf(-x)); }
__device__ __forceinline__ unsigned fenc(float f) {
    unsigned u = __float_as_uint(f);
    return (u >> 31) ? ~u : (u | 0x80000000u);
}
__device__ __forceinline__ float fdec(unsigned u) {
    return (u >> 31) ? __uint_as_float(u & 0x7fffffffu) : __uint_as_float(~u);
}

__global__ void zero_f4(float4* p, size_t n4) {
    size_t i = (size_t)blockIdx.x * blockDim.x + threadIdx.x;
    size_t st = (size_t)gridDim.x * blockDim.x;
    for (; i < n4; i += st) p[i] = make_float4(0.f, 0.f, 0.f, 0.f);
}

// B1[k][n] (1024x1024): k<512 -> w_ih[n][k], else w_hh[n][k-512]  (r,z gate rows n<1024)
__global__ void prep_b1(const float* __restrict__ w_ih, const float* __restrict__ w_hh,
                        float* __restrict__ B1) {
    int i = blockIdx.x * blockDim.x + threadIdx.x;
    int st = gridDim.x * blockDim.x;
    for (; i < 1024 * 1024; i += st) {
        int k = i >> 10;
        int n = i & 1023;
        B1[i] = (k < 512) ? w_ih[(size_t)n * 512 + k] : w_hh[(size_t)n * 512 + (k - 512)];
    }
}

// T512[k][n] = W[(rowoff+n)*512 + k]
__global__ void prep_t512(const float* __restrict__ W, int rowoff, float* __restrict__ T) {
    int i = blockIdx.x * blockDim.x + threadIdx.x;
    int st = gridDim.x * blockDim.x;
    for (; i < 512 * 512; i += st) {
        int k = i >> 9;
        int n = i & 511;
        T[i] = W[(size_t)(rowoff + n) * 512 + k];
    }
}

__global__ void pad_kernel(const float* __restrict__ x, float* __restrict__ ah) {
    int i = blockIdx.x * blockDim.x + threadIdx.x;
    int st = gridDim.x * blockDim.x;
    int tot = NN * H1;
    for (; i < tot; i += st) {
        int c = i & (H1 - 1);
        int n = i >> 9;
        ah[(size_t)n * 1024 + 512 + c] = (c < INF_) ? x[(size_t)n * INF_ + c] : 0.f;
    }
}

__global__ void aggregate_kernel(const float* __restrict__ ah,
                                 const int* __restrict__ src, const int* __restrict__ dst,
                                 const int* __restrict__ et,
                                 float* __restrict__ sagg, int* __restrict__ cnt) {
    int e = blockIdx.x;
    int s = src[e], d = dst[e], k = et[e];
    if (threadIdx.x == 0) atomicAdd(&cnt[d * KT + k], 1);
    const float* hv = ah + (size_t)s * 1024 + 512;
    float* out = sagg + (size_t)d * 2048 + k * 512;
    int c = threadIdx.x * 4;
    float4 v = *(const float4*)(hv + c);
    atomicAdd(&out[c + 0], v.x);
    atomicAdd(&out[c + 1], v.y);
    atomicAdd(&out[c + 2], v.z);
    atomicAdd(&out[c + 3], v.w);
}

__global__ void bias_a_kernel(const float* __restrict__ bmsg, const int* __restrict__ cnt,
                              float* __restrict__ ah) {
    int n = blockIdx.x;
    __shared__ float bm[KT * H1];
    for (int i = threadIdx.x; i < KT * H1; i += blockDim.x) bm[i] = bmsg[i];
    __shared__ int cn[KT];
    if (threadIdx.x < KT) cn[threadIdx.x] = cnt[n * KT + threadIdx.x];
    __syncthreads();
    float c0 = (float)cn[0], c1 = (float)cn[1], c2 = (float)cn[2], c3 = (float)cn[3];
    for (int c = threadIdx.x; c < H1; c += blockDim.x)
        ah[(size_t)n * 1024 + c] =
            c0 * bm[c] + c1 * bm[H1 + c] + c2 * bm[2 * H1 + c] + c3 * bm[3 * H1 + c];
}

__global__ void gru_kernel(const float* __restrict__ P, const float* __restrict__ Qi,
                           const float* __restrict__ Qh,
                           const float* __restrict__ b_ih, const float* __restrict__ b_hh,
                           float* __restrict__ ah) {
    int i = blockIdx.x * blockDim.x + threadIdx.x;
    int st = gridDim.x * blockDim.x;
    int tot = NN * H1;
    for (; i < tot; i += st) {
        int n = i >> 9, c = i & (H1 - 1);
        float r = sigm(P[(size_t)n * 1024 + c] + b_ih[c] + b_hh[c]);
        float z = sigm(P[(size_t)n * 1024 + 512 + c] + b_ih[512 + c] + b_hh[512 + c]);
        float nn = tanhf(Qi[(size_t)n * 512 + c] + b_ih[1024 + c] +
                         r * (Qh[(size_t)n * 512 + c] + b_hh[1024 + c]));
        float* hp = &ah[(size_t)n * 1024 + 512 + c];
        *hp = (1.f - z) * nn + z * *hp;
    }
}

__global__ void norm_sig_kernel(float* __restrict__ ah) {
    int n = blockIdx.x;
    int t = threadIdx.x;
    float* row = ah + (size_t)n * 1024 + 512;
    float s = 0.f;
    for (int c = t; c < H1; c += 128) {
        float v = row[c];
        s += v * v;
    }
    __shared__ float sm[128];
    sm[t] = s;
    __syncthreads();
    for (int o = 64; o > 0; o >>= 1) {
        if (t < o) sm[t] += sm[t + o];
        __syncthreads();
    }
    float inv = 1.f / fmaxf(sqrtf(sm[0]), 1e-12f);
    for (int c = t; c < H1; c += 128) row[c] = sigm(row[c] * inv);
}

__global__ void elr_kernel(const float* __restrict__ feat, const float* __restrict__ attn_l,
                           const float* __restrict__ attn_r,
                           float* __restrict__ el, float* __restrict__ er) {
    int n = blockIdx.x;
    int t = threadIdx.x;  // 256
    float f0 = feat[(size_t)n * H1 + t];
    float f1 = feat[(size_t)n * H1 + H2C + t];
    float vals[4] = {f0 * attn_l[t], f0 * attn_r[t], f1 * attn_l[H2C + t], f1 * attn_r[H2C + t]};
    float outp[4];
    __shared__ float sm[256];
#pragma unroll
    for (int q = 0; q < 4; q++) {
        sm[t] = vals[q];
        __syncthreads();
        for (int o = 128; o > 0; o >>= 1) {
            if (t < o) sm[t] += sm[t + o];
            __syncthreads();
        }
        outp[q] = sm[0];
        __syncthreads();
    }
    if (t == 0) {
        el[n * 2] = outp[0];
        er[n * 2] = outp[1];
        el[n * 2 + 1] = outp[2];
        er[n * 2 + 1] = outp[3];
    }
}

__global__ void edge_max_kernel(const int* __restrict__ src, const int* __restrict__ dst,
                                const float* __restrict__ el, const float* __restrict__ er,
                                float* __restrict__ eedge, unsigned* __restrict__ emax) {
    int e = blockIdx.x * blockDim.x + threadIdx.x;
    if (e >= EE) return;
    int s = src[e], d = dst[e];
#pragma unroll
    for (int hd = 0; hd < HEADS; hd++) {
        float v = el[s * 2 + hd] + er[d * 2 + hd];
        v = v > 0.f ? v : 0.2f * v;
        eedge[e * 2 + hd] = v;
        atomicMax(&emax[d * 2 + hd], fenc(v));
    }
}

__global__ void edge_exp_kernel(const int* __restrict__ dst, const float* __restrict__ eedge,
                                const unsigned* __restrict__ emax,
                                float* __restrict__ eexp, float* __restrict__ den) {
    int e = blockIdx.x * blockDim.x + threadIdx.x;
    if (e >= EE) return;
    int d = dst[e];
#pragma unroll
    for (int hd = 0; hd < HEADS; hd++) {
        float ee = expf(eedge[e * 2 + hd] - fdec(emax[d * 2 + hd]));
        eexp[e * 2 + hd] = ee;
        atomicAdd(&den[d * 2 + hd], ee);
    }
}

__global__ void edge_scatter_kernel(const int* __restrict__ src, const int* __restrict__ dst,
                                    const float* __restrict__ eexp, const float* __restrict__ den,
                                    const float* __restrict__ feat, float* __restrict__ rst) {
    int e = blockIdx.x;
    int s = src[e], d = dst[e];
    float a0 = eexp[e * 2] / den[d * 2];
    float a1 = eexp[e * 2 + 1] / den[d * 2 + 1];
    const float* f = feat + (size_t)s * H1;
    float* r = rst + (size_t)d * H1;
    int c = threadIdx.x * 4;
    float al = (c < H2C) ? a0 : a1;
    float4 v = *(const float4*)(f + c);
    atomicAdd(&r[c + 0], al * v.x);
    atomicAdd(&r[c + 1], al * v.y);
    atomicAdd(&r[c + 2], al * v.z);
    atomicAdd(&r[c + 3], al * v.w);
}

__global__ void gcnt_kernel(const int* __restrict__ gid, float* __restrict__ gcnt) {
    int n = blockIdx.x * blockDim.x + threadIdx.x;
    if (n < NN) atomicAdd(&gcnt[gid[n]], 1.f);
}

__global__ void graph_accum_kernel(const int* __restrict__ gid, const float* __restrict__ rst,
                                   const float* __restrict__ gat_bias, float* __restrict__ hg) {
    int i = blockIdx.x * blockDim.x + threadIdx.x;
    int st = gridDim.x * blockDim.x;
    int tot = NN * H1;
    for (; i < tot; i += st) {
        int n = i >> 9, c = i & (H1 - 1);
        float v = rst[i] + gat_bias[c];
        v = fmaxf(v, 0.f);
        atomicAdd(&hg[(size_t)gid[n] * H1 + c], v);
    }
}

__global__ void final_kernel(const float* __restrict__ hg, const float* __restrict__ gcnt,
                             const float* __restrict__ cw, const float* __restrict__ cb,
                             float* __restrict__ out) {
    int g = blockIdx.x >> 1, hd = blockIdx.x & 1;
    int t = threadIdx.x;  // 256
    __shared__ float row[H2C];
    float inv = 1.f / fmaxf(gcnt[g], 1.f);
    row[t] = hg[(size_t)g * H1 + hd * H2C + t] * inv;
    __syncthreads();
    if (t < CC) {
        float s = cb[t];
        for (int j = 0; j < H2C; j++) s += row[j] * cw[t * H2C + j];
        out[((size_t)g * HEADS + hd) * CC + t] = s;
    }
}

// ================= launch =================
extern "C" void kernel_launch(void* const* d_in, const int* in_sizes, int n_in,
                              void* d_out, int out_size) {
    const float* in_feat  = (const float*)d_in[0];
    const int*   src      = (const int*)d_in[1];
    const int*   dst      = (const int*)d_in[2];
    const int*   etype    = (const int*)d_in[3];
    const int*   gid      = (const int*)d_in[4];
    const float* Wmsg     = (const float*)d_in[5];
    const float* bmsg     = (const float*)d_in[6];
    const float* w_ih     = (const float*)d_in[7];
    const float* w_hh     = (const float*)d_in[8];
    const float* b_ih     = (const float*)d_in[9];
    const float* b_hh     = (const float*)d_in[10];
    const float* fc_w     = (const float*)d_in[11];
    const float* attn_l   = (const float*)d_in[12];
    const float* attn_r   = (const float*)d_in[13];
    const float* gat_bias = (const float*)d_in[14];
    const float* cw       = (const float*)d_in[15];
    const float* cb       = (const float*)d_in[16];
    float* out = (float*)d_out;

    cudaFuncSetAttribute(gemm_hmma, cudaFuncAttributeMaxDynamicSharedMemorySize, SMEM_BYTES);

    float* base = nullptr;
    cudaGetSymbolAddress((void**)&base, g_buf);

    float*    ah    = base + OFF_AH;
    float*    sagg  = base + OFF_SAGG;
    float*    P     = base + OFF_P;
    float*    Qi    = base + OFF_QI;
    float*    Qh    = base + OFF_QH;
    float*    B1    = base + OFF_B1;
    float*    WnIT  = base + OFF_WNIT;
    float*    WnHT  = base + OFF_WNHT;
    float*    fcwT  = base + OFF_FCWT;
    float*    feat  = base + OFF_FEAT;
    float*    el    = base + OFF_EL;
    float*    er    = base + OFF_ER;
    float*    eedge = base + OFF_EEDGE;
    float*    eexp  = base + OFF_EEXP;
    unsigned* emax  = (unsigned*)(base + OFF_EMAX);
    float*    den   = base + OFF_DEN;
    float*    rst   = base + OFF_RST;
    float*    hg    = base + OFF_HG;
    float*    gcnt  = base + OFF_GCNT;
    int*      cnt   = (int*)(base + OFF_CNT);

    prep_b1<<<512, 256>>>(w_ih, w_hh, B1);
    prep_t512<<<256, 256>>>(w_ih, 1024, WnIT);
    prep_t512<<<256, 256>>>(w_hh, 1024, WnHT);
    prep_t512<<<256, 256>>>(fc_w, 0, fcwT);
    pad_kernel<<<4096, 256>>>(in_feat, ah);

    auto gemm = [](const float* A, int lda, const float* B, int ldb, float* C, int ldc,
                   int M, int K, int N, int accum) {
        dim3 g((M + 127) / 128, N / 128);
        gemm_hmma<<<g, 256, SMEM_BYTES>>>(A, lda, B, ldb, C, ldc, M, K, accum);
    };

    for (int step = 0; step < NSTEPS; step++) {
        zero_f4<<<4096, 256>>>((float4*)sagg, ((size_t)NN * 2048) / 4);
        zero_f4<<<64, 256>>>((float4*)cnt, ((size_t)NN * KT) / 4);
        aggregate_kernel<<<EE, 128>>>(ah, src, dst, etype, sagg, cnt);
        bias_a_kernel<<<NN, 256>>>(bmsg, cnt, ah);
        // a += sagg @ Wmsg  (Wmsg is natively [2048][512] row-major = [K][N])
        gemm(sagg, 2048, Wmsg, 512, ah, 1024, NN, 2048, 512, 1);
        // P = [a|h] @ B1  (B1: [1024][1024] = [K][N], r/z gate pre-sums)
        gemm(ah, 1024, B1, 1024, P, 1024, NN, 1024, 1024, 0);
        // Qi = a @ WnIT ; Qh = h @ WnHT
        gemm(ah, 1024, WnIT, 512, Qi, 512, NN, 512, 512, 0);
        gemm(ah + 512, 1024, WnHT, 512, Qh, 512, NN, 512, 512, 0);
        gru_kernel<<<4096, 256>>>(P, Qi, Qh, b_ih, b_hh, ah);
    }

    norm_sig_kernel<<<NN, 128>>>(ah);
    // feat = h @ fc_w^T
    gemm(ah + 512, 1024, fcwT, 512, feat, 512, NN, 512, 512, 0);
    elr_kernel<<<NN, 256>>>(feat, attn_l, attn_r, el, er);

    zero_f4<<<64, 256>>>((float4*)emax, (2 * (size_t)NN * HEADS) / 4);
    edge_max_kernel<<<(EE + 255) / 256, 256>>>(src, dst, el, er, eedge, emax);
    edge_exp_kernel<<<(EE + 255) / 256, 256>>>(dst, eedge, emax, eexp, den);

    zero_f4<<<2048, 256>>>((float4*)rst, ((size_t)NN * H1) / 4);
    edge_scatter_kernel<<<EE, 128>>>(src, dst, eexp, den, feat, rst);

    zero_f4<<<32, 256>>>((float4*)hg, ((size_t)GG * H1 + GG) / 4);
    gcnt_kernel<<<(NN + 255) / 256, 256>>>(gid, gcnt);
    graph_accum_kernel<<<4096, 256>>>(gid, rst, gat_bias, hg);
    final_kernel<<<GG * HEADS, 256>>>(hg, gcnt, cw, cb, out);
}

// round 6
// speedup vs baseline: 2.7532x; 1.1472x over previous
#include <cuda_runtime.h>
#include <cuda_fp16.h>
#include <math.h>
#include <stdint.h>

#define NN 20000
#define EE 320000
#define GG 64
#define INF_ 256
#define H1 512
#define H2C 256
#define HEADS 2
#define CC 16
#define NSTEPS 4
#define KT 4

// ================= scratch layout (float units) =================
constexpr size_t OFF_HF    = 0;                               // NN x 512 f32 (h)
constexpr size_t OFF_AF    = OFF_HF + (size_t)NN * 512;       // NN x 512 f32 (a bias base)
constexpr size_t OFF_P     = OFF_AF + (size_t)NN * 512;       // NN x 1024 f32
constexpr size_t OFF_QI    = OFF_P + (size_t)NN * 1024;       // NN x 512
constexpr size_t OFF_QH    = OFF_QI + (size_t)NN * 512;
constexpr size_t OFF_FEAT  = OFF_QH + (size_t)NN * 512;       // NN x 512
constexpr size_t OFF_AHH   = OFF_FEAT + (size_t)NN * 512;     // NN x 1024 halves (hi)
constexpr size_t OFF_AHL   = OFF_AHH + (size_t)NN * 512;      // NN x 1024 halves (lo)
constexpr size_t OFF_SAGH  = OFF_AHL + (size_t)NN * 512;      // NN x 2048 halves
constexpr size_t OFF_SAGL  = OFF_SAGH + (size_t)NN * 1024;
constexpr size_t OFF_WMH   = OFF_SAGL + (size_t)NN * 1024;    // 2048x512 halves
constexpr size_t OFF_WML   = OFF_WMH + 524288;
constexpr size_t OFF_B1H   = OFF_WML + 524288;                // 1024x1024 halves
constexpr size_t OFF_B1L   = OFF_B1H + 524288;
constexpr size_t OFF_WIH   = OFF_B1L + 524288;                // 512x512 halves
constexpr size_t OFF_WIL   = OFF_WIH + 131072;
constexpr size_t OFF_WHH   = OFF_WIL + 131072;
constexpr size_t OFF_WHL   = OFF_WHH + 131072;
constexpr size_t OFF_FCH   = OFF_WHL + 131072;
constexpr size_t OFF_FCL   = OFF_FCH + 131072;
constexpr size_t OFF_EL    = OFF_FCL + 131072;                // NN x 2
constexpr size_t OFF_ER    = OFF_EL + (size_t)NN * 2;
constexpr size_t OFF_HG    = OFF_ER + (size_t)NN * 2;         // GG x 512
constexpr size_t OFF_GCNT  = OFF_HG + (size_t)GG * 512;       // GG
// int regions
constexpr size_t OFF_DEG   = OFF_GCNT + GG;                   // NN ints
constexpr size_t OFF_RPTR  = OFF_DEG + NN;                    // NN+4 ints
constexpr size_t OFF_CUR   = OFF_RPTR + NN + 4;               // NN ints
constexpr size_t OFF_EIDX  = OFF_CUR + NN;                    // EE ints
constexpr size_t OFF_CNT   = OFF_EIDX + EE;                   // NN*4 ints
constexpr size_t TOTAL_F   = OFF_CNT + (size_t)NN * 4 + 16;

__device__ __align__(16) float g_buf[TOTAL_F];

// ================= PTX helpers =================
__device__ __forceinline__ uint32_t smem_to_u32(const void* p) {
    uint32_t a;
    asm("{ .reg .u64 t; cvta.to.shared.u64 t, %1; cvt.u32.u64 %0, t; }" : "=r"(a) : "l"(p));
    return a;
}
__device__ __forceinline__ void ldsm_x4(uint32_t addr, uint32_t* r) {
    asm volatile("ldmatrix.sync.aligned.m8n8.x4.shared.b16 {%0,%1,%2,%3}, [%4];"
                 : "=r"(r[0]), "=r"(r[1]), "=r"(r[2]), "=r"(r[3]) : "r"(addr));
}
__device__ __forceinline__ void ldsm_x4_t(uint32_t addr, uint32_t* r) {
    asm volatile("ldmatrix.sync.aligned.m8n8.x4.trans.shared.b16 {%0,%1,%2,%3}, [%4];"
                 : "=r"(r[0]), "=r"(r[1]), "=r"(r[2]), "=r"(r[3]) : "r"(addr));
}
__device__ __forceinline__ void mma_f16(float* c, const uint32_t* a, const uint32_t* b) {
    asm volatile(
        "mma.sync.aligned.m16n8k16.row.col.f32.f16.f16.f32 "
        "{%0,%1,%2,%3},{%4,%5,%6,%7},{%8,%9},{%0,%1,%2,%3};"
        : "+f"(c[0]), "+f"(c[1]), "+f"(c[2]), "+f"(c[3])
        : "r"(a[0]), "r"(a[1]), "r"(a[2]), "r"(a[3]), "r"(b[0]), "r"(b[1]));
}
__device__ __forceinline__ void split2(float x0, float x1, __half2& hi, __half2& lo) {
    __half h0 = __float2half_rn(x0), h1 = __float2half_rn(x1);
    hi = __halves2half2(h0, h1);
    lo = __halves2half2(__float2half_rn(x0 - __half2float(h0)),
                        __float2half_rn(x1 - __half2float(h1)));
}

// ================= SMEM layout for gemm_h (half-element offsets) =================
#define AS_PITCH 40
#define BS_PITCH 136
#define SM_AHI(b) ((b) * 5120)
#define SM_ALO(b) (10240 + (b) * 5120)
#define SM_BHI(b) (20480 + (b) * 4352)
#define SM_BLO(b) (29184 + (b) * 4352)
#define SMEM_HALFS 37888
#define SMEM_BYTES (SMEM_HALFS * 2)

// ================= half-plane HMMA GEMM =================
// acc = A @ B with A=(Ahi+Alo) [M,K] halves row-major stride lda,
// B=(Bhi+Blo) [K,N] halves row-major stride ldb (3-term split product).
// mode 0: Cf[r][c] = acc (fp32, stride ldc)
// mode 1: v = Cf_in + acc; split v -> (Ohi,Olo) halves, stride ldo
__global__ __launch_bounds__(256, 2)
void gemm_h(const __half* __restrict__ Ahi, const __half* __restrict__ Alo, int lda,
            const __half* __restrict__ Bhi, const __half* __restrict__ Blo, int ldb,
            float* __restrict__ Cf, int ldc,
            __half* __restrict__ Ohi, __half* __restrict__ Olo, int ldo,
            int M, int K, int mode) {
    extern __shared__ __half smh[];
    const uint32_t sbase = smem_to_u32(smh);

    const int tid = threadIdx.x;
    const int lane = tid & 31;
    const int wid = tid >> 5;
    const int wm = wid >> 2;
    const int wn = wid & 3;
    const int blockM = blockIdx.x * 128;
    const int n0 = blockIdx.y * 128;

    const int ar = tid >> 1, ac = (tid & 1) * 16;
    const int bk = tid >> 3, bn = (tid & 7) * 16;
    const bool aval = (blockM + ar) < M;
    const __half* Ahp = Ahi + (size_t)(aval ? blockM + ar : 0) * lda + ac;
    const __half* Alp = Alo + (size_t)(aval ? blockM + ar : 0) * lda + ac;
    const __half* Bhp = Bhi + (size_t)bk * ldb + n0 + bn;
    const __half* Blp = Blo + (size_t)bk * ldb + n0 + bn;

    const int nC = K >> 5;

    float acc[4][4][4];
#pragma unroll
    for (int mi = 0; mi < 4; mi++)
#pragma unroll
        for (int ni = 0; ni < 4; ni++)
#pragma unroll
            for (int q = 0; q < 4; q++) acc[mi][ni][q] = 0.f;

    // each thread stages 16 halves (= 2 x uint4) per plane
    uint4 rah[2], ral[2], rbh[2], rbl[2];
    const uint4 z4 = make_uint4(0, 0, 0, 0);
    rah[0] = aval ? *(const uint4*)Ahp : z4;
    rah[1] = aval ? *(const uint4*)(Ahp + 8) : z4;
    ral[0] = aval ? *(const uint4*)Alp : z4;
    ral[1] = aval ? *(const uint4*)(Alp + 8) : z4;
    rbh[0] = *(const uint4*)Bhp;
    rbh[1] = *(const uint4*)(Bhp + 8);
    rbl[0] = *(const uint4*)Blp;
    rbl[1] = *(const uint4*)(Blp + 8);

    const int lrow = lane & 15;
    const int lhalf = (lane >> 4) * 8;

    for (int c = 0; c < nC; c++) {
        const int b = c & 1;
        {
            __half* pa = smh + SM_AHI(b) + ar * AS_PITCH + ac;
            *(uint4*)pa = rah[0];
            *(uint4*)(pa + 8) = rah[1];
            __half* pl = smh + SM_ALO(b) + ar * AS_PITCH + ac;
            *(uint4*)pl = ral[0];
            *(uint4*)(pl + 8) = ral[1];
            __half* pb = smh + SM_BHI(b) + bk * BS_PITCH + bn;
            *(uint4*)pb = rbh[0];
            *(uint4*)(pb + 8) = rbh[1];
            __half* pbl = smh + SM_BLO(b) + bk * BS_PITCH + bn;
            *(uint4*)pbl = rbl[0];
            *(uint4*)(pbl + 8) = rbl[1];
        }
        __syncthreads();

        if (c + 1 < nC) {
            const __half* an = Ahp + (c + 1) * 32;
            const __half* aln = Alp + (c + 1) * 32;
            const __half* bnh = Bhp + (size_t)(c + 1) * 32 * ldb;
            const __half* bnl = Blp + (size_t)(c + 1) * 32 * ldb;
            rah[0] = aval ? *(const uint4*)an : z4;
            rah[1] = aval ? *(const uint4*)(an + 8) : z4;
            ral[0] = aval ? *(const uint4*)aln : z4;
            ral[1] = aval ? *(const uint4*)(aln + 8) : z4;
            rbh[0] = *(const uint4*)bnh;
            rbh[1] = *(const uint4*)(bnh + 8);
            rbl[0] = *(const uint4*)bnl;
            rbl[1] = *(const uint4*)(bnl + 8);
        }

#pragma unroll
        for (int s = 0; s < 2; s++) {
            uint32_t ahi[4][4], alo[4][4], bhi[4][2], blo[4][2];
#pragma unroll
            for (int mi = 0; mi < 4; mi++) {
                uint32_t off = (uint32_t)((wm * 64 + mi * 16 + lrow) * AS_PITCH + s * 16 + lhalf);
                ldsm_x4(sbase + 2 * (SM_AHI(b) + off), ahi[mi]);
                ldsm_x4(sbase + 2 * (SM_ALO(b) + off), alo[mi]);
            }
#pragma unroll
            for (int np = 0; np < 2; np++) {
                uint32_t off = (uint32_t)((s * 16 + lrow) * BS_PITCH + wn * 32 + np * 16 + lhalf);
                uint32_t t[4];
                ldsm_x4_t(sbase + 2 * (SM_BHI(b) + off), t);
                bhi[2 * np][0] = t[0]; bhi[2 * np][1] = t[1];
                bhi[2 * np + 1][0] = t[2]; bhi[2 * np + 1][1] = t[3];
                ldsm_x4_t(sbase + 2 * (SM_BLO(b) + off), t);
                blo[2 * np][0] = t[0]; blo[2 * np][1] = t[1];
                blo[2 * np + 1][0] = t[2]; blo[2 * np + 1][1] = t[3];
            }
#pragma unroll
            for (int mi = 0; mi < 4; mi++)
#pragma unroll
                for (int ni = 0; ni < 4; ni++) {
                    mma_f16(acc[mi][ni], ahi[mi], bhi[ni]);
                    mma_f16(acc[mi][ni], ahi[mi], blo[ni]);
                    mma_f16(acc[mi][ni], alo[mi], bhi[ni]);
                }
        }
        __syncthreads();
    }

    const int row0 = blockM + wm * 64;
    const int col0 = n0 + wn * 32;
#pragma unroll
    for (int mi = 0; mi < 4; mi++) {
        int r0 = row0 + mi * 16 + (lane >> 2);
        int r1 = r0 + 8;
#pragma unroll
        for (int ni = 0; ni < 4; ni++) {
            int cc = col0 + ni * 8 + (lane & 3) * 2;
#pragma unroll
            for (int h = 0; h < 2; h++) {
                int r = h ? r1 : r0;
                if (r >= M) continue;
                float v0 = acc[mi][ni][2 * h], v1 = acc[mi][ni][2 * h + 1];
                if (mode == 0) {
                    *(float2*)(Cf + (size_t)r * ldc + cc) = make_float2(v0, v1);
                } else {
                    float2 ci = *(const float2*)(Cf + (size_t)r * ldc + cc);
                    v0 += ci.x; v1 += ci.y;
                    __half2 hi, lo;
                    split2(v0, v1, hi, lo);
                    *(__half2*)(Ohi + (size_t)r * ldo + cc) = hi;
                    *(__half2*)(Olo + (size_t)r * ldo + cc) = lo;
                }
            }
        }
    }
}

// ================= misc =================
__device__ __forceinline__ float sigm(float x) { return 1.f / (1.f + expf(-x)); }

__global__ void zero_f4(float4* p, size_t n4) {
    size_t i = (size_t)blockIdx.x * blockDim.x + threadIdx.x;
    size_t st = (size_t)gridDim.x * blockDim.x;
    for (; i < n4; i += st) p[i] = make_float4(0.f, 0.f, 0.f, 0.f);
}

// split fp32 array -> hi/lo half planes
__global__ void conv_split(const float* __restrict__ in, __half* __restrict__ hi,
                           __half* __restrict__ lo, size_t n2) {
    size_t i = (size_t)blockIdx.x * blockDim.x + threadIdx.x;
    size_t st = (size_t)gridDim.x * blockDim.x;
    for (; i < n2; i += st) {
        float2 v = *(const float2*)(in + 2 * i);
        __half2 h, l;
        split2(v.x, v.y, h, l);
        *(__half2*)(hi + 2 * i) = h;
        *(__half2*)(lo + 2 * i) = l;
    }
}

// B1[k][n] halves: k<512 -> w_ih[n][k], else w_hh[n][k-512]; n in 0..1023
__global__ void prep_b1_h(const float* __restrict__ w_ih, const float* __restrict__ w_hh,
                          __half* __restrict__ hi, __half* __restrict__ lo) {
    int i = blockIdx.x * blockDim.x + threadIdx.x;
    int st = gridDim.x * blockDim.x;
    for (; i < 1024 * 512; i += st) {
        int k = i >> 9;
        int n = (i & 511) * 2;
        float v0 = (k < 512) ? w_ih[(size_t)n * 512 + k] : w_hh[(size_t)n * 512 + k - 512];
        float v1 = (k < 512) ? w_ih[(size_t)(n + 1) * 512 + k] : w_hh[(size_t)(n + 1) * 512 + k - 512];
        __half2 h, l;
        split2(v0, v1, h, l);
        *(__half2*)(hi + (size_t)k * 1024 + n) = h;
        *(__half2*)(lo + (size_t)k * 1024 + n) = l;
    }
}

// T[k][n] halves = W[(rowoff+n)*512 + k]
__global__ void prep_t512_h(const float* __restrict__ W, int rowoff,
                            __half* __restrict__ hi, __half* __restrict__ lo) {
    int i = blockIdx.x * blockDim.x + threadIdx.x;
    int st = gridDim.x * blockDim.x;
    for (; i < 512 * 256; i += st) {
        int k = i >> 8;
        int n = (i & 255) * 2;
        float v0 = W[(size_t)(rowoff + n) * 512 + k];
        float v1 = W[(size_t)(rowoff + n + 1) * 512 + k];
        __half2 h, l;
        split2(v0, v1, h, l);
        *(__half2*)(hi + (size_t)k * 512 + n) = h;
        *(__half2*)(lo + (size_t)k * 512 + n) = l;
    }
}

// pad input -> hF fp32 + h halves (ah cols 512..1023)
__global__ void pad_kernel(const float* __restrict__ x, float* __restrict__ hF,
                           __half* __restrict__ ahHi, __half* __restrict__ ahLo) {
    int i = blockIdx.x * blockDim.x + threadIdx.x;
    int st = gridDim.x * blockDim.x;
    int tot = NN * 256;
    for (; i < tot; i += st) {
        int n = i >> 8;
        int c = (i & 255) * 2;
        float v0 = (c < INF_) ? x[(size_t)n * INF_ + c] : 0.f;
        float v1 = (c + 1 < INF_) ? x[(size_t)n * INF_ + c + 1] : 0.f;
        *(float2*)(hF + (size_t)n * 512 + c) = make_float2(v0, v1);
        __half2 h, l;
        split2(v0, v1, h, l);
        *(__half2*)(ahHi + (size_t)n * 1024 + 512 + c) = h;
        *(__half2*)(ahLo + (size_t)n * 1024 + 512 + c) = l;
    }
}

// ================= CSR build =================
__global__ void csr_count(const int* __restrict__ dst, int* __restrict__ deg) {
    int e = blockIdx.x * blockDim.x + threadIdx.x;
    if (e < EE) atomicAdd(&deg[dst[e]], 1);
}

__global__ void csr_scan(const int* __restrict__ deg, int* __restrict__ rowptr,
                         int* __restrict__ cursor) {
    __shared__ int part[1024];
    int t = threadIdx.x;
    int b = t * 20;
    int loc[20];
    int s = 0;
#pragma unroll
    for (int i = 0; i < 20; i++) {
        int n = b + i;
        loc[i] = (n < NN) ? deg[n] : 0;
        s += loc[i];
    }
    part[t] = s;
    __syncthreads();
    for (int off = 1; off < 1024; off <<= 1) {
        int v = (t >= off) ? part[t - off] : 0;
        __syncthreads();
        part[t] += v;
        __syncthreads();
    }
    int run = part[t] - s;
#pragma unroll
    for (int i = 0; i < 20; i++) {
        int n = b + i;
        if (n < NN) {
            rowptr[n] = run;
            cursor[n] = run;
            run += loc[i];
        }
    }
    if (t == 0) rowptr[NN] = EE;
}

__global__ void csr_scatter(const int* __restrict__ dst, int* __restrict__ cursor,
                            int* __restrict__ eidx) {
    int e = blockIdx.x * blockDim.x + threadIdx.x;
    if (e < EE) {
        int pos = atomicAdd(&cursor[dst[e]], 1);
        eidx[pos] = e;
    }
}

// ================= per-dst aggregate gather =================
__global__ __launch_bounds__(128)
void agg_gather(const float* __restrict__ hF, const int* __restrict__ src,
                const int* __restrict__ et, const int* __restrict__ rowptr,
                const int* __restrict__ eidx,
                __half* __restrict__ sHi, __half* __restrict__ sLo, int* __restrict__ cnt) {
    int d = blockIdx.x;
    int t = threadIdx.x;
    int beg = rowptr[d], end = rowptr[d + 1];
    int c = t * 4;
    float4 acc[KT];
#pragma unroll
    for (int k = 0; k < KT; k++) acc[k] = make_float4(0.f, 0.f, 0.f, 0.f);
    int cn[KT] = {0, 0, 0, 0};

    __shared__ int ssrc[128];
    __shared__ int sket[128];
    for (int base = beg; base < end; base += 128) {
        int jj = base + t;
        if (jj < end) {
            int e = eidx[jj];
            ssrc[t] = src[e];
            sket[t] = et[e];
        }
        __syncthreads();
        int m = min(128, end - base);
        for (int q = 0; q < m; q++) {
            int s = ssrc[q];
            int k = sket[q];
            float4 v = *(const float4*)(hF + (size_t)s * 512 + c);
#pragma unroll
            for (int kk = 0; kk < KT; kk++) {
                if (k == kk) {
                    acc[kk].x += v.x; acc[kk].y += v.y;
                    acc[kk].z += v.z; acc[kk].w += v.w;
                    cn[kk]++;
                }
            }
        }
        __syncthreads();
    }
#pragma unroll
    for (int k = 0; k < KT; k++) {
        __half2 h0, l0, h1, l1;
        split2(acc[k].x, acc[k].y, h0, l0);
        split2(acc[k].z, acc[k].w, h1, l1);
        size_t o = (size_t)d * 2048 + k * 512 + c;
        *(__half2*)(sHi + o) = h0;
        *(__half2*)(sHi + o + 2) = h1;
        *(__half2*)(sLo + o) = l0;
        *(__half2*)(sLo + o + 2) = l1;
    }
    if (t == 0) {
#pragma unroll
        for (int k = 0; k < KT; k++) cnt[d * KT + k] = cn[k];
    }
}

// aF[n][c] = sum_k cnt[n][k]*bmsg[k][c]
__global__ void bias_a_kernel(const float* __restrict__ bmsg, const int* __restrict__ cnt,
                              float* __restrict__ aF) {
    int n = blockIdx.x;
    __shared__ float bm[KT * H1];
    for (int i = threadIdx.x; i < KT * H1; i += blockDim.x) bm[i] = bmsg[i];
    __shared__ int cn[KT];
    if (threadIdx.x < KT) cn[threadIdx.x] = cnt[n * KT + threadIdx.x];
    __syncthreads();
    float c0 = (float)cn[0], c1 = (float)cn[1], c2 = (float)cn[2], c3 = (float)cn[3];
    for (int c = threadIdx.x; c < H1; c += blockDim.x)
        aF[(size_t)n * H1 + c] =
            c0 * bm[c] + c1 * bm[H1 + c] + c2 * bm[2 * H1 + c] + c3 * bm[3 * H1 + c];
}

// GRU pointwise: writes hF fp32 + h halves
__global__ void gru_kernel(const float* __restrict__ P, const float* __restrict__ Qi,
                           const float* __restrict__ Qh,
                           const float* __restrict__ b_ih, const float* __restrict__ b_hh,
                           float* __restrict__ hF, __half* __restrict__ ahHi,
                           __half* __restrict__ ahLo) {
    int i = blockIdx.x * blockDim.x + threadIdx.x;
    int st = gridDim.x * blockDim.x;
    int tot = NN * 256;
    for (; i < tot; i += st) {
        int n = i >> 8;
        int c = (i & 255) * 2;
        float hv[2];
#pragma unroll
        for (int u = 0; u < 2; u++) {
            int cc = c + u;
            float r = sigm(P[(size_t)n * 1024 + cc] + b_ih[cc] + b_hh[cc]);
            float z = sigm(P[(size_t)n * 1024 + 512 + cc] + b_ih[512 + cc] + b_hh[512 + cc]);
            float nn = tanhf(Qi[(size_t)n * 512 + cc] + b_ih[1024 + cc] +
                             r * (Qh[(size_t)n * 512 + cc] + b_hh[1024 + cc]));
            float ho = hF[(size_t)n * 512 + cc];
            hv[u] = (1.f - z) * nn + z * ho;
        }
        *(float2*)(hF + (size_t)n * 512 + c) = make_float2(hv[0], hv[1]);
        __half2 h, l;
        split2(hv[0], hv[1], h, l);
        *(__half2*)(ahHi + (size_t)n * 1024 + 512 + c) = h;
        *(__half2*)(ahLo + (size_t)n * 1024 + 512 + c) = l;
    }
}

// L2-normalize + sigmoid; writes h halves only
__global__ void norm_sig_kernel(const float* __restrict__ hF, __half* __restrict__ ahHi,
                                __half* __restrict__ ahLo) {
    int n = blockIdx.x;
    int t = threadIdx.x;  // 128
    const float* row = hF + (size_t)n * 512;
    float4 v = *(const float4*)(row + t * 4);
    float s = v.x * v.x + v.y * v.y + v.z * v.z + v.w * v.w;
    __shared__ float sm[128];
    sm[t] = s;
    __syncthreads();
    for (int o = 64; o > 0; o >>= 1) {
        if (t < o) sm[t] += sm[t + o];
        __syncthreads();
    }
    float inv = 1.f / fmaxf(sqrtf(sm[0]), 1e-12f);
    float o0 = sigm(v.x * inv), o1 = sigm(v.y * inv), o2 = sigm(v.z * inv), o3 = sigm(v.w * inv);
    __half2 h0, l0, h1, l1;
    split2(o0, o1, h0, l0);
    split2(o2, o3, h1, l1);
    size_t off = (size_t)n * 1024 + 512 + t * 4;
    *(__half2*)(ahHi + off) = h0;
    *(__half2*)(ahHi + off + 2) = h1;
    *(__half2*)(ahLo + off) = l0;
    *(__half2*)(ahLo + off + 2) = l1;
}

__global__ void elr_kernel(const float* __restrict__ feat, const float* __restrict__ attn_l,
                           const float* __restrict__ attn_r,
                           float* __restrict__ el, float* __restrict__ er) {
    int n = blockIdx.x;
    int t = threadIdx.x;  // 256
    float f0 = feat[(size_t)n * H1 + t];
    float f1 = feat[(size_t)n * H1 + H2C + t];
    float vals[4] = {f0 * attn_l[t], f0 * attn_r[t], f1 * attn_l[H2C + t], f1 * attn_r[H2C + t]};
    float outp[4];
    __shared__ float sm[256];
#pragma unroll
    for (int q = 0; q < 4; q++) {
        sm[t] = vals[q];
        __syncthreads();
        for (int o = 128; o > 0; o >>= 1) {
            if (t < o) sm[t] += sm[t + o];
            __syncthreads();
        }
        outp[q] = sm[0];
        __syncthreads();
    }
    if (t == 0) {
        el[n * 2] = outp[0];
        er[n * 2] = outp[1];
        el[n * 2 + 1] = outp[2];
        er[n * 2 + 1] = outp[3];
    }
}

// ================= fused GAT per-dst =================
__global__ __launch_bounds__(128)
void gat_fused(const int* __restrict__ src, const int* __restrict__ rowptr,
               const int* __restrict__ eidx, const float* __restrict__ el,
               const float* __restrict__ er, const float* __restrict__ feat,
               const int* __restrict__ gid, const float* __restrict__ gat_bias,
               float* __restrict__ hg) {
    int d = blockIdx.x;
    int t = threadIdx.x;
    int beg = rowptr[d], end = rowptr[d + 1];
    float er0 = er[2 * d], er1 = er[2 * d + 1];

    __shared__ float red[128];
    float m0 = -1e30f, m1 = -1e30f;
    for (int j = beg + t; j < end; j += 128) {
        int s = src[eidx[j]];
        float v0 = el[2 * s] + er0;      v0 = v0 > 0.f ? v0 : 0.2f * v0;
        float v1 = el[2 * s + 1] + er1;  v1 = v1 > 0.f ? v1 : 0.2f * v1;
        m0 = fmaxf(m0, v0);
        m1 = fmaxf(m1, v1);
    }
    red[t] = m0; __syncthreads();
    for (int o = 64; o > 0; o >>= 1) { if (t < o) red[t] = fmaxf(red[t], red[t + o]); __syncthreads(); }
    float M0 = red[0]; __syncthreads();
    red[t] = m1; __syncthreads();
    for (int o = 64; o > 0; o >>= 1) { if (t < o) red[t] = fmaxf(red[t], red[t + o]); __syncthreads(); }
    float M1 = red[0]; __syncthreads();

    float s0 = 0.f, s1 = 0.f;
    for (int j = beg + t; j < end; j += 128) {
        int s = src[eidx[j]];
        float v0 = el[2 * s] + er0;      v0 = v0 > 0.f ? v0 : 0.2f * v0;
        float v1 = el[2 * s + 1] + er1;  v1 = v1 > 0.f ? v1 : 0.2f * v1;
        s0 += expf(v0 - M0);
        s1 += expf(v1 - M1);
    }
    red[t] = s0; __syncthreads();
    for (int o = 64; o > 0; o >>= 1) { if (t < o) red[t] += red[t + o]; __syncthreads(); }
    float D0 = red[0]; __syncthreads();
    red[t] = s1; __syncthreads();
    for (int o = 64; o > 0; o >>= 1) { if (t < o) red[t] += red[t + o]; __syncthreads(); }
    float D1 = red[0]; __syncthreads();
    float inv0 = (D0 > 0.f) ? 1.f / D0 : 0.f;
    float inv1 = (D1 > 0.f) ? 1.f / D1 : 0.f;

    __shared__ float sal0[128], sal1[128];
    __shared__ int ssrc[128];
    int c = t * 4;
    bool head0 = c < H2C;
    float4 acc = make_float4(0.f, 0.f, 0.f, 0.f);
    for (int base = beg; base < end; base += 128) {
        int jj = base + t;
        if (jj < end) {
            int s = src[eidx[jj]];
            float v0 = el[2 * s] + er0;      v0 = v0 > 0.f ? v0 : 0.2f * v0;
            float v1 = el[2 * s + 1] + er1;  v1 = v1 > 0.f ? v1 : 0.2f * v1;
            sal0[t] = expf(v0 - M0) * inv0;
            sal1[t] = expf(v1 - M1) * inv1;
            ssrc[t] = s;
        }
        __syncthreads();
        int m = min(128, end - base);
        for (int q = 0; q < m; q++) {
            float al = head0 ? sal0[q] : sal1[q];
            float4 v = *(const float4*)(feat + (size_t)ssrc[q] * 512 + c);
            acc.x += al * v.x; acc.y += al * v.y;
            acc.z += al * v.z; acc.w += al * v.w;
        }
        __syncthreads();
    }
    float4 b = *(const float4*)(gat_bias + c);
    int g = gid[d];
    atomicAdd(&hg[(size_t)g * 512 + c + 0], fmaxf(acc.x + b.x, 0.f));
    atomicAdd(&hg[(size_t)g * 512 + c + 1], fmaxf(acc.y + b.y, 0.f));
    atomicAdd(&hg[(size_t)g * 512 + c + 2], fmaxf(acc.z + b.z, 0.f));
    atomicAdd(&hg[(size_t)g * 512 + c + 3], fmaxf(acc.w + b.w, 0.f));
}

__global__ void gcnt_kernel(const int* __restrict__ gid, float* __restrict__ gcnt) {
    int n = blockIdx.x * blockDim.x + threadIdx.x;
    if (n < NN) atomicAdd(&gcnt[gid[n]], 1.f);
}

__global__ void final_kernel(const float* __restrict__ hg, const float* __restrict__ gcnt,
                             const float* __restrict__ cw, const float* __restrict__ cb,
                             float* __restrict__ out) {
    int g = blockIdx.x >> 1, hd = blockIdx.x & 1;
    int t = threadIdx.x;  // 256
    __shared__ float row[H2C];
    float inv = 1.f / fmaxf(gcnt[g], 1.f);
    row[t] = hg[(size_t)g * H1 + hd * H2C + t] * inv;
    __syncthreads();
    if (t < CC) {
        float s = cb[t];
        for (int j = 0; j < H2C; j++) s += row[j] * cw[t * H2C + j];
        out[((size_t)g * HEADS + hd) * CC + t] = s;
    }
}

// ================= launch =================
extern "C" void kernel_launch(void* const* d_in, const int* in_sizes, int n_in,
                              void* d_out, int out_size) {
    const float* in_feat  = (const float*)d_in[0];
    const int*   src      = (const int*)d_in[1];
    const int*   dst      = (const int*)d_in[2];
    const int*   etype    = (const int*)d_in[3];
    const int*   gid      = (const int*)d_in[4];
    const float* Wmsg     = (const float*)d_in[5];
    const float* bmsg     = (const float*)d_in[6];
    const float* w_ih     = (const float*)d_in[7];
    const float* w_hh     = (const float*)d_in[8];
    const float* b_ih     = (const float*)d_in[9];
    const float* b_hh     = (const float*)d_in[10];
    const float* fc_w     = (const float*)d_in[11];
    const float* attn_l   = (const float*)d_in[12];
    const float* attn_r   = (const float*)d_in[13];
    const float* gat_bias = (const float*)d_in[14];
    const float* cw       = (const float*)d_in[15];
    const float* cb       = (const float*)d_in[16];
    float* out = (float*)d_out;

    cudaFuncSetAttribute(gemm_h, cudaFuncAttributeMaxDynamicSharedMemorySize, SMEM_BYTES);

    float* base = nullptr;
    cudaGetSymbolAddress((void**)&base, g_buf);

    float*  hF    = base + OFF_HF;
    float*  aF    = base + OFF_AF;
    float*  P     = base + OFF_P;
    float*  Qi    = base + OFF_QI;
    float*  Qh    = base + OFF_QH;
    float*  feat  = base + OFF_FEAT;
    __half* ahHi  = (__half*)(base + OFF_AHH);
    __half* ahLo  = (__half*)(base + OFF_AHL);
    __half* sHi   = (__half*)(base + OFF_SAGH);
    __half* sLo   = (__half*)(base + OFF_SAGL);
    __half* WmH   = (__half*)(base + OFF_WMH);
    __half* WmL   = (__half*)(base + OFF_WML);
    __half* B1H   = (__half*)(base + OFF_B1H);
    __half* B1L   = (__half*)(base + OFF_B1L);
    __half* WiH   = (__half*)(base + OFF_WIH);
    __half* WiL   = (__half*)(base + OFF_WIL);
    __half* WhH   = (__half*)(base + OFF_WHH);
    __half* WhL   = (__half*)(base + OFF_WHL);
    __half* FcH   = (__half*)(base + OFF_FCH);
    __half* FcL   = (__half*)(base + OFF_FCL);
    float*  el    = base + OFF_EL;
    float*  er    = base + OFF_ER;
    float*  hg    = base + OFF_HG;
    float*  gcnt  = base + OFF_GCNT;
    int*    deg   = (int*)(base + OFF_DEG);
    int*    rptr  = (int*)(base + OFF_RPTR);
    int*    cur   = (int*)(base + OFF_CUR);
    int*    eidx  = (int*)(base + OFF_EIDX);
    int*    cnt   = (int*)(base + OFF_CNT);

    conv_split<<<512, 256>>>(Wmsg, WmH, WmL, (size_t)2048 * 512 / 2);
    prep_b1_h<<<512, 256>>>(w_ih, w_hh, B1H, B1L);
    prep_t512_h<<<256, 256>>>(w_ih, 1024, WiH, WiL);
    prep_t512_h<<<256, 256>>>(w_hh, 1024, WhH, WhL);
    prep_t512_h<<<256, 256>>>(fc_w, 0, FcH, FcL);
    pad_kernel<<<4096, 256>>>(in_feat, hF, ahHi, ahLo);

    zero_f4<<<32, 256>>>((float4*)deg, NN / 4);
    csr_count<<<(EE + 255) / 256, 256>>>(dst, deg);
    csr_scan<<<1, 1024>>>(deg, rptr, cur);
    csr_scatter<<<(EE + 255) / 256, 256>>>(dst, cur, eidx);

    auto gemm = [](const __half* Ah, const __half* Al, int lda,
                   const __half* Bh, const __half* Bl, int ldb,
                   float* Cf, int ldc, __half* Oh, __half* Ol, int ldo,
                   int M, int K, int N, int mode) {
        dim3 g((M + 127) / 128, N / 128);
        gemm_h<<<g, 256, SMEM_BYTES>>>(Ah, Al, lda, Bh, Bl, ldb, Cf, ldc, Oh, Ol, ldo, M, K, mode);
    };

    for (int step = 0; step < NSTEPS; step++) {
        agg_gather<<<NN, 128>>>(hF, src, etype, rptr, eidx, sHi, sLo, cnt);
        bias_a_kernel<<<NN, 256>>>(bmsg, cnt, aF);
        gemm(sHi, sLo, 2048, WmH, WmL, 512, aF, 512, ahHi, ahLo, 1024, NN, 2048, 512, 1);
        gemm(ahHi, ahLo, 1024, B1H, B1L, 1024, P, 1024, nullptr, nullptr, 0, NN, 1024, 1024, 0);
        gemm(ahHi, ahLo, 1024, WiH, WiL, 512, Qi, 512, nullptr, nullptr, 0, NN, 512, 512, 0);
        gemm(ahHi + 512, ahLo + 512, 1024, WhH, WhL, 512, Qh, 512, nullptr, nullptr, 0, NN, 512, 512, 0);
        gru_kernel<<<4096, 256>>>(P, Qi, Qh, b_ih, b_hh, hF, ahHi, ahLo);
    }

    norm_sig_kernel<<<NN, 128>>>(hF, ahHi, ahLo);
    gemm(ahHi + 512, ahLo + 512, 1024, FcH, FcL, 512, feat, 512, nullptr, nullptr, 0, NN, 512, 512, 0);
    elr_kernel<<<NN, 256>>>(feat, attn_l, attn_r, el, er);

    zero_f4<<<32, 256>>>((float4*)hg, ((size_t)GG * 512 + GG) / 4);
    gat_fused<<<NN, 128>>>(src, rptr, eidx, el, er, feat, gid, gat_bias, hg);
    gcnt_kernel<<<(NN + 255) / 256, 256>>>(gid, gcnt);
    final_kernel<<<GG * HEADS, 256>>>(hg, gcnt, cw, cb, out);
}

// round 7
// speedup vs baseline: 3.5441x; 1.2872x over previous
#include <cuda_runtime.h>
#include <cuda_fp16.h>
#include <math.h>
#include <stdint.h>

#define NN 20000
#define EE 320000
#define GG 64
#define INF_ 256
#define H1 512
#define H2C 256
#define HEADS 2
#define CC 16
#define NSTEPS 4
#define KT 4

// ================= scratch layout (float units) =================
constexpr size_t OFF_HF    = 0;                               // NN x 512 f32 (h)
constexpr size_t OFF_AF    = OFF_HF + (size_t)NN * 512;       // NN x 512 f32 (a bias base)
constexpr size_t OFF_P     = OFF_AF + (size_t)NN * 512;       // NN x 1024 f32
constexpr size_t OFF_QI    = OFF_P + (size_t)NN * 1024;       // NN x 512
constexpr size_t OFF_QH    = OFF_QI + (size_t)NN * 512;
constexpr size_t OFF_FEAT  = OFF_QH + (size_t)NN * 512;       // NN x 512
constexpr size_t OFF_AHH   = OFF_FEAT + (size_t)NN * 512;     // NN x 1024 halves (hi)
constexpr size_t OFF_AHL   = OFF_AHH + (size_t)NN * 512;      // NN x 1024 halves (lo)
constexpr size_t OFF_SAGH  = OFF_AHL + (size_t)NN * 512;      // NN x 2048 halves
constexpr size_t OFF_SAGL  = OFF_SAGH + (size_t)NN * 1024;
constexpr size_t OFF_WMH   = OFF_SAGL + (size_t)NN * 1024;    // 2048x512 halves
constexpr size_t OFF_WML   = OFF_WMH + 524288;
constexpr size_t OFF_B1H   = OFF_WML + 524288;                // 1024x1024 halves
constexpr size_t OFF_B1L   = OFF_B1H + 524288;
constexpr size_t OFF_WIH   = OFF_B1L + 524288;                // 512x512 halves
constexpr size_t OFF_WIL   = OFF_WIH + 131072;
constexpr size_t OFF_WHH   = OFF_WIL + 131072;
constexpr size_t OFF_WHL   = OFF_WHH + 131072;
constexpr size_t OFF_FCH   = OFF_WHL + 131072;
constexpr size_t OFF_FCL   = OFF_FCH + 131072;
constexpr size_t OFF_EL    = OFF_FCL + 131072;                // NN x 2
constexpr size_t OFF_ER    = OFF_EL + (size_t)NN * 2;
constexpr size_t OFF_HG    = OFF_ER + (size_t)NN * 2;         // GG x 512
constexpr size_t OFF_GCNT  = OFF_HG + (size_t)GG * 512;       // GG
// int regions
constexpr size_t OFF_DEG   = OFF_GCNT + GG;                   // NN ints
constexpr size_t OFF_RPTR  = OFF_DEG + NN;                    // NN+4 ints
constexpr size_t OFF_CUR   = OFF_RPTR + NN + 4;               // NN ints
constexpr size_t OFF_EIDX  = OFF_CUR + NN;                    // EE ints
constexpr size_t OFF_CNT   = OFF_EIDX + EE;                   // NN*4 ints
constexpr size_t TOTAL_F   = OFF_CNT + (size_t)NN * 4 + 16;

__device__ __align__(16) float g_buf[TOTAL_F];

// ================= PTX helpers =================
__device__ __forceinline__ uint32_t smem_to_u32(const void* p) {
    uint32_t a;
    asm("{ .reg .u64 t; cvta.to.shared.u64 t, %1; cvt.u32.u64 %0, t; }" : "=r"(a) : "l"(p));
    return a;
}
__device__ __forceinline__ void ldsm_x4(uint32_t addr, uint32_t* r) {
    asm volatile("ldmatrix.sync.aligned.m8n8.x4.shared.b16 {%0,%1,%2,%3}, [%4];"
                 : "=r"(r[0]), "=r"(r[1]), "=r"(r[2]), "=r"(r[3]) : "r"(addr));
}
__device__ __forceinline__ void ldsm_x4_t(uint32_t addr, uint32_t* r) {
    asm volatile("ldmatrix.sync.aligned.m8n8.x4.trans.shared.b16 {%0,%1,%2,%3}, [%4];"
                 : "=r"(r[0]), "=r"(r[1]), "=r"(r[2]), "=r"(r[3]) : "r"(addr));
}
__device__ __forceinline__ void mma_f16(float* c, const uint32_t* a, const uint32_t* b) {
    asm volatile(
        "mma.sync.aligned.m16n8k16.row.col.f32.f16.f16.f32 "
        "{%0,%1,%2,%3},{%4,%5,%6,%7},{%8,%9},{%0,%1,%2,%3};"
        : "+f"(c[0]), "+f"(c[1]), "+f"(c[2]), "+f"(c[3])
        : "r"(a[0]), "r"(a[1]), "r"(a[2]), "r"(a[3]), "r"(b[0]), "r"(b[1]));
}
__device__ __forceinline__ void split2(float x0, float x1, __half2& hi, __half2& lo) {
    __half h0 = __float2half_rn(x0), h1 = __float2half_rn(x1);
    hi = __halves2half2(h0, h1);
    lo = __halves2half2(__float2half_rn(x0 - __half2float(h0)),
                        __float2half_rn(x1 - __half2float(h1)));
}
// 16B async copy; sz = 16 (copy) or 0 (zero-fill)
__device__ __forceinline__ void cpa16(uint32_t d, const void* g, int sz) {
    asm volatile("cp.async.cg.shared.global [%0], [%1], 16, %2;"
                 :: "r"(d), "l"(g), "r"(sz) : "memory");
}
__device__ __forceinline__ void cpa_commit() {
    asm volatile("cp.async.commit_group;" ::: "memory");
}
template <int N>
__device__ __forceinline__ void cpa_wait() {
    asm volatile("cp.async.wait_group %0;" :: "n"(N) : "memory");
}

// ================= SMEM layout for gemm_h (half-element offsets) =================
#define AS_PITCH 40
#define BS_PITCH 136
#define SM_AHI(b) ((b) * 5120)
#define SM_ALO(b) (10240 + (b) * 5120)
#define SM_BHI(b) (20480 + (b) * 4352)
#define SM_BLO(b) (29184 + (b) * 4352)
#define SMEM_HALFS 37888
#define SMEM_BYTES (SMEM_HALFS * 2)

// ================= half-plane HMMA GEMM (cp.async staged) =================
// acc = A @ B with A=(Ahi+Alo) [M,K] halves row-major stride lda,
// B=(Bhi+Blo) [K,N] halves row-major stride ldb (3-term split product).
// mode 0: Cf[r][c] = acc (fp32, stride ldc)
// mode 1: v = Cf_in + acc; split v -> (Ohi,Olo) halves, stride ldo
__global__ __launch_bounds__(256, 2)
void gemm_h(const __half* __restrict__ Ahi, const __half* __restrict__ Alo, int lda,
            const __half* __restrict__ Bhi, const __half* __restrict__ Blo, int ldb,
            float* __restrict__ Cf, int ldc,
            __half* __restrict__ Ohi, __half* __restrict__ Olo, int ldo,
            int M, int K, int mode) {
    extern __shared__ __half smh[];
    const uint32_t sbase = smem_to_u32(smh);

    const int tid = threadIdx.x;
    const int lane = tid & 31;
    const int wid = tid >> 5;
    const int wm = wid >> 2;
    const int wn = wid & 3;
    const int blockM = blockIdx.x * 128;
    const int n0 = blockIdx.y * 128;

    const int ar = tid >> 1, ac = (tid & 1) * 16;
    const int bk = tid >> 3, bn = (tid & 7) * 16;
    const bool aval = (blockM + ar) < M;
    const int asz = aval ? 16 : 0;
    const __half* Ahp = Ahi + (size_t)(aval ? blockM + ar : 0) * lda + ac;
    const __half* Alp = Alo + (size_t)(aval ? blockM + ar : 0) * lda + ac;
    const __half* Bhp = Bhi + (size_t)bk * ldb + n0 + bn;
    const __half* Blp = Blo + (size_t)bk * ldb + n0 + bn;

    // per-thread smem byte targets (two 16B slots each, +0 / +16 bytes)
    const uint32_t dAh = sbase + 2 * (uint32_t)(ar * AS_PITCH + ac);
    const uint32_t dAl = dAh + 2 * 10240;
    const uint32_t dBh = sbase + 2 * (uint32_t)(20480 + bk * BS_PITCH + bn);
    const uint32_t dBl = dBh + 2 * 8704;

    const int nC = K >> 5;

    float acc[4][4][4];
#pragma unroll
    for (int mi = 0; mi < 4; mi++)
#pragma unroll
        for (int ni = 0; ni < 4; ni++)
#pragma unroll
            for (int q = 0; q < 4; q++) acc[mi][ni][q] = 0.f;

    // issue chunk c into buffer c&1
    auto issue = [&](int c) {
        const int boff = (c & 1) * 2 * 5120;   // A buffers: 5120 halves apart
        const int boffB = (c & 1) * 2 * 4352;  // B buffers: 4352 halves apart
        const __half* ah = Ahp + c * 32;
        const __half* al = Alp + c * 32;
        const __half* bh = Bhp + (size_t)c * 32 * ldb;
        const __half* bl = Blp + (size_t)c * 32 * ldb;
        cpa16(dAh + boff, ah, asz);
        cpa16(dAh + boff + 16, ah + 8, asz);
        cpa16(dAl + boff, al, asz);
        cpa16(dAl + boff + 16, al + 8, asz);
        cpa16(dBh + boffB, bh, 16);
        cpa16(dBh + boffB + 16, bh + 8, 16);
        cpa16(dBl + boffB, bl, 16);
        cpa16(dBl + boffB + 16, bl + 8, 16);
        cpa_commit();
    };

    issue(0);

    const int lrow = lane & 15;
    const int lhalf = (lane >> 4) * 8;

    for (int c = 0; c < nC; c++) {
        const int b = c & 1;
        if (c + 1 < nC) {
            issue(c + 1);
            cpa_wait<1>();
        } else {
            cpa_wait<0>();
        }
        __syncthreads();

#pragma unroll
        for (int s = 0; s < 2; s++) {
            uint32_t ahi[4][4], alo[4][4], bhi[4][2], blo[4][2];
#pragma unroll
            for (int mi = 0; mi < 4; mi++) {
                uint32_t off = (uint32_t)((wm * 64 + mi * 16 + lrow) * AS_PITCH + s * 16 + lhalf);
                ldsm_x4(sbase + 2 * (SM_AHI(b) + off), ahi[mi]);
                ldsm_x4(sbase + 2 * (SM_ALO(b) + off), alo[mi]);
            }
#pragma unroll
            for (int np = 0; np < 2; np++) {
                uint32_t off = (uint32_t)((s * 16 + lrow) * BS_PITCH + wn * 32 + np * 16 + lhalf);
                uint32_t t[4];
                ldsm_x4_t(sbase + 2 * (SM_BHI(b) + off), t);
                bhi[2 * np][0] = t[0]; bhi[2 * np][1] = t[1];
                bhi[2 * np + 1][0] = t[2]; bhi[2 * np + 1][1] = t[3];
                ldsm_x4_t(sbase + 2 * (SM_BLO(b) + off), t);
                blo[2 * np][0] = t[0]; blo[2 * np][1] = t[1];
                blo[2 * np + 1][0] = t[2]; blo[2 * np + 1][1] = t[3];
            }
#pragma unroll
            for (int mi = 0; mi < 4; mi++)
#pragma unroll
                for (int ni = 0; ni < 4; ni++) {
                    mma_f16(acc[mi][ni], ahi[mi], bhi[ni]);
                    mma_f16(acc[mi][ni], ahi[mi], blo[ni]);
                    mma_f16(acc[mi][ni], alo[mi], bhi[ni]);
                }
        }
        __syncthreads();
    }

    const int row0 = blockM + wm * 64;
    const int col0 = n0 + wn * 32;
#pragma unroll
    for (int mi = 0; mi < 4; mi++) {
        int r0 = row0 + mi * 16 + (lane >> 2);
        int r1 = r0 + 8;
#pragma unroll
        for (int ni = 0; ni < 4; ni++) {
            int cc = col0 + ni * 8 + (lane & 3) * 2;
#pragma unroll
            for (int h = 0; h < 2; h++) {
                int r = h ? r1 : r0;
                if (r >= M) continue;
                float v0 = acc[mi][ni][2 * h], v1 = acc[mi][ni][2 * h + 1];
                if (mode == 0) {
                    *(float2*)(Cf + (size_t)r * ldc + cc) = make_float2(v0, v1);
                } else {
                    float2 ci = *(const float2*)(Cf + (size_t)r * ldc + cc);
                    v0 += ci.x; v1 += ci.y;
                    __half2 hi, lo;
                    split2(v0, v1, hi, lo);
                    *(__half2*)(Ohi + (size_t)r * ldo + cc) = hi;
                    *(__half2*)(Olo + (size_t)r * ldo + cc) = lo;
                }
            }
        }
    }
}

// ================= misc =================
__device__ __forceinline__ float sigm(float x) { return 1.f / (1.f + expf(-x)); }

__global__ void zero_f4(float4* p, size_t n4) {
    size_t i = (size_t)blockIdx.x * blockDim.x + threadIdx.x;
    size_t st = (size_t)gridDim.x * blockDim.x;
    for (; i < n4; i += st) p[i] = make_float4(0.f, 0.f, 0.f, 0.f);
}

__global__ void conv_split(const float* __restrict__ in, __half* __restrict__ hi,
                           __half* __restrict__ lo, size_t n2) {
    size_t i = (size_t)blockIdx.x * blockDim.x + threadIdx.x;
    size_t st = (size_t)gridDim.x * blockDim.x;
    for (; i < n2; i += st) {
        float2 v = *(const float2*)(in + 2 * i);
        __half2 h, l;
        split2(v.x, v.y, h, l);
        *(__half2*)(hi + 2 * i) = h;
        *(__half2*)(lo + 2 * i) = l;
    }
}

__global__ void prep_b1_h(const float* __restrict__ w_ih, const float* __restrict__ w_hh,
                          __half* __restrict__ hi, __half* __restrict__ lo) {
    int i = blockIdx.x * blockDim.x + threadIdx.x;
    int st = gridDim.x * blockDim.x;
    for (; i < 1024 * 512; i += st) {
        int k = i >> 9;
        int n = (i & 511) * 2;
        float v0 = (k < 512) ? w_ih[(size_t)n * 512 + k] : w_hh[(size_t)n * 512 + k - 512];
        float v1 = (k < 512) ? w_ih[(size_t)(n + 1) * 512 + k] : w_hh[(size_t)(n + 1) * 512 + k - 512];
        __half2 h, l;
        split2(v0, v1, h, l);
        *(__half2*)(hi + (size_t)k * 1024 + n) = h;
        *(__half2*)(lo + (size_t)k * 1024 + n) = l;
    }
}

__global__ void prep_t512_h(const float* __restrict__ W, int rowoff,
                            __half* __restrict__ hi, __half* __restrict__ lo) {
    int i = blockIdx.x * blockDim.x + threadIdx.x;
    int st = gridDim.x * blockDim.x;
    for (; i < 512 * 256; i += st) {
        int k = i >> 8;
        int n = (i & 255) * 2;
        float v0 = W[(size_t)(rowoff + n) * 512 + k];
        float v1 = W[(size_t)(rowoff + n + 1) * 512 + k];
        __half2 h, l;
        split2(v0, v1, h, l);
        *(__half2*)(hi + (size_t)k * 512 + n) = h;
        *(__half2*)(lo + (size_t)k * 512 + n) = l;
    }
}

__global__ void pad_kernel(const float* __restrict__ x, float* __restrict__ hF,
                           __half* __restrict__ ahHi, __half* __restrict__ ahLo) {
    int i = blockIdx.x * blockDim.x + threadIdx.x;
    int st = gridDim.x * blockDim.x;
    int tot = NN * 256;
    for (; i < tot; i += st) {
        int n = i >> 8;
        int c = (i & 255) * 2;
        float v0 = (c < INF_) ? x[(size_t)n * INF_ + c] : 0.f;
        float v1 = (c + 1 < INF_) ? x[(size_t)n * INF_ + c + 1] : 0.f;
        *(float2*)(hF + (size_t)n * 512 + c) = make_float2(v0, v1);
        __half2 h, l;
        split2(v0, v1, h, l);
        *(__half2*)(ahHi + (size_t)n * 1024 + 512 + c) = h;
        *(__half2*)(ahLo + (size_t)n * 1024 + 512 + c) = l;
    }
}

// ================= CSR build =================
__global__ void csr_count(const int* __restrict__ dst, int* __restrict__ deg) {
    int e = blockIdx.x * blockDim.x + threadIdx.x;
    if (e < EE) atomicAdd(&deg[dst[e]], 1);
}

__global__ void csr_scan(const int* __restrict__ deg, int* __restrict__ rowptr,
                         int* __restrict__ cursor) {
    __shared__ int part[1024];
    int t = threadIdx.x;
    int b = t * 20;
    int loc[20];
    int s = 0;
#pragma unroll
    for (int i = 0; i < 20; i++) {
        int n = b + i;
        loc[i] = (n < NN) ? deg[n] : 0;
        s += loc[i];
    }
    part[t] = s;
    __syncthreads();
    for (int off = 1; off < 1024; off <<= 1) {
        int v = (t >= off) ? part[t - off] : 0;
        __syncthreads();
        part[t] += v;
        __syncthreads();
    }
    int run = part[t] - s;
#pragma unroll
    for (int i = 0; i < 20; i++) {
        int n = b + i;
        if (n < NN) {
            rowptr[n] = run;
            cursor[n] = run;
            run += loc[i];
        }
    }
    if (t == 0) rowptr[NN] = EE;
}

__global__ void csr_scatter(const int* __restrict__ dst, int* __restrict__ cursor,
                            int* __restrict__ eidx) {
    int e = blockIdx.x * blockDim.x + threadIdx.x;
    if (e < EE) {
        int pos = atomicAdd(&cursor[dst[e]], 1);
        eidx[pos] = e;
    }
}

// ================= per-dst aggregate gather =================
__global__ __launch_bounds__(128)
void agg_gather(const float* __restrict__ hF, const int* __restrict__ src,
                const int* __restrict__ et, const int* __restrict__ rowptr,
                const int* __restrict__ eidx,
                __half* __restrict__ sHi, __half* __restrict__ sLo, int* __restrict__ cnt) {
    int d = blockIdx.x;
    int t = threadIdx.x;
    int beg = rowptr[d], end = rowptr[d + 1];
    int c = t * 4;
    float4 acc[KT];
#pragma unroll
    for (int k = 0; k < KT; k++) acc[k] = make_float4(0.f, 0.f, 0.f, 0.f);
    int cn[KT] = {0, 0, 0, 0};

    __shared__ int ssrc[128];
    __shared__ int sket[128];
    for (int base = beg; base < end; base += 128) {
        int jj = base + t;
        if (jj < end) {
            int e = eidx[jj];
            ssrc[t] = src[e];
            sket[t] = et[e];
        }
        __syncthreads();
        int m = min(128, end - base);
        for (int q = 0; q < m; q++) {
            int s = ssrc[q];
            int k = sket[q];
            float4 v = *(const float4*)(hF + (size_t)s * 512 + c);
#pragma unroll
            for (int kk = 0; kk < KT; kk++) {
                if (k == kk) {
                    acc[kk].x += v.x; acc[kk].y += v.y;
                    acc[kk].z += v.z; acc[kk].w += v.w;
                    cn[kk]++;
                }
            }
        }
        __syncthreads();
    }
#pragma unroll
    for (int k = 0; k < KT; k++) {
        __half2 h0, l0, h1, l1;
        split2(acc[k].x, acc[k].y, h0, l0);
        split2(acc[k].z, acc[k].w, h1, l1);
        size_t o = (size_t)d * 2048 + k * 512 + c;
        *(__half2*)(sHi + o) = h0;
        *(__half2*)(sHi + o + 2) = h1;
        *(__half2*)(sLo + o) = l0;
        *(__half2*)(sLo + o + 2) = l1;
    }
    if (t == 0) {
#pragma unroll
        for (int k = 0; k < KT; k++) cnt[d * KT + k] = cn[k];
    }
}

// aF[n][c] = sum_k cnt[n][k]*bmsg[k][c]
__global__ void bias_a_kernel(const float* __restrict__ bmsg, const int* __restrict__ cnt,
                              float* __restrict__ aF) {
    int n = blockIdx.x;
    __shared__ float bm[KT * H1];
    for (int i = threadIdx.x; i < KT * H1; i += blockDim.x) bm[i] = bmsg[i];
    __shared__ int cn[KT];
    if (threadIdx.x < KT) cn[threadIdx.x] = cnt[n * KT + threadIdx.x];
    __syncthreads();
    float c0 = (float)cn[0], c1 = (float)cn[1], c2 = (float)cn[2], c3 = (float)cn[3];
    for (int c = threadIdx.x; c < H1; c += blockDim.x)
        aF[(size_t)n * H1 + c] =
            c0 * bm[c] + c1 * bm[H1 + c] + c2 * bm[2 * H1 + c] + c3 * bm[3 * H1 + c];
}

// GRU pointwise: writes hF fp32 + h halves
__global__ void gru_kernel(const float* __restrict__ P, const float* __restrict__ Qi,
                           const float* __restrict__ Qh,
                           const float* __restrict__ b_ih, const float* __restrict__ b_hh,
                           float* __restrict__ hF, __half* __restrict__ ahHi,
                           __half* __restrict__ ahLo) {
    int i = blockIdx.x * blockDim.x + threadIdx.x;
    int st = gridDim.x * blockDim.x;
    int tot = NN * 256;
    for (; i < tot; i += st) {
        int n = i >> 8;
        int c = (i & 255) * 2;
        float hv[2];
#pragma unroll
        for (int u = 0; u < 2; u++) {
            int cc = c + u;
            float r = sigm(P[(size_t)n * 1024 + cc] + b_ih[cc] + b_hh[cc]);
            float z = sigm(P[(size_t)n * 1024 + 512 + cc] + b_ih[512 + cc] + b_hh[512 + cc]);
            float nn = tanhf(Qi[(size_t)n * 512 + cc] + b_ih[1024 + cc] +
                             r * (Qh[(size_t)n * 512 + cc] + b_hh[1024 + cc]));
            float ho = hF[(size_t)n * 512 + cc];
            hv[u] = (1.f - z) * nn + z * ho;
        }
        *(float2*)(hF + (size_t)n * 512 + c) = make_float2(hv[0], hv[1]);
        __half2 h, l;
        split2(hv[0], hv[1], h, l);
        *(__half2*)(ahHi + (size_t)n * 1024 + 512 + c) = h;
        *(__half2*)(ahLo + (size_t)n * 1024 + 512 + c) = l;
    }
}

// L2-normalize + sigmoid; writes h halves only
__global__ void norm_sig_kernel(const float* __restrict__ hF, __half* __restrict__ ahHi,
                                __half* __restrict__ ahLo) {
    int n = blockIdx.x;
    int t = threadIdx.x;  // 128
    const float* row = hF + (size_t)n * 512;
    float4 v = *(const float4*)(row + t * 4);
    float s = v.x * v.x + v.y * v.y + v.z * v.z + v.w * v.w;
    __shared__ float sm[128];
    sm[t] = s;
    __syncthreads();
    for (int o = 64; o > 0; o >>= 1) {
        if (t < o) sm[t] += sm[t + o];
        __syncthreads();
    }
    float inv = 1.f / fmaxf(sqrtf(sm[0]), 1e-12f);
    float o0 = sigm(v.x * inv), o1 = sigm(v.y * inv), o2 = sigm(v.z * inv), o3 = sigm(v.w * inv);
    __half2 h0, l0, h1, l1;
    split2(o0, o1, h0, l0);
    split2(o2, o3, h1, l1);
    size_t off = (size_t)n * 1024 + 512 + t * 4;
    *(__half2*)(ahHi + off) = h0;
    *(__half2*)(ahHi + off + 2) = h1;
    *(__half2*)(ahLo + off) = l0;
    *(__half2*)(ahLo + off + 2) = l1;
}

__global__ void elr_kernel(const float* __restrict__ feat, const float* __restrict__ attn_l,
                           const float* __restrict__ attn_r,
                           float* __restrict__ el, float* __restrict__ er) {
    int n = blockIdx.x;
    int t = threadIdx.x;  // 256
    float f0 = feat[(size_t)n * H1 + t];
    float f1 = feat[(size_t)n * H1 + H2C + t];
    float vals[4] = {f0 * attn_l[t], f0 * attn_r[t], f1 * attn_l[H2C + t], f1 * attn_r[H2C + t]};
    float outp[4];
    __shared__ float sm[256];
#pragma unroll
    for (int q = 0; q < 4; q++) {
        sm[t] = vals[q];
        __syncthreads();
        for (int o = 128; o > 0; o >>= 1) {
            if (t < o) sm[t] += sm[t + o];
            __syncthreads();
        }
        outp[q] = sm[0];
        __syncthreads();
    }
    if (t == 0) {
        el[n * 2] = outp[0];
        er[n * 2] = outp[1];
        el[n * 2 + 1] = outp[2];
        er[n * 2 + 1] = outp[3];
    }
}

// ================= fused GAT per-dst =================
__global__ __launch_bounds__(128)
void gat_fused(const int* __restrict__ src, const int* __restrict__ rowptr,
               const int* __restrict__ eidx, const float* __restrict__ el,
               const float* __restrict__ er, const float* __restrict__ feat,
               const int* __restrict__ gid, const float* __restrict__ gat_bias,
               float* __restrict__ hg) {
    int d = blockIdx.x;
    int t = threadIdx.x;
    int beg = rowptr[d], end = rowptr[d + 1];
    float er0 = er[2 * d], er1 = er[2 * d + 1];

    __shared__ float red[128];
    float m0 = -1e30f, m1 = -1e30f;
    for (int j = beg + t; j < end; j += 128) {
        int s = src[eidx[j]];
        float v0 = el[2 * s] + er0;      v0 = v0 > 0.f ? v0 : 0.2f * v0;
        float v1 = el[2 * s + 1] + er1;  v1 = v1 > 0.f ? v1 : 0.2f * v1;
        m0 = fmaxf(m0, v0);
        m1 = fmaxf(m1, v1);
    }
    red[t] = m0; __syncthreads();
    for (int o = 64; o > 0; o >>= 1) { if (t < o) red[t] = fmaxf(red[t], red[t + o]); __syncthreads(); }
    float M0 = red[0]; __syncthreads();
    red[t] = m1; __syncthreads();
    for (int o = 64; o > 0; o >>= 1) { if (t < o) red[t] = fmaxf(red[t], red[t + o]); __syncthreads(); }
    float M1 = red[0]; __syncthreads();

    float s0 = 0.f, s1 = 0.f;
    for (int j = beg + t; j < end; j += 128) {
        int s = src[eidx[j]];
        float v0 = el[2 * s] + er0;      v0 = v0 > 0.f ? v0 : 0.2f * v0;
        float v1 = el[2 * s + 1] + er1;  v1 = v1 > 0.f ? v1 : 0.2f * v1;
        s0 += expf(v0 - M0);
        s1 += expf(v1 - M1);
    }
    red[t] = s0; __syncthreads();
    for (int o = 64; o > 0; o >>= 1) { if (t < o) red[t] += red[t + o]; __syncthreads(); }
    float D0 = red[0]; __syncthreads();
    red[t] = s1; __syncthreads();
    for (int o = 64; o > 0; o >>= 1) { if (t < o) red[t] += red[t + o]; __syncthreads(); }
    float D1 = red[0]; __syncthreads();
    float inv0 = (D0 > 0.f) ? 1.f / D0 : 0.f;
    float inv1 = (D1 > 0.f) ? 1.f / D1 : 0.f;

    __shared__ float sal0[128], sal1[128];
    __shared__ int ssrc[128];
    int c = t * 4;
    bool head0 = c < H2C;
    float4 acc = make_float4(0.f, 0.f, 0.f, 0.f);
    for (int base = beg; base < end; base += 128) {
        int jj = base + t;
        if (jj < end) {
            int s = src[eidx[jj]];
            float v0 = el[2 * s] + er0;      v0 = v0 > 0.f ? v0 : 0.2f * v0;
            float v1 = el[2 * s + 1] + er1;  v1 = v1 > 0.f ? v1 : 0.2f * v1;
            sal0[t] = expf(v0 - M0) * inv0;
            sal1[t] = expf(v1 - M1) * inv1;
            ssrc[t] = s;
        }
        __syncthreads();
        int m = min(128, end - base);
        for (int q = 0; q < m; q++) {
            float al = head0 ? sal0[q] : sal1[q];
            float4 v = *(const float4*)(feat + (size_t)ssrc[q] * 512 + c);
            acc.x += al * v.x; acc.y += al * v.y;
            acc.z += al * v.z; acc.w += al * v.w;
        }
        __syncthreads();
    }
    float4 b = *(const float4*)(gat_bias + c);
    int g = gid[d];
    atomicAdd(&hg[(size_t)g * 512 + c + 0], fmaxf(acc.x + b.x, 0.f));
    atomicAdd(&hg[(size_t)g * 512 + c + 1], fmaxf(acc.y + b.y, 0.f));
    atomicAdd(&hg[(size_t)g * 512 + c + 2], fmaxf(acc.z + b.z, 0.f));
    atomicAdd(&hg[(size_t)g * 512 + c + 3], fmaxf(acc.w + b.w, 0.f));
}

__global__ void gcnt_kernel(const int* __restrict__ gid, float* __restrict__ gcnt) {
    int n = blockIdx.x * blockDim.x + threadIdx.x;
    if (n < NN) atomicAdd(&gcnt[gid[n]], 1.f);
}

__global__ void final_kernel(const float* __restrict__ hg, const float* __restrict__ gcnt,
                             const float* __restrict__ cw, const float* __restrict__ cb,
                             float* __restrict__ out) {
    int g = blockIdx.x >> 1, hd = blockIdx.x & 1;
    int t = threadIdx.x;  // 256
    __shared__ float row[H2C];
    float inv = 1.f / fmaxf(gcnt[g], 1.f);
    row[t] = hg[(size_t)g * H1 + hd * H2C + t] * inv;
    __syncthreads();
    if (t < CC) {
        float s = cb[t];
        for (int j = 0; j < H2C; j++) s += row[j] * cw[t * H2C + j];
        out[((size_t)g * HEADS + hd) * CC + t] = s;
    }
}

// ================= launch =================
extern "C" void kernel_launch(void* const* d_in, const int* in_sizes, int n_in,
                              void* d_out, int out_size) {
    const float* in_feat  = (const float*)d_in[0];
    const int*   src      = (const int*)d_in[1];
    const int*   dst      = (const int*)d_in[2];
    const int*   etype    = (const int*)d_in[3];
    const int*   gid      = (const int*)d_in[4];
    const float* Wmsg     = (const float*)d_in[5];
    const float* bmsg     = (const float*)d_in[6];
    const float* w_ih     = (const float*)d_in[7];
    const float* w_hh     = (const float*)d_in[8];
    const float* b_ih     = (const float*)d_in[9];
    const float* b_hh     = (const float*)d_in[10];
    const float* fc_w     = (const float*)d_in[11];
    const float* attn_l   = (const float*)d_in[12];
    const float* attn_r   = (const float*)d_in[13];
    const float* gat_bias = (const float*)d_in[14];
    const float* cw       = (const float*)d_in[15];
    const float* cb       = (const float*)d_in[16];
    float* out = (float*)d_out;

    cudaFuncSetAttribute(gemm_h, cudaFuncAttributeMaxDynamicSharedMemorySize, SMEM_BYTES);

    float* base = nullptr;
    cudaGetSymbolAddress((void**)&base, g_buf);

    float*  hF    = base + OFF_HF;
    float*  aF    = base + OFF_AF;
    float*  P     = base + OFF_P;
    float*  Qi    = base + OFF_QI;
    float*  Qh    = base + OFF_QH;
    float*  feat  = base + OFF_FEAT;
    __half* ahHi  = (__half*)(base + OFF_AHH);
    __half* ahLo  = (__half*)(base + OFF_AHL);
    __half* sHi   = (__half*)(base + OFF_SAGH);
    __half* sLo   = (__half*)(base + OFF_SAGL);
    __half* WmH   = (__half*)(base + OFF_WMH);
    __half* WmL   = (__half*)(base + OFF_WML);
    __half* B1H   = (__half*)(base + OFF_B1H);
    __half* B1L   = (__half*)(base + OFF_B1L);
    __half* WiH   = (__half*)(base + OFF_WIH);
    __half* WiL   = (__half*)(base + OFF_WIL);
    __half* WhH   = (__half*)(base + OFF_WHH);
    __half* WhL   = (__half*)(base + OFF_WHL);
    __half* FcH   = (__half*)(base + OFF_FCH);
    __half* FcL   = (__half*)(base + OFF_FCL);
    float*  el    = base + OFF_EL;
    float*  er    = base + OFF_ER;
    float*  hg    = base + OFF_HG;
    float*  gcnt  = base + OFF_GCNT;
    int*    deg   = (int*)(base + OFF_DEG);
    int*    rptr  = (int*)(base + OFF_RPTR);
    int*    cur   = (int*)(base + OFF_CUR);
    int*    eidx  = (int*)(base + OFF_EIDX);
    int*    cnt   = (int*)(base + OFF_CNT);

    conv_split<<<512, 256>>>(Wmsg, WmH, WmL, (size_t)2048 * 512 / 2);
    prep_b1_h<<<512, 256>>>(w_ih, w_hh, B1H, B1L);
    prep_t512_h<<<256, 256>>>(w_ih, 1024, WiH, WiL);
    prep_t512_h<<<256, 256>>>(w_hh, 1024, WhH, WhL);
    prep_t512_h<<<256, 256>>>(fc_w, 0, FcH, FcL);
    pad_kernel<<<4096, 256>>>(in_feat, hF, ahHi, ahLo);

    zero_f4<<<32, 256>>>((float4*)deg, NN / 4);
    csr_count<<<(EE + 255) / 256, 256>>>(dst, deg);
    csr_scan<<<1, 1024>>>(deg, rptr, cur);
    csr_scatter<<<(EE + 255) / 256, 256>>>(dst, cur, eidx);

    auto gemm = [](const __half* Ah, const __half* Al, int lda,
                   const __half* Bh, const __half* Bl, int ldb,
                   float* Cf, int ldc, __half* Oh, __half* Ol, int ldo,
                   int M, int K, int N, int mode) {
        dim3 g((M + 127) / 128, N / 128);
        gemm_h<<<g, 256, SMEM_BYTES>>>(Ah, Al, lda, Bh, Bl, ldb, Cf, ldc, Oh, Ol, ldo, M, K, mode);
    };

    for (int step = 0; step < NSTEPS; step++) {
        agg_gather<<<NN, 128>>>(hF, src, etype, rptr, eidx, sHi, sLo, cnt);
        bias_a_kernel<<<NN, 256>>>(bmsg, cnt, aF);
        gemm(sHi, sLo, 2048, WmH, WmL, 512, aF, 512, ahHi, ahLo, 1024, NN, 2048, 512, 1);
        gemm(ahHi, ahLo, 1024, B1H, B1L, 1024, P, 1024, nullptr, nullptr, 0, NN, 1024, 1024, 0);
        gemm(ahHi, ahLo, 1024, WiH, WiL, 512, Qi, 512, nullptr, nullptr, 0, NN, 512, 512, 0);
        gemm(ahHi + 512, ahLo + 512, 1024, WhH, WhL, 512, Qh, 512, nullptr, nullptr, 0, NN, 512, 512, 0);
        gru_kernel<<<4096, 256>>>(P, Qi, Qh, b_ih, b_hh, hF, ahHi, ahLo);
    }

    norm_sig_kernel<<<NN, 128>>>(hF, ahHi, ahLo);
    gemm(ahHi + 512, ahLo + 512, 1024, FcH, FcL, 512, feat, 512, nullptr, nullptr, 0, NN, 512, 512, 0);
    elr_kernel<<<NN, 256>>>(feat, attn_l, attn_r, el, er);

    zero_f4<<<32, 256>>>((float4*)hg, ((size_t)GG * 512 + GG) / 4);
    gat_fused<<<NN, 128>>>(src, rptr, eidx, el, er, feat, gid, gat_bias, hg);
    gcnt_kernel<<<(NN + 255) / 256, 256>>>(gid, gcnt);
    final_kernel<<<GG * HEADS, 256>>>(hg, gcnt, cw, cb, out);
}

// round 8
// speedup vs baseline: 4.5674x; 1.2887x over previous
#include <cuda_runtime.h>
#include <cuda_fp16.h>
#include <math.h>
#include <stdint.h>

#define NN 20000
#define EE 320000
#define GG 64
#define INF_ 256
#define H1 512
#define H2C 256
#define HEADS 2
#define CC 16
#define NSTEPS 4
#define KT 4

// ================= scratch layout (float units) =================
constexpr size_t OFF_HF    = 0;                               // NN x 512 f32 (h)
constexpr size_t OFF_AF    = OFF_HF + (size_t)NN * 512;       // NN x 512 f32 (a bias base)
constexpr size_t OFF_P     = OFF_AF + (size_t)NN * 512;       // NN x 1024 f32
constexpr size_t OFF_QI    = OFF_P + (size_t)NN * 1024;       // NN x 512
constexpr size_t OFF_QH    = OFF_QI + (size_t)NN * 512;
constexpr size_t OFF_FEAT  = OFF_QH + (size_t)NN * 512;       // NN x 512
constexpr size_t OFF_AHH   = OFF_FEAT + (size_t)NN * 512;     // NN x 1024 halves (hi)
constexpr size_t OFF_AHL   = OFF_AHH + (size_t)NN * 512;      // NN x 1024 halves (lo)
constexpr size_t OFF_SAGH  = OFF_AHL + (size_t)NN * 512;      // NN x 2048 halves
constexpr size_t OFF_SAGL  = OFF_SAGH + (size_t)NN * 1024;
constexpr size_t OFF_WMH   = OFF_SAGL + (size_t)NN * 1024;    // 2048x512 halves
constexpr size_t OFF_B1H   = OFF_WMH + 524288;                // 1024x1024 halves
constexpr size_t OFF_WIH   = OFF_B1H + 524288;                // 512x512 halves
constexpr size_t OFF_WHH   = OFF_WIH + 131072;
constexpr size_t OFF_FCH   = OFF_WHH + 131072;
constexpr size_t OFF_EL    = OFF_FCH + 131072;                // NN x 2
constexpr size_t OFF_ER    = OFF_EL + (size_t)NN * 2;
constexpr size_t OFF_HG    = OFF_ER + (size_t)NN * 2;         // GG x 512
constexpr size_t OFF_GCNT  = OFF_HG + (size_t)GG * 512;       // GG
// int regions
constexpr size_t OFF_DEG   = OFF_GCNT + GG;                   // NN ints
constexpr size_t OFF_RPTR  = OFF_DEG + NN;                    // NN+4 ints
constexpr size_t OFF_CUR   = OFF_RPTR + NN + 4;               // NN ints
constexpr size_t OFF_EIDX  = OFF_CUR + NN;                    // EE ints
constexpr size_t OFF_CNT   = OFF_EIDX + EE;                   // NN*4 ints
constexpr size_t TOTAL_F   = OFF_CNT + (size_t)NN * 4 + 16;

__device__ __align__(16) float g_buf[TOTAL_F];

// ================= PTX helpers =================
__device__ __forceinline__ uint32_t smem_to_u32(const void* p) {
    uint32_t a;
    asm("{ .reg .u64 t; cvta.to.shared.u64 t, %1; cvt.u32.u64 %0, t; }" : "=r"(a) : "l"(p));
    return a;
}
__device__ __forceinline__ void ldsm_x4(uint32_t addr, uint32_t* r) {
    asm volatile("ldmatrix.sync.aligned.m8n8.x4.shared.b16 {%0,%1,%2,%3}, [%4];"
                 : "=r"(r[0]), "=r"(r[1]), "=r"(r[2]), "=r"(r[3]) : "r"(addr));
}
__device__ __forceinline__ void ldsm_x4_t(uint32_t addr, uint32_t* r) {
    asm volatile("ldmatrix.sync.aligned.m8n8.x4.trans.shared.b16 {%0,%1,%2,%3}, [%4];"
                 : "=r"(r[0]), "=r"(r[1]), "=r"(r[2]), "=r"(r[3]) : "r"(addr));
}
__device__ __forceinline__ void mma_f16(float* c, const uint32_t* a, const uint32_t* b) {
    asm volatile(
        "mma.sync.aligned.m16n8k16.row.col.f32.f16.f16.f32 "
        "{%0,%1,%2,%3},{%4,%5,%6,%7},{%8,%9},{%0,%1,%2,%3};"
        : "+f"(c[0]), "+f"(c[1]), "+f"(c[2]), "+f"(c[3])
        : "r"(a[0]), "r"(a[1]), "r"(a[2]), "r"(a[3]), "r"(b[0]), "r"(b[1]));
}
__device__ __forceinline__ void split2(float x0, float x1, __half2& hi, __half2& lo) {
    __half h0 = __float2half_rn(x0), h1 = __float2half_rn(x1);
    hi = __halves2half2(h0, h1);
    lo = __halves2half2(__float2half_rn(x0 - __half2float(h0)),
                        __float2half_rn(x1 - __half2float(h1)));
}
__device__ __forceinline__ void cpa16(uint32_t d, const void* g, int sz) {
    asm volatile("cp.async.cg.shared.global [%0], [%1], 16, %2;"
                 :: "r"(d), "l"(g), "r"(sz) : "memory");
}
__device__ __forceinline__ void cpa_commit() {
    asm volatile("cp.async.commit_group;" ::: "memory");
}
template <int N>
__device__ __forceinline__ void cpa_wait() {
    asm volatile("cp.async.wait_group %0;" :: "n"(N) : "memory");
}

// ================= SMEM layout for gemm_h (half-element offsets) =================
// A hi: 2 x 5120 (128 rows x 40 pitch), A lo: 2 x 5120, B hi: 2 x 4352 (32 x 136)
#define AS_PITCH 40
#define BS_PITCH 136
#define SM_AHI(b) ((b) * 5120)
#define SM_ALO(b) (10240 + (b) * 5120)
#define SM_BHI(b) (20480 + (b) * 4352)
#define SMEM_HALFS 29184
#define SMEM_BYTES (SMEM_HALFS * 2)

// ================= half-plane HMMA GEMM (2-term split, cp.async staged) =================
// acc = (Ahi+Alo) @ Bhi;  A [M,K] halves row-major stride lda, Bhi [K,N] halves stride ldb.
// mode 0: Cf[r][c] = acc (fp32 stride ldc)
// mode 1: v = Cf_in + acc; split v -> (Ohi,Olo) halves stride ldo
__global__ __launch_bounds__(256, 2)
void gemm_h(const __half* __restrict__ Ahi, const __half* __restrict__ Alo, int lda,
            const __half* __restrict__ Bhi, int ldb,
            float* __restrict__ Cf, int ldc,
            __half* __restrict__ Ohi, __half* __restrict__ Olo, int ldo,
            int M, int K, int mode) {
    extern __shared__ __half smh[];
    const uint32_t sbase = smem_to_u32(smh);

    const int tid = threadIdx.x;
    const int lane = tid & 31;
    const int wid = tid >> 5;
    const int wm = wid >> 2;
    const int wn = wid & 3;
    const int blockM = blockIdx.x * 128;
    const int n0 = blockIdx.y * 128;

    const int ar = tid >> 1, ac = (tid & 1) * 16;
    const int bk = tid >> 3, bn = (tid & 7) * 16;
    const bool aval = (blockM + ar) < M;
    const int asz = aval ? 16 : 0;
    const __half* Ahp = Ahi + (size_t)(aval ? blockM + ar : 0) * lda + ac;
    const __half* Alp = Alo + (size_t)(aval ? blockM + ar : 0) * lda + ac;
    const __half* Bhp = Bhi + (size_t)bk * ldb + n0 + bn;

    const uint32_t dAh = sbase + 2 * (uint32_t)(ar * AS_PITCH + ac);
    const uint32_t dAl = dAh + 2 * 10240;
    const uint32_t dBh = sbase + 2 * (uint32_t)(20480 + bk * BS_PITCH + bn);

    const int nC = K >> 5;

    float acc[4][4][4];
#pragma unroll
    for (int mi = 0; mi < 4; mi++)
#pragma unroll
        for (int ni = 0; ni < 4; ni++)
#pragma unroll
            for (int q = 0; q < 4; q++) acc[mi][ni][q] = 0.f;

    auto issue = [&](int c) {
        const int boffA = (c & 1) * 2 * 5120;
        const int boffB = (c & 1) * 2 * 4352;
        const __half* ah = Ahp + c * 32;
        const __half* al = Alp + c * 32;
        const __half* bh = Bhp + (size_t)c * 32 * ldb;
        cpa16(dAh + boffA, ah, asz);
        cpa16(dAh + boffA + 16, ah + 8, asz);
        cpa16(dAl + boffA, al, asz);
        cpa16(dAl + boffA + 16, al + 8, asz);
        cpa16(dBh + boffB, bh, 16);
        cpa16(dBh + boffB + 16, bh + 8, 16);
        cpa_commit();
    };

    issue(0);

    const int lrow = lane & 15;
    const int lhalf = (lane >> 4) * 8;

    for (int c = 0; c < nC; c++) {
        const int b = c & 1;
        if (c + 1 < nC) {
            issue(c + 1);
            cpa_wait<1>();
        } else {
            cpa_wait<0>();
        }
        __syncthreads();

#pragma unroll
        for (int s = 0; s < 2; s++) {
            // preload B fragments for this k16
            uint32_t bhi[4][2];
#pragma unroll
            for (int np = 0; np < 2; np++) {
                uint32_t off = (uint32_t)((s * 16 + lrow) * BS_PITCH + wn * 32 + np * 16 + lhalf);
                uint32_t t[4];
                ldsm_x4_t(sbase + 2 * (SM_BHI(b) + off), t);
                bhi[2 * np][0] = t[0]; bhi[2 * np][1] = t[1];
                bhi[2 * np + 1][0] = t[2]; bhi[2 * np + 1][1] = t[3];
            }
            // per-mi A fragments (short-lived)
#pragma unroll
            for (int mi = 0; mi < 4; mi++) {
                uint32_t off = (uint32_t)((wm * 64 + mi * 16 + lrow) * AS_PITCH + s * 16 + lhalf);
                uint32_t ahi[4], alo[4];
                ldsm_x4(sbase + 2 * (SM_AHI(b) + off), ahi);
                ldsm_x4(sbase + 2 * (SM_ALO(b) + off), alo);
#pragma unroll
                for (int ni = 0; ni < 4; ni++) {
                    mma_f16(acc[mi][ni], ahi, bhi[ni]);
                    mma_f16(acc[mi][ni], alo, bhi[ni]);
                }
            }
        }
        __syncthreads();
    }

    const int row0 = blockM + wm * 64;
    const int col0 = n0 + wn * 32;
#pragma unroll
    for (int mi = 0; mi < 4; mi++) {
        int r0 = row0 + mi * 16 + (lane >> 2);
        int r1 = r0 + 8;
#pragma unroll
        for (int ni = 0; ni < 4; ni++) {
            int cc = col0 + ni * 8 + (lane & 3) * 2;
#pragma unroll
            for (int h = 0; h < 2; h++) {
                int r = h ? r1 : r0;
                if (r >= M) continue;
                float v0 = acc[mi][ni][2 * h], v1 = acc[mi][ni][2 * h + 1];
                if (mode == 0) {
                    *(float2*)(Cf + (size_t)r * ldc + cc) = make_float2(v0, v1);
                } else {
                    float2 ci = *(const float2*)(Cf + (size_t)r * ldc + cc);
                    v0 += ci.x; v1 += ci.y;
                    __half2 hi, lo;
                    split2(v0, v1, hi, lo);
                    *(__half2*)(Ohi + (size_t)r * ldo + cc) = hi;
                    *(__half2*)(Olo + (size_t)r * ldo + cc) = lo;
                }
            }
        }
    }
}

// ================= misc =================
__device__ __forceinline__ float sigm(float x) { return 1.f / (1.f + expf(-x)); }

__global__ void zero_f4(float4* p, size_t n4) {
    size_t i = (size_t)blockIdx.x * blockDim.x + threadIdx.x;
    size_t st = (size_t)gridDim.x * blockDim.x;
    for (; i < n4; i += st) p[i] = make_float4(0.f, 0.f, 0.f, 0.f);
}

// fp32 -> fp16 (hi plane only, for weights)
__global__ void conv_h(const float* __restrict__ in, __half* __restrict__ hi, size_t n2) {
    size_t i = (size_t)blockIdx.x * blockDim.x + threadIdx.x;
    size_t st = (size_t)gridDim.x * blockDim.x;
    for (; i < n2; i += st) {
        float2 v = *(const float2*)(in + 2 * i);
        *(__half2*)(hi + 2 * i) = __halves2half2(__float2half_rn(v.x), __float2half_rn(v.y));
    }
}

// B1[k][n] fp16: k<512 -> w_ih[n][k], else w_hh[n][k-512]; n in 0..1023
__global__ void prep_b1_h(const float* __restrict__ w_ih, const float* __restrict__ w_hh,
                          __half* __restrict__ hi) {
    int i = blockIdx.x * blockDim.x + threadIdx.x;
    int st = gridDim.x * blockDim.x;
    for (; i < 1024 * 512; i += st) {
        int k = i >> 9;
        int n = (i & 511) * 2;
        float v0 = (k < 512) ? w_ih[(size_t)n * 512 + k] : w_hh[(size_t)n * 512 + k - 512];
        float v1 = (k < 512) ? w_ih[(size_t)(n + 1) * 512 + k] : w_hh[(size_t)(n + 1) * 512 + k - 512];
        *(__half2*)(hi + (size_t)k * 1024 + n) = __halves2half2(__float2half_rn(v0), __float2half_rn(v1));
    }
}

// T[k][n] fp16 = W[(rowoff+n)*512 + k]
__global__ void prep_t512_h(const float* __restrict__ W, int rowoff, __half* __restrict__ hi) {
    int i = blockIdx.x * blockDim.x + threadIdx.x;
    int st = gridDim.x * blockDim.x;
    for (; i < 512 * 256; i += st) {
        int k = i >> 8;
        int n = (i & 255) * 2;
        float v0 = W[(size_t)(rowoff + n) * 512 + k];
        float v1 = W[(size_t)(rowoff + n + 1) * 512 + k];
        *(__half2*)(hi + (size_t)k * 512 + n) = __halves2half2(__float2half_rn(v0), __float2half_rn(v1));
    }
}

// pad input -> hF fp32 + h halves (ah cols 512..1023)
__global__ void pad_kernel(const float* __restrict__ x, float* __restrict__ hF,
                           __half* __restrict__ ahHi, __half* __restrict__ ahLo) {
    int i = blockIdx.x * blockDim.x + threadIdx.x;
    int st = gridDim.x * blockDim.x;
    int tot = NN * 256;
    for (; i < tot; i += st) {
        int n = i >> 8;
        int c = (i & 255) * 2;
        float v0 = (c < INF_) ? x[(size_t)n * INF_ + c] : 0.f;
        float v1 = (c + 1 < INF_) ? x[(size_t)n * INF_ + c + 1] : 0.f;
        *(float2*)(hF + (size_t)n * 512 + c) = make_float2(v0, v1);
        __half2 h, l;
        split2(v0, v1, h, l);
        *(__half2*)(ahHi + (size_t)n * 1024 + 512 + c) = h;
        *(__half2*)(ahLo + (size_t)n * 1024 + 512 + c) = l;
    }
}

// ================= CSR build =================
__global__ void csr_count(const int* __restrict__ dst, int* __restrict__ deg) {
    int e = blockIdx.x * blockDim.x + threadIdx.x;
    if (e < EE) atomicAdd(&deg[dst[e]], 1);
}

__global__ void csr_scan(const int* __restrict__ deg, int* __restrict__ rowptr,
                         int* __restrict__ cursor) {
    __shared__ int part[1024];
    int t = threadIdx.x;
    int b = t * 20;
    int loc[20];
    int s = 0;
#pragma unroll
    for (int i = 0; i < 20; i++) {
        int n = b + i;
        loc[i] = (n < NN) ? deg[n] : 0;
        s += loc[i];
    }
    part[t] = s;
    __syncthreads();
    for (int off = 1; off < 1024; off <<= 1) {
        int v = (t >= off) ? part[t - off] : 0;
        __syncthreads();
        part[t] += v;
        __syncthreads();
    }
    int run = part[t] - s;
#pragma unroll
    for (int i = 0; i < 20; i++) {
        int n = b + i;
        if (n < NN) {
            rowptr[n] = run;
            cursor[n] = run;
            run += loc[i];
        }
    }
    if (t == 0) rowptr[NN] = EE;
}

__global__ void csr_scatter(const int* __restrict__ dst, int* __restrict__ cursor,
                            int* __restrict__ eidx) {
    int e = blockIdx.x * blockDim.x + threadIdx.x;
    if (e < EE) {
        int pos = atomicAdd(&cursor[dst[e]], 1);
        eidx[pos] = e;
    }
}

// ================= per-dst aggregate gather =================
__global__ __launch_bounds__(128)
void agg_gather(const float* __restrict__ hF, const int* __restrict__ src,
                const int* __restrict__ et, const int* __restrict__ rowptr,
                const int* __restrict__ eidx,
                __half* __restrict__ sHi, __half* __restrict__ sLo, int* __restrict__ cnt) {
    int d = blockIdx.x;
    int t = threadIdx.x;
    int beg = rowptr[d], end = rowptr[d + 1];
    int c = t * 4;
    float4 acc[KT];
#pragma unroll
    for (int k = 0; k < KT; k++) acc[k] = make_float4(0.f, 0.f, 0.f, 0.f);
    int cn[KT] = {0, 0, 0, 0};

    __shared__ int ssrc[128];
    __shared__ int sket[128];
    for (int base = beg; base < end; base += 128) {
        int jj = base + t;
        if (jj < end) {
            int e = eidx[jj];
            ssrc[t] = src[e];
            sket[t] = et[e];
        }
        __syncthreads();
        int m = min(128, end - base);
        for (int q = 0; q < m; q++) {
            int s = ssrc[q];
            int k = sket[q];
            float4 v = *(const float4*)(hF + (size_t)s * 512 + c);
#pragma unroll
            for (int kk = 0; kk < KT; kk++) {
                if (k == kk) {
                    acc[kk].x += v.x; acc[kk].y += v.y;
                    acc[kk].z += v.z; acc[kk].w += v.w;
                    cn[kk]++;
                }
            }
        }
        __syncthreads();
    }
#pragma unroll
    for (int k = 0; k < KT; k++) {
        __half2 h0, l0, h1, l1;
        split2(acc[k].x, acc[k].y, h0, l0);
        split2(acc[k].z, acc[k].w, h1, l1);
        size_t o = (size_t)d * 2048 + k * 512 + c;
        *(__half2*)(sHi + o) = h0;
        *(__half2*)(sHi + o + 2) = h1;
        *(__half2*)(sLo + o) = l0;
        *(__half2*)(sLo + o + 2) = l1;
    }
    if (t == 0) {
#pragma unroll
        for (int k = 0; k < KT; k++) cnt[d * KT + k] = cn[k];
    }
}

// aF[n][c] = sum_k cnt[n][k]*bmsg[k][c]
__global__ void bias_a_kernel(const float* __restrict__ bmsg, const int* __restrict__ cnt,
                              float* __restrict__ aF) {
    int n = blockIdx.x;
    __shared__ float bm[KT * H1];
    for (int i = threadIdx.x; i < KT * H1; i += blockDim.x) bm[i] = bmsg[i];
    __shared__ int cn[KT];
    if (threadIdx.x < KT) cn[threadIdx.x] = cnt[n * KT + threadIdx.x];
    __syncthreads();
    float c0 = (float)cn[0], c1 = (float)cn[1], c2 = (float)cn[2], c3 = (float)cn[3];
    for (int c = threadIdx.x; c < H1; c += blockDim.x)
        aF[(size_t)n * H1 + c] =
            c0 * bm[c] + c1 * bm[H1 + c] + c2 * bm[2 * H1 + c] + c3 * bm[3 * H1 + c];
}

// GRU pointwise: writes hF fp32 + h halves
__global__ void gru_kernel(const float* __restrict__ P, const float* __restrict__ Qi,
                           const float* __restrict__ Qh,
                           const float* __restrict__ b_ih, const float* __restrict__ b_hh,
                           float* __restrict__ hF, __half* __restrict__ ahHi,
                           __half* __restrict__ ahLo) {
    int i = blockIdx.x * blockDim.x + threadIdx.x;
    int st = gridDim.x * blockDim.x;
    int tot = NN * 256;
    for (; i < tot; i += st) {
        int n = i >> 8;
        int c = (i & 255) * 2;
        float hv[2];
#pragma unroll
        for (int u = 0; u < 2; u++) {
            int cc = c + u;
            float r = sigm(P[(size_t)n * 1024 + cc] + b_ih[cc] + b_hh[cc]);
            float z = sigm(P[(size_t)n * 1024 + 512 + cc] + b_ih[512 + cc] + b_hh[512 + cc]);
            float nn = tanhf(Qi[(size_t)n * 512 + cc] + b_ih[1024 + cc] +
                             r * (Qh[(size_t)n * 512 + cc] + b_hh[1024 + cc]));
            float ho = hF[(size_t)n * 512 + cc];
            hv[u] = (1.f - z) * nn + z * ho;
        }
        *(float2*)(hF + (size_t)n * 512 + c) = make_float2(hv[0], hv[1]);
        __half2 h, l;
        split2(hv[0], hv[1], h, l);
        *(__half2*)(ahHi + (size_t)n * 1024 + 512 + c) = h;
        *(__half2*)(ahLo + (size_t)n * 1024 + 512 + c) = l;
    }
}

// L2-normalize + sigmoid; writes h halves only
__global__ void norm_sig_kernel(const float* __restrict__ hF, __half* __restrict__ ahHi,
                                __half* __restrict__ ahLo) {
    int n = blockIdx.x;
    int t = threadIdx.x;  // 128
    const float* row = hF + (size_t)n * 512;
    float4 v = *(const float4*)(row + t * 4);
    float s = v.x * v.x + v.y * v.y + v.z * v.z + v.w * v.w;
    __shared__ float sm[128];
    sm[t] = s;
    __syncthreads();
    for (int o = 64; o > 0; o >>= 1) {
        if (t < o) sm[t] += sm[t + o];
        __syncthreads();
    }
    float inv = 1.f / fmaxf(sqrtf(sm[0]), 1e-12f);
    float o0 = sigm(v.x * inv), o1 = sigm(v.y * inv), o2 = sigm(v.z * inv), o3 = sigm(v.w * inv);
    __half2 h0, l0, h1, l1;
    split2(o0, o1, h0, l0);
    split2(o2, o3, h1, l1);
    size_t off = (size_t)n * 1024 + 512 + t * 4;
    *(__half2*)(ahHi + off) = h0;
    *(__half2*)(ahHi + off + 2) = h1;
    *(__half2*)(ahLo + off) = l0;
    *(__half2*)(ahLo + off + 2) = l1;
}

__global__ void elr_kernel(const float* __restrict__ feat, const float* __restrict__ attn_l,
                           const float* __restrict__ attn_r,
                           float* __restrict__ el, float* __restrict__ er) {
    int n = blockIdx.x;
    int t = threadIdx.x;  // 256
    float f0 = feat[(size_t)n * H1 + t];
    float f1 = feat[(size_t)n * H1 + H2C + t];
    float vals[4] = {f0 * attn_l[t], f0 * attn_r[t], f1 * attn_l[H2C + t], f1 * attn_r[H2C + t]};
    float outp[4];
    __shared__ float sm[256];
#pragma unroll
    for (int q = 0; q < 4; q++) {
        sm[t] = vals[q];
        __syncthreads();
        for (int o = 128; o > 0; o >>= 1) {
            if (t < o) sm[t] += sm[t + o];
            __syncthreads();
        }
        outp[q] = sm[0];
        __syncthreads();
    }
    if (t == 0) {
        el[n * 2] = outp[0];
        er[n * 2] = outp[1];
        el[n * 2 + 1] = outp[2];
        er[n * 2 + 1] = outp[3];
    }
}

// ================= fused GAT per-dst =================
__global__ __launch_bounds__(128)
void gat_fused(const int* __restrict__ src, const int* __restrict__ rowptr,
               const int* __restrict__ eidx, const float* __restrict__ el,
               const float* __restrict__ er, const float* __restrict__ feat,
               const int* __restrict__ gid, const float* __restrict__ gat_bias,
               float* __restrict__ hg) {
    int d = blockIdx.x;
    int t = threadIdx.x;
    int beg = rowptr[d], end = rowptr[d + 1];
    float er0 = er[2 * d], er1 = er[2 * d + 1];

    __shared__ float red[128];
    float m0 = -1e30f, m1 = -1e30f;
    for (int j = beg + t; j < end; j += 128) {
        int s = src[eidx[j]];
        float v0 = el[2 * s] + er0;      v0 = v0 > 0.f ? v0 : 0.2f * v0;
        float v1 = el[2 * s + 1] + er1;  v1 = v1 > 0.f ? v1 : 0.2f * v1;
        m0 = fmaxf(m0, v0);
        m1 = fmaxf(m1, v1);
    }
    red[t] = m0; __syncthreads();
    for (int o = 64; o > 0; o >>= 1) { if (t < o) red[t] = fmaxf(red[t], red[t + o]); __syncthreads(); }
    float M0 = red[0]; __syncthreads();
    red[t] = m1; __syncthreads();
    for (int o = 64; o > 0; o >>= 1) { if (t < o) red[t] = fmaxf(red[t], red[t + o]); __syncthreads(); }
    float M1 = red[0]; __syncthreads();

    float s0 = 0.f, s1 = 0.f;
    for (int j = beg + t; j < end; j += 128) {
        int s = src[eidx[j]];
        float v0 = el[2 * s] + er0;      v0 = v0 > 0.f ? v0 : 0.2f * v0;
        float v1 = el[2 * s + 1] + er1;  v1 = v1 > 0.f ? v1 : 0.2f * v1;
        s0 += expf(v0 - M0);
        s1 += expf(v1 - M1);
    }
    red[t] = s0; __syncthreads();
    for (int o = 64; o > 0; o >>= 1) { if (t < o) red[t] += red[t + o]; __syncthreads(); }
    float D0 = red[0]; __syncthreads();
    red[t] = s1; __syncthreads();
    for (int o = 64; o > 0; o >>= 1) { if (t < o) red[t] += red[t + o]; __syncthreads(); }
    float D1 = red[0]; __syncthreads();
    float inv0 = (D0 > 0.f) ? 1.f / D0 : 0.f;
    float inv1 = (D1 > 0.f) ? 1.f / D1 : 0.f;

    __shared__ float sal0[128], sal1[128];
    __shared__ int ssrc[128];
    int c = t * 4;
    bool head0 = c < H2C;
    float4 acc = make_float4(0.f, 0.f, 0.f, 0.f);
    for (int base = beg; base < end; base += 128) {
        int jj = base + t;
        if (jj < end) {
            int s = src[eidx[jj]];
            float v0 = el[2 * s] + er0;      v0 = v0 > 0.f ? v0 : 0.2f * v0;
            float v1 = el[2 * s + 1] + er1;  v1 = v1 > 0.f ? v1 : 0.2f * v1;
            sal0[t] = expf(v0 - M0) * inv0;
            sal1[t] = expf(v1 - M1) * inv1;
            ssrc[t] = s;
        }
        __syncthreads();
        int m = min(128, end - base);
        for (int q = 0; q < m; q++) {
            float al = head0 ? sal0[q] : sal1[q];
            float4 v = *(const float4*)(feat + (size_t)ssrc[q] * 512 + c);
            acc.x += al * v.x; acc.y += al * v.y;
            acc.z += al * v.z; acc.w += al * v.w;
        }
        __syncthreads();
    }
    float4 b = *(const float4*)(gat_bias + c);
    int g = gid[d];
    atomicAdd(&hg[(size_t)g * 512 + c + 0], fmaxf(acc.x + b.x, 0.f));
    atomicAdd(&hg[(size_t)g * 512 + c + 1], fmaxf(acc.y + b.y, 0.f));
    atomicAdd(&hg[(size_t)g * 512 + c + 2], fmaxf(acc.z + b.z, 0.f));
    atomicAdd(&hg[(size_t)g * 512 + c + 3], fmaxf(acc.w + b.w, 0.f));
}

__global__ void gcnt_kernel(const int* __restrict__ gid, float* __restrict__ gcnt) {
    int n = blockIdx.x * blockDim.x + threadIdx.x;
    if (n < NN) atomicAdd(&gcnt[gid[n]], 1.f);
}

__global__ void final_kernel(const float* __restrict__ hg, const float* __restrict__ gcnt,
                             const float* __restrict__ cw, const float* __restrict__ cb,
                             float* __restrict__ out) {
    int g = blockIdx.x >> 1, hd = blockIdx.x & 1;
    int t = threadIdx.x;  // 256
    __shared__ float row[H2C];
    float inv = 1.f / fmaxf(gcnt[g], 1.f);
    row[t] = hg[(size_t)g * H1 + hd * H2C + t] * inv;
    __syncthreads();
    if (t < CC) {
        float s = cb[t];
        for (int j = 0; j < H2C; j++) s += row[j] * cw[t * H2C + j];
        out[((size_t)g * HEADS + hd) * CC + t] = s;
    }
}

// ================= launch =================
extern "C" void kernel_launch(void* const* d_in, const int* in_sizes, int n_in,
                              void* d_out, int out_size) {
    const float* in_feat  = (const float*)d_in[0];
    const int*   src      = (const int*)d_in[1];
    const int*   dst      = (const int*)d_in[2];
    const int*   etype    = (const int*)d_in[3];
    const int*   gid      = (const int*)d_in[4];
    const float* Wmsg     = (const float*)d_in[5];
    const float* bmsg     = (const float*)d_in[6];
    const float* w_ih     = (const float*)d_in[7];
    const float* w_hh     = (const float*)d_in[8];
    const float* b_ih     = (const float*)d_in[9];
    const float* b_hh     = (const float*)d_in[10];
    const float* fc_w     = (const float*)d_in[11];
    const float* attn_l   = (const float*)d_in[12];
    const float* attn_r   = (const float*)d_in[13];
    const float* gat_bias = (const float*)d_in[14];
    const float* cw       = (const float*)d_in[15];
    const float* cb       = (const float*)d_in[16];
    float* out = (float*)d_out;

    cudaFuncSetAttribute(gemm_h, cudaFuncAttributeMaxDynamicSharedMemorySize, SMEM_BYTES);

    float* base = nullptr;
    cudaGetSymbolAddress((void**)&base, g_buf);

    float*  hF    = base + OFF_HF;
    float*  aF    = base + OFF_AF;
    float*  P     = base + OFF_P;
    float*  Qi    = base + OFF_QI;
    float*  Qh    = base + OFF_QH;
    float*  feat  = base + OFF_FEAT;
    __half* ahHi  = (__half*)(base + OFF_AHH);
    __half* ahLo  = (__half*)(base + OFF_AHL);
    __half* sHi   = (__half*)(base + OFF_SAGH);
    __half* sLo   = (__half*)(base + OFF_SAGL);
    __half* WmH   = (__half*)(base + OFF_WMH);
    __half* B1H   = (__half*)(base + OFF_B1H);
    __half* WiH   = (__half*)(base + OFF_WIH);
    __half* WhH   = (__half*)(base + OFF_WHH);
    __half* FcH   = (__half*)(base + OFF_FCH);
    float*  el    = base + OFF_EL;
    float*  er    = base + OFF_ER;
    float*  hg    = base + OFF_HG;
    float*  gcnt  = base + OFF_GCNT;
    int*    deg   = (int*)(base + OFF_DEG);
    int*    rptr  = (int*)(base + OFF_RPTR);
    int*    cur   = (int*)(base + OFF_CUR);
    int*    eidx  = (int*)(base + OFF_EIDX);
    int*    cnt   = (int*)(base + OFF_CNT);

    conv_h<<<512, 256>>>(Wmsg, WmH, (size_t)2048 * 512 / 2);
    prep_b1_h<<<512, 256>>>(w_ih, w_hh, B1H);
    prep_t512_h<<<256, 256>>>(w_ih, 1024, WiH);
    prep_t512_h<<<256, 256>>>(w_hh, 1024, WhH);
    prep_t512_h<<<256, 256>>>(fc_w, 0, FcH);
    pad_kernel<<<4096, 256>>>(in_feat, hF, ahHi, ahLo);

    zero_f4<<<32, 256>>>((float4*)deg, NN / 4);
    csr_count<<<(EE + 255) / 256, 256>>>(dst, deg);
    csr_scan<<<1, 1024>>>(deg, rptr, cur);
    csr_scatter<<<(EE + 255) / 256, 256>>>(dst, cur, eidx);

    auto gemm = [](const __half* Ah, const __half* Al, int lda,
                   const __half* Bh, int ldb,
                   float* Cf, int ldc, __half* Oh, __half* Ol, int ldo,
                   int M, int K, int N, int mode) {
        dim3 g((M + 127) / 128, N / 128);
        gemm_h<<<g, 256, SMEM_BYTES>>>(Ah, Al, lda, Bh, ldb, Cf, ldc, Oh, Ol, ldo, M, K, mode);
    };

    for (int step = 0; step < NSTEPS; step++) {
        agg_gather<<<NN, 128>>>(hF, src, etype, rptr, eidx, sHi, sLo, cnt);
        bias_a_kernel<<<NN, 256>>>(bmsg, cnt, aF);
        gemm(sHi, sLo, 2048, WmH, 512, aF, 512, ahHi, ahLo, 1024, NN, 2048, 512, 1);
        gemm(ahHi, ahLo, 1024, B1H, 1024, P, 1024, nullptr, nullptr, 0, NN, 1024, 1024, 0);
        gemm(ahHi, ahLo, 1024, WiH, 512, Qi, 512, nullptr, nullptr, 0, NN, 512, 512, 0);
        gemm(ahHi + 512, ahLo + 512, 1024, WhH, 512, Qh, 512, nullptr, nullptr, 0, NN, 512, 512, 0);
        gru_kernel<<<4096, 256>>>(P, Qi, Qh, b_ih, b_hh, hF, ahHi, ahLo);
    }

    norm_sig_kernel<<<NN, 128>>>(hF, ahHi, ahLo);
    gemm(ahHi + 512, ahLo + 512, 1024, FcH, 512, feat, 512, nullptr, nullptr, 0, NN, 512, 512, 0);
    elr_kernel<<<NN, 256>>>(feat, attn_l, attn_r, el, er);

    zero_f4<<<32, 256>>>((float4*)hg, ((size_t)GG * 512 + GG) / 4);
    gat_fused<<<NN, 128>>>(src, rptr, eidx, el, er, feat, gid, gat_bias, hg);
    gcnt_kernel<<<(NN + 255) / 256, 256>>>(gid, gcnt);
    final_kernel<<<GG * HEADS, 256>>>(hg, gcnt, cw, cb, out);
}

// round 9
// speedup vs baseline: 6.4687x; 1.4163x over previous
#include <cuda_runtime.h>
#include <cuda_fp16.h>
#include <math.h>
#include <stdint.h>

#define NN 20000
#define EE 320000
#define GG 64
#define INF_ 256
#define H1 512
#define H2C 256
#define HEADS 2
#define CC 16
#define NSTEPS 4
#define KT 4

// ================= scratch layout (float units) =================
constexpr size_t OFF_HF    = 0;                               // NN x 512 f32 (h)
constexpr size_t OFF_AF    = OFF_HF + (size_t)NN * 512;       // NN x 512 f32 (a bias base)
constexpr size_t OFF_P     = OFF_AF + (size_t)NN * 512;       // NN x 1024 f32
constexpr size_t OFF_QI    = OFF_P + (size_t)NN * 1024;       // NN x 512
constexpr size_t OFF_QH    = OFF_QI + (size_t)NN * 512;
constexpr size_t OFF_FEAT  = OFF_QH + (size_t)NN * 512;       // NN x 512
constexpr size_t OFF_AHH   = OFF_FEAT + (size_t)NN * 512;     // NN x 1024 halves ([a|h] fp16)
constexpr size_t OFF_SAGH  = OFF_AHH + (size_t)NN * 512;      // NN x 2048 halves
constexpr size_t OFF_WMH   = OFF_SAGH + (size_t)NN * 1024;    // 2048x512 halves
constexpr size_t OFF_B1H   = OFF_WMH + 524288;                // 1024x1024 halves
constexpr size_t OFF_WIH   = OFF_B1H + 524288;                // 512x512 halves
constexpr size_t OFF_WHH   = OFF_WIH + 131072;
constexpr size_t OFF_FCH   = OFF_WHH + 131072;
constexpr size_t OFF_EL    = OFF_FCH + 131072;                // NN x 2
constexpr size_t OFF_ER    = OFF_EL + (size_t)NN * 2;
constexpr size_t OFF_HG    = OFF_ER + (size_t)NN * 2;         // GG x 512
constexpr size_t OFF_GCNT  = OFF_HG + (size_t)GG * 512;       // GG
// int regions
constexpr size_t OFF_DEG   = OFF_GCNT + GG;                   // NN ints
constexpr size_t OFF_RPTR  = OFF_DEG + NN;                    // NN+4 ints
constexpr size_t OFF_CUR   = OFF_RPTR + NN + 4;               // NN ints
constexpr size_t OFF_EIDX  = OFF_CUR + NN;                    // EE ints
constexpr size_t OFF_CNT   = OFF_EIDX + EE;                   // NN*4 ints
constexpr size_t TOTAL_F   = OFF_CNT + (size_t)NN * 4 + 16;

__device__ __align__(16) float g_buf[TOTAL_F];

// ================= PTX helpers =================
__device__ __forceinline__ uint32_t smem_to_u32(const void* p) {
    uint32_t a;
    asm("{ .reg .u64 t; cvta.to.shared.u64 t, %1; cvt.u32.u64 %0, t; }" : "=r"(a) : "l"(p));
    return a;
}
__device__ __forceinline__ void ldsm_x4(uint32_t addr, uint32_t* r) {
    asm volatile("ldmatrix.sync.aligned.m8n8.x4.shared.b16 {%0,%1,%2,%3}, [%4];"
                 : "=r"(r[0]), "=r"(r[1]), "=r"(r[2]), "=r"(r[3]) : "r"(addr));
}
__device__ __forceinline__ void ldsm_x4_t(uint32_t addr, uint32_t* r) {
    asm volatile("ldmatrix.sync.aligned.m8n8.x4.trans.shared.b16 {%0,%1,%2,%3}, [%4];"
                 : "=r"(r[0]), "=r"(r[1]), "=r"(r[2]), "=r"(r[3]) : "r"(addr));
}
__device__ __forceinline__ void mma_f16(float* c, const uint32_t* a, const uint32_t* b) {
    asm volatile(
        "mma.sync.aligned.m16n8k16.row.col.f32.f16.f16.f32 "
        "{%0,%1,%2,%3},{%4,%5,%6,%7},{%8,%9},{%0,%1,%2,%3};"
        : "+f"(c[0]), "+f"(c[1]), "+f"(c[2]), "+f"(c[3])
        : "r"(a[0]), "r"(a[1]), "r"(a[2]), "r"(a[3]), "r"(b[0]), "r"(b[1]));
}
__device__ __forceinline__ __half2 h2rn(float x0, float x1) {
    return __halves2half2(__float2half_rn(x0), __float2half_rn(x1));
}
__device__ __forceinline__ void cpa16(uint32_t d, const void* g, int sz) {
    asm volatile("cp.async.cg.shared.global [%0], [%1], 16, %2;"
                 :: "r"(d), "l"(g), "r"(sz) : "memory");
}
__device__ __forceinline__ void cpa_commit() {
    asm volatile("cp.async.commit_group;" ::: "memory");
}
template <int N>
__device__ __forceinline__ void cpa_wait() {
    asm volatile("cp.async.wait_group %0;" :: "n"(N) : "memory");
}

// ================= SMEM layout for gemm_h (half-element offsets) =================
// A: 2 x 5120 (128 rows x 40 pitch), B: 2 x 4352 (32 x 136)
#define AS_PITCH 40
#define BS_PITCH 136
#define SM_AH(b) ((b) * 5120)
#define SM_BH(b) (10240 + (b) * 4352)
#define SMEM_HALFS 18944
#define SMEM_BYTES (SMEM_HALFS * 2)

// ================= pure-fp16 HMMA GEMM (cp.async staged) =================
// acc = A @ B; A [M,K] fp16 row-major stride lda, B [K,N] fp16 stride ldb.
// mode 0: Cf[r][c] = acc (fp32 stride ldc)
// mode 1: v = Cf_in + acc; Oh[r][c] = fp16(v) (stride ldo)
__global__ __launch_bounds__(256, 2)
void gemm_h(const __half* __restrict__ A, int lda,
            const __half* __restrict__ B, int ldb,
            float* __restrict__ Cf, int ldc,
            __half* __restrict__ Oh, int ldo,
            int M, int K, int mode) {
    extern __shared__ __half smh[];
    const uint32_t sbase = smem_to_u32(smh);

    const int tid = threadIdx.x;
    const int lane = tid & 31;
    const int wid = tid >> 5;
    const int wm = wid >> 2;
    const int wn = wid & 3;
    const int blockM = blockIdx.x * 128;
    const int n0 = blockIdx.y * 128;

    const int ar = tid >> 1, ac = (tid & 1) * 16;
    const int bk = tid >> 3, bn = (tid & 7) * 16;
    const bool aval = (blockM + ar) < M;
    const int asz = aval ? 16 : 0;
    const __half* Ap = A + (size_t)(aval ? blockM + ar : 0) * lda + ac;
    const __half* Bp = B + (size_t)bk * ldb + n0 + bn;

    const uint32_t dA = sbase + 2 * (uint32_t)(ar * AS_PITCH + ac);
    const uint32_t dB = sbase + 2 * (uint32_t)(10240 + bk * BS_PITCH + bn);

    const int nC = K >> 5;

    float acc[4][4][4];
#pragma unroll
    for (int mi = 0; mi < 4; mi++)
#pragma unroll
        for (int ni = 0; ni < 4; ni++)
#pragma unroll
            for (int q = 0; q < 4; q++) acc[mi][ni][q] = 0.f;

    auto issue = [&](int c) {
        const int boffA = (c & 1) * 2 * 5120;
        const int boffB = (c & 1) * 2 * 4352;
        const __half* a = Ap + c * 32;
        const __half* b = Bp + (size_t)c * 32 * ldb;
        cpa16(dA + boffA, a, asz);
        cpa16(dA + boffA + 16, a + 8, asz);
        cpa16(dB + boffB, b, 16);
        cpa16(dB + boffB + 16, b + 8, 16);
        cpa_commit();
    };

    issue(0);

    const int lrow = lane & 15;
    const int lhalf = (lane >> 4) * 8;

    for (int c = 0; c < nC; c++) {
        const int b = c & 1;
        if (c + 1 < nC) {
            issue(c + 1);
            cpa_wait<1>();
        } else {
            cpa_wait<0>();
        }
        __syncthreads();

#pragma unroll
        for (int s = 0; s < 2; s++) {
            uint32_t bf[4][2];
#pragma unroll
            for (int np = 0; np < 2; np++) {
                uint32_t off = (uint32_t)((s * 16 + lrow) * BS_PITCH + wn * 32 + np * 16 + lhalf);
                uint32_t t[4];
                ldsm_x4_t(sbase + 2 * (SM_BH(b) + off), t);
                bf[2 * np][0] = t[0]; bf[2 * np][1] = t[1];
                bf[2 * np + 1][0] = t[2]; bf[2 * np + 1][1] = t[3];
            }
#pragma unroll
            for (int mi = 0; mi < 4; mi++) {
                uint32_t off = (uint32_t)((wm * 64 + mi * 16 + lrow) * AS_PITCH + s * 16 + lhalf);
                uint32_t af[4];
                ldsm_x4(sbase + 2 * (SM_AH(b) + off), af);
#pragma unroll
                for (int ni = 0; ni < 4; ni++) mma_f16(acc[mi][ni], af, bf[ni]);
            }
        }
        __syncthreads();
    }

    const int row0 = blockM + wm * 64;
    const int col0 = n0 + wn * 32;
#pragma unroll
    for (int mi = 0; mi < 4; mi++) {
        int r0 = row0 + mi * 16 + (lane >> 2);
        int r1 = r0 + 8;
#pragma unroll
        for (int ni = 0; ni < 4; ni++) {
            int cc = col0 + ni * 8 + (lane & 3) * 2;
#pragma unroll
            for (int h = 0; h < 2; h++) {
                int r = h ? r1 : r0;
                if (r >= M) continue;
                float v0 = acc[mi][ni][2 * h], v1 = acc[mi][ni][2 * h + 1];
                if (mode == 0) {
                    *(float2*)(Cf + (size_t)r * ldc + cc) = make_float2(v0, v1);
                } else {
                    float2 ci = *(const float2*)(Cf + (size_t)r * ldc + cc);
                    *(__half2*)(Oh + (size_t)r * ldo + cc) = h2rn(v0 + ci.x, v1 + ci.y);
                }
            }
        }
    }
}

// ================= misc =================
__device__ __forceinline__ float sigm(float x) { return 1.f / (1.f + expf(-x)); }

__global__ void zero_f4(float4* p, size_t n4) {
    size_t i = (size_t)blockIdx.x * blockDim.x + threadIdx.x;
    size_t st = (size_t)gridDim.x * blockDim.x;
    for (; i < n4; i += st) p[i] = make_float4(0.f, 0.f, 0.f, 0.f);
}

// fp32 -> fp16 (for weights)
__global__ void conv_h(const float* __restrict__ in, __half* __restrict__ hi, size_t n2) {
    size_t i = (size_t)blockIdx.x * blockDim.x + threadIdx.x;
    size_t st = (size_t)gridDim.x * blockDim.x;
    for (; i < n2; i += st) {
        float2 v = *(const float2*)(in + 2 * i);
        *(__half2*)(hi + 2 * i) = h2rn(v.x, v.y);
    }
}

// B1[k][n] fp16: k<512 -> w_ih[n][k], else w_hh[n][k-512]; n in 0..1023
__global__ void prep_b1_h(const float* __restrict__ w_ih, const float* __restrict__ w_hh,
                          __half* __restrict__ hi) {
    int i = blockIdx.x * blockDim.x + threadIdx.x;
    int st = gridDim.x * blockDim.x;
    for (; i < 1024 * 512; i += st) {
        int k = i >> 9;
        int n = (i & 511) * 2;
        float v0 = (k < 512) ? w_ih[(size_t)n * 512 + k] : w_hh[(size_t)n * 512 + k - 512];
        float v1 = (k < 512) ? w_ih[(size_t)(n + 1) * 512 + k] : w_hh[(size_t)(n + 1) * 512 + k - 512];
        *(__half2*)(hi + (size_t)k * 1024 + n) = h2rn(v0, v1);
    }
}

// T[k][n] fp16 = W[(rowoff+n)*512 + k]
__global__ void prep_t512_h(const float* __restrict__ W, int rowoff, __half* __restrict__ hi) {
    int i = blockIdx.x * blockDim.x + threadIdx.x;
    int st = gridDim.x * blockDim.x;
    for (; i < 512 * 256; i += st) {
        int k = i >> 8;
        int n = (i & 255) * 2;
        float v0 = W[(size_t)(rowoff + n) * 512 + k];
        float v1 = W[(size_t)(rowoff + n + 1) * 512 + k];
        *(__half2*)(hi + (size_t)k * 512 + n) = h2rn(v0, v1);
    }
}

// pad input -> hF fp32 + h fp16 (ah cols 512..1023)
__global__ void pad_kernel(const float* __restrict__ x, float* __restrict__ hF,
                           __half* __restrict__ ahH) {
    int i = blockIdx.x * blockDim.x + threadIdx.x;
    int st = gridDim.x * blockDim.x;
    int tot = NN * 256;
    for (; i < tot; i += st) {
        int n = i >> 8;
        int c = (i & 255) * 2;
        float v0 = (c < INF_) ? x[(size_t)n * INF_ + c] : 0.f;
        float v1 = (c + 1 < INF_) ? x[(size_t)n * INF_ + c + 1] : 0.f;
        *(float2*)(hF + (size_t)n * 512 + c) = make_float2(v0, v1);
        *(__half2*)(ahH + (size_t)n * 1024 + 512 + c) = h2rn(v0, v1);
    }
}

// ================= CSR build =================
__global__ void csr_count(const int* __restrict__ dst, int* __restrict__ deg) {
    int e = blockIdx.x * blockDim.x + threadIdx.x;
    if (e < EE) atomicAdd(&deg[dst[e]], 1);
}

__global__ void csr_scan(const int* __restrict__ deg, int* __restrict__ rowptr,
                         int* __restrict__ cursor) {
    __shared__ int part[1024];
    int t = threadIdx.x;
    int b = t * 20;
    int loc[20];
    int s = 0;
#pragma unroll
    for (int i = 0; i < 20; i++) {
        int n = b + i;
        loc[i] = (n < NN) ? deg[n] : 0;
        s += loc[i];
    }
    part[t] = s;
    __syncthreads();
    for (int off = 1; off < 1024; off <<= 1) {
        int v = (t >= off) ? part[t - off] : 0;
        __syncthreads();
        part[t] += v;
        __syncthreads();
    }
    int run = part[t] - s;
#pragma unroll
    for (int i = 0; i < 20; i++) {
        int n = b + i;
        if (n < NN) {
            rowptr[n] = run;
            cursor[n] = run;
            run += loc[i];
        }
    }
    if (t == 0) rowptr[NN] = EE;
}

__global__ void csr_scatter(const int* __restrict__ dst, int* __restrict__ cursor,
                            int* __restrict__ eidx) {
    int e = blockIdx.x * blockDim.x + threadIdx.x;
    if (e < EE) {
        int pos = atomicAdd(&cursor[dst[e]], 1);
        eidx[pos] = e;
    }
}

// ================= per-dst aggregate gather (fp16 h rows) =================
__global__ __launch_bounds__(128)
void agg_gather(const __half* __restrict__ ahH, const int* __restrict__ src,
                const int* __restrict__ et, const int* __restrict__ rowptr,
                const int* __restrict__ eidx,
                __half* __restrict__ sH, int* __restrict__ cnt) {
    int d = blockIdx.x;
    int t = threadIdx.x;
    int beg = rowptr[d], end = rowptr[d + 1];
    int c = t * 4;
    float4 acc[KT];
#pragma unroll
    for (int k = 0; k < KT; k++) acc[k] = make_float4(0.f, 0.f, 0.f, 0.f);
    int cn[KT] = {0, 0, 0, 0};

    __shared__ int ssrc[128];
    __shared__ int sket[128];
    for (int base = beg; base < end; base += 128) {
        int jj = base + t;
        if (jj < end) {
            int e = eidx[jj];
            ssrc[t] = src[e];
            sket[t] = et[e];
        }
        __syncthreads();
        int m = min(128, end - base);
        for (int q = 0; q < m; q++) {
            int s = ssrc[q];
            int k = sket[q];
            uint2 u = *(const uint2*)(ahH + (size_t)s * 1024 + 512 + c);
            float2 f0 = __half22float2(*(__half2*)&u.x);
            float2 f1 = __half22float2(*(__half2*)&u.y);
#pragma unroll
            for (int kk = 0; kk < KT; kk++) {
                if (k == kk) {
                    acc[kk].x += f0.x; acc[kk].y += f0.y;
                    acc[kk].z += f1.x; acc[kk].w += f1.y;
                    cn[kk]++;
                }
            }
        }
        __syncthreads();
    }
#pragma unroll
    for (int k = 0; k < KT; k++) {
        size_t o = (size_t)d * 2048 + k * 512 + c;
        *(__half2*)(sH + o) = h2rn(acc[k].x, acc[k].y);
        *(__half2*)(sH + o + 2) = h2rn(acc[k].z, acc[k].w);
    }
    if (t == 0) {
#pragma unroll
        for (int k = 0; k < KT; k++) cnt[d * KT + k] = cn[k];
    }
}

// aF[n][c] = sum_k cnt[n][k]*bmsg[k][c]
__global__ void bias_a_kernel(const float* __restrict__ bmsg, const int* __restrict__ cnt,
                              float* __restrict__ aF) {
    int n = blockIdx.x;
    __shared__ float bm[KT * H1];
    for (int i = threadIdx.x; i < KT * H1; i += blockDim.x) bm[i] = bmsg[i];
    __shared__ int cn[KT];
    if (threadIdx.x < KT) cn[threadIdx.x] = cnt[n * KT + threadIdx.x];
    __syncthreads();
    float c0 = (float)cn[0], c1 = (float)cn[1], c2 = (float)cn[2], c3 = (float)cn[3];
    for (int c = threadIdx.x; c < H1; c += blockDim.x)
        aF[(size_t)n * H1 + c] =
            c0 * bm[c] + c1 * bm[H1 + c] + c2 * bm[2 * H1 + c] + c3 * bm[3 * H1 + c];
}

// GRU pointwise: writes hF fp32 + h fp16
__global__ void gru_kernel(const float* __restrict__ P, const float* __restrict__ Qi,
                           const float* __restrict__ Qh,
                           const float* __restrict__ b_ih, const float* __restrict__ b_hh,
                           float* __restrict__ hF, __half* __restrict__ ahH) {
    int i = blockIdx.x * blockDim.x + threadIdx.x;
    int st = gridDim.x * blockDim.x;
    int tot = NN * 256;
    for (; i < tot; i += st) {
        int n = i >> 8;
        int c = (i & 255) * 2;
        float hv[2];
#pragma unroll
        for (int u = 0; u < 2; u++) {
            int cc = c + u;
            float r = sigm(P[(size_t)n * 1024 + cc] + b_ih[cc] + b_hh[cc]);
            float z = sigm(P[(size_t)n * 1024 + 512 + cc] + b_ih[512 + cc] + b_hh[512 + cc]);
            float nn = tanhf(Qi[(size_t)n * 512 + cc] + b_ih[1024 + cc] +
                             r * (Qh[(size_t)n * 512 + cc] + b_hh[1024 + cc]));
            float ho = hF[(size_t)n * 512 + cc];
            hv[u] = (1.f - z) * nn + z * ho;
        }
        *(float2*)(hF + (size_t)n * 512 + c) = make_float2(hv[0], hv[1]);
        *(__half2*)(ahH + (size_t)n * 1024 + 512 + c) = h2rn(hv[0], hv[1]);
    }
}

// L2-normalize + sigmoid; writes h fp16 only
__global__ void norm_sig_kernel(const float* __restrict__ hF, __half* __restrict__ ahH) {
    int n = blockIdx.x;
    int t = threadIdx.x;  // 128
    const float* row = hF + (size_t)n * 512;
    float4 v = *(const float4*)(row + t * 4);
    float s = v.x * v.x + v.y * v.y + v.z * v.z + v.w * v.w;
    __shared__ float sm[128];
    sm[t] = s;
    __syncthreads();
    for (int o = 64; o > 0; o >>= 1) {
        if (t < o) sm[t] += sm[t + o];
        __syncthreads();
    }
    float inv = 1.f / fmaxf(sqrtf(sm[0]), 1e-12f);
    size_t off = (size_t)n * 1024 + 512 + t * 4;
    *(__half2*)(ahH + off) = h2rn(sigm(v.x * inv), sigm(v.y * inv));
    *(__half2*)(ahH + off + 2) = h2rn(sigm(v.z * inv), sigm(v.w * inv));
}

__global__ void elr_kernel(const float* __restrict__ feat, const float* __restrict__ attn_l,
                           const float* __restrict__ attn_r,
                           float* __restrict__ el, float* __restrict__ er) {
    int n = blockIdx.x;
    int t = threadIdx.x;  // 256
    float f0 = feat[(size_t)n * H1 + t];
    float f1 = feat[(size_t)n * H1 + H2C + t];
    float vals[4] = {f0 * attn_l[t], f0 * attn_r[t], f1 * attn_l[H2C + t], f1 * attn_r[H2C + t]};
    float outp[4];
    __shared__ float sm[256];
#pragma unroll
    for (int q = 0; q < 4; q++) {
        sm[t] = vals[q];
        __syncthreads();
        for (int o = 128; o > 0; o >>= 1) {
            if (t < o) sm[t] += sm[t + o];
            __syncthreads();
        }
        outp[q] = sm[0];
        __syncthreads();
    }
    if (t == 0) {
        el[n * 2] = outp[0];
        er[n * 2] = outp[1];
        el[n * 2 + 1] = outp[2];
        er[n * 2 + 1] = outp[3];
    }
}

// ================= fused GAT per-dst =================
__global__ __launch_bounds__(128)
void gat_fused(const int* __restrict__ src, const int* __restrict__ rowptr,
               const int* __restrict__ eidx, const float* __restrict__ el,
               const float* __restrict__ er, const float* __restrict__ feat,
               const int* __restrict__ gid, const float* __restrict__ gat_bias,
               float* __restrict__ hg) {
    int d = blockIdx.x;
    int t = threadIdx.x;
    int beg = rowptr[d], end = rowptr[d + 1];
    float er0 = er[2 * d], er1 = er[2 * d + 1];

    __shared__ float red[128];
    float m0 = -1e30f, m1 = -1e30f;
    for (int j = beg + t; j < end; j += 128) {
        int s = src[eidx[j]];
        float v0 = el[2 * s] + er0;      v0 = v0 > 0.f ? v0 : 0.2f * v0;
        float v1 = el[2 * s + 1] + er1;  v1 = v1 > 0.f ? v1 : 0.2f * v1;
        m0 = fmaxf(m0, v0);
        m1 = fmaxf(m1, v1);
    }
    red[t] = m0; __syncthreads();
    for (int o = 64; o > 0; o >>= 1) { if (t < o) red[t] = fmaxf(red[t], red[t + o]); __syncthreads(); }
    float M0 = red[0]; __syncthreads();
    red[t] = m1; __syncthreads();
    for (int o = 64; o > 0; o >>= 1) { if (t < o) red[t] = fmaxf(red[t], red[t + o]); __syncthreads(); }
    float M1 = red[0]; __syncthreads();

    float s0 = 0.f, s1 = 0.f;
    for (int j = beg + t; j < end; j += 128) {
        int s = src[eidx[j]];
        float v0 = el[2 * s] + er0;      v0 = v0 > 0.f ? v0 : 0.2f * v0;
        float v1 = el[2 * s + 1] + er1;  v1 = v1 > 0.f ? v1 : 0.2f * v1;
        s0 += expf(v0 - M0);
        s1 += expf(v1 - M1);
    }
    red[t] = s0; __syncthreads();
    for (int o = 64; o > 0; o >>= 1) { if (t < o) red[t] += red[t + o]; __syncthreads(); }
    float D0 = red[0]; __syncthreads();
    red[t] = s1; __syncthreads();
    for (int o = 64; o > 0; o >>= 1) { if (t < o) red[t] += red[t + o]; __syncthreads(); }
    float D1 = red[0]; __syncthreads();
    float inv0 = (D0 > 0.f) ? 1.f / D0 : 0.f;
    float inv1 = (D1 > 0.f) ? 1.f / D1 : 0.f;

    __shared__ float sal0[128], sal1[128];
    __shared__ int ssrc[128];
    int c = t * 4;
    bool head0 = c < H2C;
    float4 acc = make_float4(0.f, 0.f, 0.f, 0.f);
    for (int base = beg; base < end; base += 128) {
        int jj = base + t;
        if (jj < end) {
            int s = src[eidx[jj]];
            float v0 = el[2 * s] + er0;      v0 = v0 > 0.f ? v0 : 0.2f * v0;
            float v1 = el[2 * s + 1] + er1;  v1 = v1 > 0.f ? v1 : 0.2f * v1;
            sal0[t] = expf(v0 - M0) * inv0;
            sal1[t] = expf(v1 - M1) * inv1;
            ssrc[t] = s;
        }
        __syncthreads();
        int m = min(128, end - base);
        for (int q = 0; q < m; q++) {
            float al = head0 ? sal0[q] : sal1[q];
            float4 v = *(const float4*)(feat + (size_t)ssrc[q] * 512 + c);
            acc.x += al * v.x; acc.y += al * v.y;
            acc.z += al * v.z; acc.w += al * v.w;
        }
        __syncthreads();
    }
    float4 b = *(const float4*)(gat_bias + c);
    int g = gid[d];
    atomicAdd(&hg[(size_t)g * 512 + c + 0], fmaxf(acc.x + b.x, 0.f));
    atomicAdd(&hg[(size_t)g * 512 + c + 1], fmaxf(acc.y + b.y, 0.f));
    atomicAdd(&hg[(size_t)g * 512 + c + 2], fmaxf(acc.z + b.z, 0.f));
    atomicAdd(&hg[(size_t)g * 512 + c + 3], fmaxf(acc.w + b.w, 0.f));
}

__global__ void gcnt_kernel(const int* __restrict__ gid, float* __restrict__ gcnt) {
    int n = blockIdx.x * blockDim.x + threadIdx.x;
    if (n < NN) atomicAdd(&gcnt[gid[n]], 1.f);
}

__global__ void final_kernel(const float* __restrict__ hg, const float* __restrict__ gcnt,
                             const float* __restrict__ cw, const float* __restrict__ cb,
                             float* __restrict__ out) {
    int g = blockIdx.x >> 1, hd = blockIdx.x & 1;
    int t = threadIdx.x;  // 256
    __shared__ float row[H2C];
    float inv = 1.f / fmaxf(gcnt[g], 1.f);
    row[t] = hg[(size_t)g * H1 + hd * H2C + t] * inv;
    __syncthreads();
    if (t < CC) {
        float s = cb[t];
        for (int j = 0; j < H2C; j++) s += row[j] * cw[t * H2C + j];
        out[((size_t)g * HEADS + hd) * CC + t] = s;
    }
}

// ================= launch =================
extern "C" void kernel_launch(void* const* d_in, const int* in_sizes, int n_in,
                              void* d_out, int out_size) {
    const float* in_feat  = (const float*)d_in[0];
    const int*   src      = (const int*)d_in[1];
    const int*   dst      = (const int*)d_in[2];
    const int*   etype    = (const int*)d_in[3];
    const int*   gid      = (const int*)d_in[4];
    const float* Wmsg     = (const float*)d_in[5];
    const float* bmsg     = (const float*)d_in[6];
    const float* w_ih     = (const float*)d_in[7];
    const float* w_hh     = (const float*)d_in[8];
    const float* b_ih     = (const float*)d_in[9];
    const float* b_hh     = (const float*)d_in[10];
    const float* fc_w     = (const float*)d_in[11];
    const float* attn_l   = (const float*)d_in[12];
    const float* attn_r   = (const float*)d_in[13];
    const float* gat_bias = (const float*)d_in[14];
    const float* cw       = (const float*)d_in[15];
    const float* cb       = (const float*)d_in[16];
    float* out = (float*)d_out;

    cudaFuncSetAttribute(gemm_h, cudaFuncAttributeMaxDynamicSharedMemorySize, SMEM_BYTES);

    float* base = nullptr;
    cudaGetSymbolAddress((void**)&base, g_buf);

    float*  hF    = base + OFF_HF;
    float*  aF    = base + OFF_AF;
    float*  P     = base + OFF_P;
    float*  Qi    = base + OFF_QI;
    float*  Qh    = base + OFF_QH;
    float*  feat  = base + OFF_FEAT;
    __half* ahH   = (__half*)(base + OFF_AHH);
    __half* sH    = (__half*)(base + OFF_SAGH);
    __half* WmH   = (__half*)(base + OFF_WMH);
    __half* B1H   = (__half*)(base + OFF_B1H);
    __half* WiH   = (__half*)(base + OFF_WIH);
    __half* WhH   = (__half*)(base + OFF_WHH);
    __half* FcH   = (__half*)(base + OFF_FCH);
    float*  el    = base + OFF_EL;
    float*  er    = base + OFF_ER;
    float*  hg    = base + OFF_HG;
    float*  gcnt  = base + OFF_GCNT;
    int*    deg   = (int*)(base + OFF_DEG);
    int*    rptr  = (int*)(base + OFF_RPTR);
    int*    cur   = (int*)(base + OFF_CUR);
    int*    eidx  = (int*)(base + OFF_EIDX);
    int*    cnt   = (int*)(base + OFF_CNT);

    conv_h<<<512, 256>>>(Wmsg, WmH, (size_t)2048 * 512 / 2);
    prep_b1_h<<<512, 256>>>(w_ih, w_hh, B1H);
    prep_t512_h<<<256, 256>>>(w_ih, 1024, WiH);
    prep_t512_h<<<256, 256>>>(w_hh, 1024, WhH);
    prep_t512_h<<<256, 256>>>(fc_w, 0, FcH);
    pad_kernel<<<4096, 256>>>(in_feat, hF, ahH);

    zero_f4<<<32, 256>>>((float4*)deg, NN / 4);
    csr_count<<<(EE + 255) / 256, 256>>>(dst, deg);
    csr_scan<<<1, 1024>>>(deg, rptr, cur);
    csr_scatter<<<(EE + 255) / 256, 256>>>(dst, cur, eidx);

    auto gemm = [](const __half* A, int lda, const __half* B, int ldb,
                   float* Cf, int ldc, __half* Oh, int ldo,
                   int M, int K, int N, int mode) {
        dim3 g((M + 127) / 128, N / 128);
        gemm_h<<<g, 256, SMEM_BYTES>>>(A, lda, B, ldb, Cf, ldc, Oh, ldo, M, K, mode);
    };

    for (int step = 0; step < NSTEPS; step++) {
        agg_gather<<<NN, 128>>>(ahH, src, etype, rptr, eidx, sH, cnt);
        bias_a_kernel<<<NN, 256>>>(bmsg, cnt, aF);
        // a = aF + sagg @ Wmsg -> fp16 into ah cols 0..511
        gemm(sH, 2048, WmH, 512, aF, 512, ahH, 1024, NN, 2048, 512, 1);
        // P = [a|h] @ B1
        gemm(ahH, 1024, B1H, 1024, P, 1024, nullptr, 0, NN, 1024, 1024, 0);
        // Qi = a @ WnI^T ; Qh = h @ WnH^T
        gemm(ahH, 1024, WiH, 512, Qi, 512, nullptr, 0, NN, 512, 512, 0);
        gemm(ahH + 512, 1024, WhH, 512, Qh, 512, nullptr, 0, NN, 512, 512, 0);
        gru_kernel<<<4096, 256>>>(P, Qi, Qh, b_ih, b_hh, hF, ahH);
    }

    norm_sig_kernel<<<NN, 128>>>(hF, ahH);
    gemm(ahH + 512, 1024, FcH, 512, feat, 512, nullptr, 0, NN, 512, 512, 0);
    elr_kernel<<<NN, 256>>>(feat, attn_l, attn_r, el, er);

    zero_f4<<<32, 256>>>((float4*)hg, ((size_t)GG * 512 + GG) / 4);
    gat_fused<<<NN, 128>>>(src, rptr, eidx, el, er, feat, gid, gat_bias, hg);
    gcnt_kernel<<<(NN + 255) / 256, 256>>>(gid, gcnt);
    final_kernel<<<GG * HEADS, 256>>>(hg, gcnt, cw, cb, out);
}

// round 10
// speedup vs baseline: 7.2243x; 1.1168x over previous
#include <cuda_runtime.h>
#include <cuda_fp16.h>
#include <math.h>
#include <stdint.h>

#define NN 20000
#define EE 320000
#define GG 64
#define INF_ 256
#define H1 512
#define H2C 256
#define HEADS 2
#define CC 16
#define NSTEPS 4
#define KT 4

// ================= scratch layout (float units) =================
constexpr size_t OFF_HF    = 0;                               // NN x 512 f32 (h)
constexpr size_t OFF_AF    = OFF_HF + (size_t)NN * 512;       // NN x 512 f32 (a bias base)
constexpr size_t OFF_PH    = OFF_AF + (size_t)NN * 512;       // NN x 1024 halves
constexpr size_t OFF_QIH   = OFF_PH + (size_t)NN * 512;       // NN x 512 halves
constexpr size_t OFF_QHH   = OFF_QIH + (size_t)NN * 256;
constexpr size_t OFF_FEATH = OFF_QHH + (size_t)NN * 256;      // NN x 512 halves
constexpr size_t OFF_AHH   = OFF_FEATH + (size_t)NN * 256;    // NN x 1024 halves ([a|h])
constexpr size_t OFF_SAGH  = OFF_AHH + (size_t)NN * 512;      // NN x 2048 halves
constexpr size_t OFF_WMH   = OFF_SAGH + (size_t)NN * 1024;    // 2048x512 halves
constexpr size_t OFF_B1H   = OFF_WMH + 524288;                // 1024x1024 halves
constexpr size_t OFF_WIH   = OFF_B1H + 524288;                // 512x512 halves
constexpr size_t OFF_WHH   = OFF_WIH + 131072;
constexpr size_t OFF_FCH   = OFF_WHH + 131072;
constexpr size_t OFF_EL    = OFF_FCH + 131072;                // NN x 2
constexpr size_t OFF_ER    = OFF_EL + (size_t)NN * 2;
constexpr size_t OFF_HG    = OFF_ER + (size_t)NN * 2;         // GG x 512
constexpr size_t OFF_GCNT  = OFF_HG + (size_t)GG * 512;       // GG
// int regions
constexpr size_t OFF_DEG   = OFF_GCNT + GG;                   // NN ints
constexpr size_t OFF_RPTR  = OFF_DEG + NN;                    // NN+4 ints
constexpr size_t OFF_CUR   = OFF_RPTR + NN + 4;               // NN ints
constexpr size_t OFF_EIDX  = OFF_CUR + NN;                    // EE ints
constexpr size_t TOTAL_F   = OFF_EIDX + EE + 16;

__device__ __align__(16) float g_buf[TOTAL_F];

// ================= PTX helpers =================
__device__ __forceinline__ uint32_t smem_to_u32(const void* p) {
    uint32_t a;
    asm("{ .reg .u64 t; cvta.to.shared.u64 t, %1; cvt.u32.u64 %0, t; }" : "=r"(a) : "l"(p));
    return a;
}
__device__ __forceinline__ void ldsm_x4(uint32_t addr, uint32_t* r) {
    asm volatile("ldmatrix.sync.aligned.m8n8.x4.shared.b16 {%0,%1,%2,%3}, [%4];"
                 : "=r"(r[0]), "=r"(r[1]), "=r"(r[2]), "=r"(r[3]) : "r"(addr));
}
__device__ __forceinline__ void ldsm_x4_t(uint32_t addr, uint32_t* r) {
    asm volatile("ldmatrix.sync.aligned.m8n8.x4.trans.shared.b16 {%0,%1,%2,%3}, [%4];"
                 : "=r"(r[0]), "=r"(r[1]), "=r"(r[2]), "=r"(r[3]) : "r"(addr));
}
__device__ __forceinline__ void mma_f16(float* c, const uint32_t* a, const uint32_t* b) {
    asm volatile(
        "mma.sync.aligned.m16n8k16.row.col.f32.f16.f16.f32 "
        "{%0,%1,%2,%3},{%4,%5,%6,%7},{%8,%9},{%0,%1,%2,%3};"
        : "+f"(c[0]), "+f"(c[1]), "+f"(c[2]), "+f"(c[3])
        : "r"(a[0]), "r"(a[1]), "r"(a[2]), "r"(a[3]), "r"(b[0]), "r"(b[1]));
}
__device__ __forceinline__ __half2 h2rn(float x0, float x1) {
    return __halves2half2(__float2half_rn(x0), __float2half_rn(x1));
}
__device__ __forceinline__ void cpa16(uint32_t d, const void* g, int sz) {
    asm volatile("cp.async.cg.shared.global [%0], [%1], 16, %2;"
                 :: "r"(d), "l"(g), "r"(sz) : "memory");
}
__device__ __forceinline__ void cpa_commit() {
    asm volatile("cp.async.commit_group;" ::: "memory");
}
template <int N>
__device__ __forceinline__ void cpa_wait() {
    asm volatile("cp.async.wait_group %0;" :: "n"(N) : "memory");
}

// ================= SMEM layout for gemm (half-element offsets) =================
#define AS_PITCH 40
#define BS_PITCH 136
#define SM_AH(b) ((b) * 5120)
#define SM_BH(b) (10240 + (b) * 4352)
#define SMEM_HALFS 18944
#define SMEM_BYTES (SMEM_HALFS * 2)

// ================= pure-fp16 HMMA GEMM core =================
// MODE 1: v = Cadd[r][c] + acc; Oh = fp16(v)
// MODE 2: Oh = fp16(acc)
template <int MODE>
__device__ __forceinline__ void gemm_core(
    const __half* __restrict__ A, int lda,
    const __half* __restrict__ B, int ldb,
    const float* __restrict__ Cadd, int ldc,
    __half* __restrict__ Oh, int ldo,
    int M, int K) {
    extern __shared__ __half smh[];
    const uint32_t sbase = smem_to_u32(smh);

    const int tid = threadIdx.x;
    const int lane = tid & 31;
    const int wid = tid >> 5;
    const int wm = wid >> 2;
    const int wn = wid & 3;
    const int blockM = blockIdx.x * 128;
    const int n0 = blockIdx.y * 128;

    const int ar = tid >> 1, ac = (tid & 1) * 16;
    const int bk = tid >> 3, bn = (tid & 7) * 16;
    const bool aval = (blockM + ar) < M;
    const int asz = aval ? 16 : 0;
    const __half* Ap = A + (size_t)(aval ? blockM + ar : 0) * lda + ac;
    const __half* Bp = B + (size_t)bk * ldb + n0 + bn;

    const uint32_t dA = sbase + 2 * (uint32_t)(ar * AS_PITCH + ac);
    const uint32_t dB = sbase + 2 * (uint32_t)(10240 + bk * BS_PITCH + bn);

    const int nC = K >> 5;

    float acc[4][4][4];
#pragma unroll
    for (int mi = 0; mi < 4; mi++)
#pragma unroll
        for (int ni = 0; ni < 4; ni++)
#pragma unroll
            for (int q = 0; q < 4; q++) acc[mi][ni][q] = 0.f;

    auto issue = [&](int c) {
        const int boffA = (c & 1) * 2 * 5120;
        const int boffB = (c & 1) * 2 * 4352;
        const __half* a = Ap + c * 32;
        const __half* b = Bp + (size_t)c * 32 * ldb;
        cpa16(dA + boffA, a, asz);
        cpa16(dA + boffA + 16, a + 8, asz);
        cpa16(dB + boffB, b, 16);
        cpa16(dB + boffB + 16, b + 8, 16);
        cpa_commit();
    };

    issue(0);

    const int lrow = lane & 15;
    const int lhalf = (lane >> 4) * 8;

    for (int c = 0; c < nC; c++) {
        const int b = c & 1;
        if (c + 1 < nC) {
            issue(c + 1);
            cpa_wait<1>();
        } else {
            cpa_wait<0>();
        }
        __syncthreads();

#pragma unroll
        for (int s = 0; s < 2; s++) {
            uint32_t bf[4][2];
#pragma unroll
            for (int np = 0; np < 2; np++) {
                uint32_t off = (uint32_t)((s * 16 + lrow) * BS_PITCH + wn * 32 + np * 16 + lhalf);
                uint32_t t[4];
                ldsm_x4_t(sbase + 2 * (SM_BH(b) + off), t);
                bf[2 * np][0] = t[0]; bf[2 * np][1] = t[1];
                bf[2 * np + 1][0] = t[2]; bf[2 * np + 1][1] = t[3];
            }
#pragma unroll
            for (int mi = 0; mi < 4; mi++) {
                uint32_t off = (uint32_t)((wm * 64 + mi * 16 + lrow) * AS_PITCH + s * 16 + lhalf);
                uint32_t af[4];
                ldsm_x4(sbase + 2 * (SM_AH(b) + off), af);
#pragma unroll
                for (int ni = 0; ni < 4; ni++) mma_f16(acc[mi][ni], af, bf[ni]);
            }
        }
        __syncthreads();
    }

    const int row0 = blockM + wm * 64;
    const int col0 = n0 + wn * 32;
#pragma unroll
    for (int mi = 0; mi < 4; mi++) {
        int r0 = row0 + mi * 16 + (lane >> 2);
        int r1 = r0 + 8;
#pragma unroll
        for (int ni = 0; ni < 4; ni++) {
            int cc = col0 + ni * 8 + (lane & 3) * 2;
#pragma unroll
            for (int h = 0; h < 2; h++) {
                int r = h ? r1 : r0;
                if (r >= M) continue;
                float v0 = acc[mi][ni][2 * h], v1 = acc[mi][ni][2 * h + 1];
                if (MODE == 1) {
                    float2 ci = *(const float2*)(Cadd + (size_t)r * ldc + cc);
                    v0 += ci.x; v1 += ci.y;
                }
                *(__half2*)(Oh + (size_t)r * ldo + cc) = h2rn(v0, v1);
            }
        }
    }
}

__global__ __launch_bounds__(256, 2)
void gemm_add(const __half* __restrict__ A, int lda, const __half* __restrict__ B, int ldb,
              const float* __restrict__ Cadd, int ldc, __half* __restrict__ Oh, int ldo,
              int M, int K) {
    gemm_core<1>(A, lda, B, ldb, Cadd, ldc, Oh, ldo, M, K);
}

__global__ __launch_bounds__(256, 2)
void gemm_p(const __half* __restrict__ A, int lda, const __half* __restrict__ B, int ldb,
            __half* __restrict__ Oh, int ldo, int M, int K) {
    gemm_core<2>(A, lda, B, ldb, nullptr, 0, Oh, ldo, M, K);
}

// dual GEMM: blockIdx.z selects (A0,B0,O0) / (A1,B1,O1); same lda/ldb/ldo/M/K
__global__ __launch_bounds__(256, 2)
void gemm_dual(const __half* __restrict__ A0, const __half* __restrict__ A1, int lda,
               const __half* __restrict__ B0, const __half* __restrict__ B1, int ldb,
               __half* __restrict__ O0, __half* __restrict__ O1, int ldo,
               int M, int K) {
    if (blockIdx.z == 0)
        gemm_core<2>(A0, lda, B0, ldb, nullptr, 0, O0, ldo, M, K);
    else
        gemm_core<2>(A1, lda, B1, ldb, nullptr, 0, O1, ldo, M, K);
}

// ================= misc =================
__device__ __forceinline__ float sigm(float x) { return 1.f / (1.f + expf(-x)); }

__global__ void zero_f4(float4* p, size_t n4) {
    size_t i = (size_t)blockIdx.x * blockDim.x + threadIdx.x;
    size_t st = (size_t)gridDim.x * blockDim.x;
    for (; i < n4; i += st) p[i] = make_float4(0.f, 0.f, 0.f, 0.f);
}

__global__ void conv_h(const float* __restrict__ in, __half* __restrict__ hi, size_t n2) {
    size_t i = (size_t)blockIdx.x * blockDim.x + threadIdx.x;
    size_t st = (size_t)gridDim.x * blockDim.x;
    for (; i < n2; i += st) {
        float2 v = *(const float2*)(in + 2 * i);
        *(__half2*)(hi + 2 * i) = h2rn(v.x, v.y);
    }
}

__global__ void prep_b1_h(const float* __restrict__ w_ih, const float* __restrict__ w_hh,
                          __half* __restrict__ hi) {
    int i = blockIdx.x * blockDim.x + threadIdx.x;
    int st = gridDim.x * blockDim.x;
    for (; i < 1024 * 512; i += st) {
        int k = i >> 9;
        int n = (i & 511) * 2;
        float v0 = (k < 512) ? w_ih[(size_t)n * 512 + k] : w_hh[(size_t)n * 512 + k - 512];
        float v1 = (k < 512) ? w_ih[(size_t)(n + 1) * 512 + k] : w_hh[(size_t)(n + 1) * 512 + k - 512];
        *(__half2*)(hi + (size_t)k * 1024 + n) = h2rn(v0, v1);
    }
}

__global__ void prep_t512_h(const float* __restrict__ W, int rowoff, __half* __restrict__ hi) {
    int i = blockIdx.x * blockDim.x + threadIdx.x;
    int st = gridDim.x * blockDim.x;
    for (; i < 512 * 256; i += st) {
        int k = i >> 8;
        int n = (i & 255) * 2;
        float v0 = W[(size_t)(rowoff + n) * 512 + k];
        float v1 = W[(size_t)(rowoff + n + 1) * 512 + k];
        *(__half2*)(hi + (size_t)k * 512 + n) = h2rn(v0, v1);
    }
}

__global__ void pad_kernel(const float* __restrict__ x, float* __restrict__ hF,
                           __half* __restrict__ ahH) {
    int i = blockIdx.x * blockDim.x + threadIdx.x;
    int st = gridDim.x * blockDim.x;
    int tot = NN * 256;
    for (; i < tot; i += st) {
        int n = i >> 8;
        int c = (i & 255) * 2;
        float v0 = (c < INF_) ? x[(size_t)n * INF_ + c] : 0.f;
        float v1 = (c + 1 < INF_) ? x[(size_t)n * INF_ + c + 1] : 0.f;
        *(float2*)(hF + (size_t)n * 512 + c) = make_float2(v0, v1);
        *(__half2*)(ahH + (size_t)n * 1024 + 512 + c) = h2rn(v0, v1);
    }
}

// ================= CSR build =================
__global__ void csr_count(const int* __restrict__ dst, int* __restrict__ deg) {
    int e = blockIdx.x * blockDim.x + threadIdx.x;
    if (e < EE) atomicAdd(&deg[dst[e]], 1);
}

__global__ void csr_scan(const int* __restrict__ deg, int* __restrict__ rowptr,
                         int* __restrict__ cursor) {
    __shared__ int part[1024];
    int t = threadIdx.x;
    int b = t * 20;
    int loc[20];
    int s = 0;
#pragma unroll
    for (int i = 0; i < 20; i++) {
        int n = b + i;
        loc[i] = (n < NN) ? deg[n] : 0;
        s += loc[i];
    }
    part[t] = s;
    __syncthreads();
    for (int off = 1; off < 1024; off <<= 1) {
        int v = (t >= off) ? part[t - off] : 0;
        __syncthreads();
        part[t] += v;
        __syncthreads();
    }
    int run = part[t] - s;
#pragma unroll
    for (int i = 0; i < 20; i++) {
        int n = b + i;
        if (n < NN) {
            rowptr[n] = run;
            cursor[n] = run;
            run += loc[i];
        }
    }
    if (t == 0) rowptr[NN] = EE;
}

__global__ void csr_scatter(const int* __restrict__ dst, int* __restrict__ cursor,
                            int* __restrict__ eidx) {
    int e = blockIdx.x * blockDim.x + threadIdx.x;
    if (e < EE) {
        int pos = atomicAdd(&cursor[dst[e]], 1);
        eidx[pos] = e;
    }
}

// ================= per-dst aggregate gather + bias fold =================
__global__ __launch_bounds__(128)
void agg_gather(const __half* __restrict__ ahH, const int* __restrict__ src,
                const int* __restrict__ et, const int* __restrict__ rowptr,
                const int* __restrict__ eidx, const float* __restrict__ bmsg,
                __half* __restrict__ sH, float* __restrict__ aF) {
    int d = blockIdx.x;
    int t = threadIdx.x;
    int beg = rowptr[d], end = rowptr[d + 1];
    int c = t * 4;
    float4 acc[KT];
#pragma unroll
    for (int k = 0; k < KT; k++) acc[k] = make_float4(0.f, 0.f, 0.f, 0.f);
    int cn[KT] = {0, 0, 0, 0};

    __shared__ int ssrc[128];
    __shared__ int sket[128];
    for (int base = beg; base < end; base += 128) {
        int jj = base + t;
        if (jj < end) {
            int e = eidx[jj];
            ssrc[t] = src[e];
            sket[t] = et[e];
        }
        __syncthreads();
        int m = min(128, end - base);
#pragma unroll 2
        for (int q = 0; q < m; q++) {
            int s = ssrc[q];
            int k = sket[q];
            uint2 u = *(const uint2*)(ahH + (size_t)s * 1024 + 512 + c);
            float2 f0 = __half22float2(*(__half2*)&u.x);
            float2 f1 = __half22float2(*(__half2*)&u.y);
#pragma unroll
            for (int kk = 0; kk < KT; kk++) {
                if (k == kk) {
                    acc[kk].x += f0.x; acc[kk].y += f0.y;
                    acc[kk].z += f1.x; acc[kk].w += f1.y;
                    cn[kk]++;
                }
            }
        }
        __syncthreads();
    }
#pragma unroll
    for (int k = 0; k < KT; k++) {
        size_t o = (size_t)d * 2048 + k * 512 + c;
        *(__half2*)(sH + o) = h2rn(acc[k].x, acc[k].y);
        *(__half2*)(sH + o + 2) = h2rn(acc[k].z, acc[k].w);
    }
    // aF[d][c..c+3] = sum_k cn[k] * bmsg[k][c..c+3]
    float f0 = (float)cn[0], f1 = (float)cn[1], f2 = (float)cn[2], f3 = (float)cn[3];
#pragma unroll
    for (int j = 0; j < 4; j++) {
        float v = f0 * bmsg[c + j] + f1 * bmsg[512 + c + j] +
                  f2 * bmsg[1024 + c + j] + f3 * bmsg[1536 + c + j];
        aF[(size_t)d * 512 + c + j] = v;
    }
}

// GRU pointwise: reads fp16 P/Qi/Qh, writes hF fp32 + h fp16
__global__ void gru_kernel(const __half* __restrict__ PH, const __half* __restrict__ QiH,
                           const __half* __restrict__ QhH,
                           const float* __restrict__ b_ih, const float* __restrict__ b_hh,
                           float* __restrict__ hF, __half* __restrict__ ahH) {
    int i = blockIdx.x * blockDim.x + threadIdx.x;
    int st = gridDim.x * blockDim.x;
    int tot = NN * 256;
    for (; i < tot; i += st) {
        int n = i >> 8;
        int c = (i & 255) * 2;
        float2 pr = __half22float2(*(const __half2*)(PH + (size_t)n * 1024 + c));
        float2 pz = __half22float2(*(const __half2*)(PH + (size_t)n * 1024 + 512 + c));
        float2 qi = __half22float2(*(const __half2*)(QiH + (size_t)n * 512 + c));
        float2 qh = __half22float2(*(const __half2*)(QhH + (size_t)n * 512 + c));
        float prr[2] = {pr.x, pr.y}, pzz[2] = {pz.x, pz.y};
        float qii[2] = {qi.x, qi.y}, qhh[2] = {qh.x, qh.y};
        float hv[2];
#pragma unroll
        for (int u = 0; u < 2; u++) {
            int cc = c + u;
            float r = sigm(prr[u] + b_ih[cc] + b_hh[cc]);
            float z = sigm(pzz[u] + b_ih[512 + cc] + b_hh[512 + cc]);
            float nn = tanhf(qii[u] + b_ih[1024 + cc] + r * (qhh[u] + b_hh[1024 + cc]));
            float ho = hF[(size_t)n * 512 + cc];
            hv[u] = (1.f - z) * nn + z * ho;
        }
        *(float2*)(hF + (size_t)n * 512 + c) = make_float2(hv[0], hv[1]);
        *(__half2*)(ahH + (size_t)n * 1024 + 512 + c) = h2rn(hv[0], hv[1]);
    }
}

// L2-normalize + sigmoid; writes h fp16 only
__global__ void norm_sig_kernel(const float* __restrict__ hF, __half* __restrict__ ahH) {
    int n = blockIdx.x;
    int t = threadIdx.x;  // 128
    const float* row = hF + (size_t)n * 512;
    float4 v = *(const float4*)(row + t * 4);
    float s = v.x * v.x + v.y * v.y + v.z * v.z + v.w * v.w;
    __shared__ float sm[128];
    sm[t] = s;
    __syncthreads();
    for (int o = 64; o > 0; o >>= 1) {
        if (t < o) sm[t] += sm[t + o];
        __syncthreads();
    }
    float inv = 1.f / fmaxf(sqrtf(sm[0]), 1e-12f);
    size_t off = (size_t)n * 1024 + 512 + t * 4;
    *(__half2*)(ahH + off) = h2rn(sigm(v.x * inv), sigm(v.y * inv));
    *(__half2*)(ahH + off + 2) = h2rn(sigm(v.z * inv), sigm(v.w * inv));
}

// el/er from fp16 feat
__global__ void elr_kernel(const __half* __restrict__ featH, const float* __restrict__ attn_l,
                           const float* __restrict__ attn_r,
                           float* __restrict__ el, float* __restrict__ er) {
    int n = blockIdx.x;
    int t = threadIdx.x;  // 256
    float f0 = __half2float(featH[(size_t)n * H1 + t]);
    float f1 = __half2float(featH[(size_t)n * H1 + H2C + t]);
    float vals[4] = {f0 * attn_l[t], f0 * attn_r[t], f1 * attn_l[H2C + t], f1 * attn_r[H2C + t]};
    float outp[4];
    __shared__ float sm[256];
#pragma unroll
    for (int q = 0; q < 4; q++) {
        sm[t] = vals[q];
        __syncthreads();
        for (int o = 128; o > 0; o >>= 1) {
            if (t < o) sm[t] += sm[t + o];
            __syncthreads();
        }
        outp[q] = sm[0];
        __syncthreads();
    }
    if (t == 0) {
        el[n * 2] = outp[0];
        er[n * 2] = outp[1];
        el[n * 2 + 1] = outp[2];
        er[n * 2 + 1] = outp[3];
    }
}

// ================= single-pass fused GAT per-dst =================
__global__ __launch_bounds__(128)
void gat_fused(const int* __restrict__ src, const int* __restrict__ rowptr,
               const int* __restrict__ eidx, const float* __restrict__ el,
               const float* __restrict__ er, const __half* __restrict__ featH,
               const int* __restrict__ gid, const float* __restrict__ gat_bias,
               float* __restrict__ hg, float* __restrict__ gcnt) {
    int d = blockIdx.x;
    int t = threadIdx.x;
    int beg = rowptr[d], end = rowptr[d + 1];
    float er0 = er[2 * d], er1 = er[2 * d + 1];

    __shared__ float sal0[128], sal1[128];
    __shared__ int ssrc[128];
    int c = t * 4;
    bool head0 = c < H2C;
    float4 acc = make_float4(0.f, 0.f, 0.f, 0.f);
    float dsum = 0.f;
    for (int base = beg; base < end; base += 128) {
        int jj = base + t;
        if (jj < end) {
            int s = src[eidx[jj]];
            float v0 = el[2 * s] + er0;      v0 = v0 > 0.f ? v0 : 0.2f * v0;
            float v1 = el[2 * s + 1] + er1;  v1 = v1 > 0.f ? v1 : 0.2f * v1;
            sal0[t] = expf(v0);
            sal1[t] = expf(v1);
            ssrc[t] = s;
        }
        __syncthreads();
        int m = min(128, end - base);
        for (int q = 0; q < m; q++) {
            float w = head0 ? sal0[q] : sal1[q];
            dsum += w;
            uint2 u = *(const uint2*)(featH + (size_t)ssrc[q] * 512 + c);
            float2 f0 = __half22float2(*(__half2*)&u.x);
            float2 f1 = __half22float2(*(__half2*)&u.y);
            acc.x += w * f0.x; acc.y += w * f0.y;
            acc.z += w * f1.x; acc.w += w * f1.y;
        }
        __syncthreads();
    }
    float invd = (dsum > 0.f) ? 1.f / dsum : 0.f;
    float4 b = *(const float4*)(gat_bias + c);
    int g = gid[d];
    atomicAdd(&hg[(size_t)g * 512 + c + 0], fmaxf(acc.x * invd + b.x, 0.f));
    atomicAdd(&hg[(size_t)g * 512 + c + 1], fmaxf(acc.y * invd + b.y, 0.f));
    atomicAdd(&hg[(size_t)g * 512 + c + 2], fmaxf(acc.z * invd + b.z, 0.f));
    atomicAdd(&hg[(size_t)g * 512 + c + 3], fmaxf(acc.w * invd + b.w, 0.f));
    if (t == 0) atomicAdd(&gcnt[g], 1.f);
}

__global__ void final_kernel(const float* __restrict__ hg, const float* __restrict__ gcnt,
                             const float* __restrict__ cw, const float* __restrict__ cb,
                             float* __restrict__ out) {
    int g = blockIdx.x >> 1, hd = blockIdx.x & 1;
    int t = threadIdx.x;  // 256
    __shared__ float row[H2C];
    float inv = 1.f / fmaxf(gcnt[g], 1.f);
    row[t] = hg[(size_t)g * H1 + hd * H2C + t] * inv;
    __syncthreads();
    if (t < CC) {
        float s = cb[t];
        for (int j = 0; j < H2C; j++) s += row[j] * cw[t * H2C + j];
        out[((size_t)g * HEADS + hd) * CC + t] = s;
    }
}

// ================= launch =================
extern "C" void kernel_launch(void* const* d_in, const int* in_sizes, int n_in,
                              void* d_out, int out_size) {
    const float* in_feat  = (const float*)d_in[0];
    const int*   src      = (const int*)d_in[1];
    const int*   dst      = (const int*)d_in[2];
    const int*   etype    = (const int*)d_in[3];
    const int*   gid      = (const int*)d_in[4];
    const float* Wmsg     = (const float*)d_in[5];
    const float* bmsg     = (const float*)d_in[6];
    const float* w_ih     = (const float*)d_in[7];
    const float* w_hh     = (const float*)d_in[8];
    const float* b_ih     = (const float*)d_in[9];
    const float* b_hh     = (const float*)d_in[10];
    const float* fc_w     = (const float*)d_in[11];
    const float* attn_l   = (const float*)d_in[12];
    const float* attn_r   = (const float*)d_in[13];
    const float* gat_bias = (const float*)d_in[14];
    const float* cw       = (const float*)d_in[15];
    const float* cb       = (const float*)d_in[16];
    float* out = (float*)d_out;

    cudaFuncSetAttribute(gemm_add, cudaFuncAttributeMaxDynamicSharedMemorySize, SMEM_BYTES);
    cudaFuncSetAttribute(gemm_p, cudaFuncAttributeMaxDynamicSharedMemorySize, SMEM_BYTES);
    cudaFuncSetAttribute(gemm_dual, cudaFuncAttributeMaxDynamicSharedMemorySize, SMEM_BYTES);

    float* base = nullptr;
    cudaGetSymbolAddress((void**)&base, g_buf);

    float*  hF    = base + OFF_HF;
    float*  aF    = base + OFF_AF;
    __half* PH    = (__half*)(base + OFF_PH);
    __half* QiH   = (__half*)(base + OFF_QIH);
    __half* QhH   = (__half*)(base + OFF_QHH);
    __half* featH = (__half*)(base + OFF_FEATH);
    __half* ahH   = (__half*)(base + OFF_AHH);
    __half* sH    = (__half*)(base + OFF_SAGH);
    __half* WmH   = (__half*)(base + OFF_WMH);
    __half* B1H   = (__half*)(base + OFF_B1H);
    __half* WiH   = (__half*)(base + OFF_WIH);
    __half* WhH   = (__half*)(base + OFF_WHH);
    __half* FcH   = (__half*)(base + OFF_FCH);
    float*  el    = base + OFF_EL;
    float*  er    = base + OFF_ER;
    float*  hg    = base + OFF_HG;
    float*  gcnt  = base + OFF_GCNT;
    int*    deg   = (int*)(base + OFF_DEG);
    int*    rptr  = (int*)(base + OFF_RPTR);
    int*    cur   = (int*)(base + OFF_CUR);
    int*    eidx  = (int*)(base + OFF_EIDX);

    conv_h<<<512, 256>>>(Wmsg, WmH, (size_t)2048 * 512 / 2);
    prep_b1_h<<<512, 256>>>(w_ih, w_hh, B1H);
    prep_t512_h<<<256, 256>>>(w_ih, 1024, WiH);
    prep_t512_h<<<256, 256>>>(w_hh, 1024, WhH);
    prep_t512_h<<<256, 256>>>(fc_w, 0, FcH);
    pad_kernel<<<4096, 256>>>(in_feat, hF, ahH);

    zero_f4<<<32, 256>>>((float4*)deg, NN / 4);
    csr_count<<<(EE + 255) / 256, 256>>>(dst, deg);
    csr_scan<<<1, 1024>>>(deg, rptr, cur);
    csr_scatter<<<(EE + 255) / 256, 256>>>(dst, cur, eidx);

    const int GM = (NN + 127) / 128;  // 157

    for (int step = 0; step < NSTEPS; step++) {
        agg_gather<<<NN, 128>>>(ahH, src, etype, rptr, eidx, bmsg, sH, aF);
        // a = aF + sagg @ Wmsg -> fp16 into ah cols 0..511
        gemm_add<<<dim3(GM, 4), 256, SMEM_BYTES>>>(sH, 2048, WmH, 512, aF, 512, ahH, 1024,
                                                   NN, 2048);
        // P = [a|h] @ B1 (fp16 out)
        gemm_p<<<dim3(GM, 8), 256, SMEM_BYTES>>>(ahH, 1024, B1H, 1024, PH, 1024, NN, 1024);
        // Qi = a @ WnI^T ; Qh = h @ WnH^T (one dual launch)
        gemm_dual<<<dim3(GM, 4, 2), 256, SMEM_BYTES>>>(ahH, ahH + 512, 1024, WiH, WhH, 512,
                                                       QiH, QhH, 512, NN, 512);
        gru_kernel<<<4096, 256>>>(PH, QiH, QhH, b_ih, b_hh, hF, ahH);
    }

    norm_sig_kernel<<<NN, 128>>>(hF, ahH);
    gemm_p<<<dim3(GM, 4), 256, SMEM_BYTES>>>(ahH + 512, 1024, FcH, 512, featH, 512, NN, 512);
    elr_kernel<<<NN, 256>>>(featH, attn_l, attn_r, el, er);

    zero_f4<<<32, 256>>>((float4*)hg, ((size_t)GG * 512 + GG) / 4);
    gat_fused<<<NN, 128>>>(src, rptr, eidx, el, er, featH, gid, gat_bias, hg, gcnt);
    final_kernel<<<GG * HEADS, 256>>>(hg, gcnt, cw, cb, out);
}

// round 11
// speedup vs baseline: 7.2274x; 1.0004x over previous
#include <cuda_runtime.h>
#include <cuda_fp16.h>
#include <math.h>
#include <stdint.h>

#define NN 20000
#define EE 320000
#define GG 64
#define INF_ 256
#define H1 512
#define H2C 256
#define HEADS 2
#define CC 16
#define NSTEPS 4
#define KT 4

// ================= scratch layout (float units) =================
constexpr size_t OFF_HF    = 0;                               // NN x 512 f32 (h)
constexpr size_t OFF_AF    = OFF_HF + (size_t)NN * 512;       // NN x 512 f32 (a bias base)
constexpr size_t OFF_YA    = OFF_AF + (size_t)NN * 512;       // NN x 1536 halves
constexpr size_t OFF_YH    = OFF_YA + (size_t)NN * 768;       // NN x 1536 halves
constexpr size_t OFF_FEATH = OFF_YH + (size_t)NN * 768;       // NN x 512 halves
constexpr size_t OFF_AHH   = OFF_FEATH + (size_t)NN * 256;    // NN x 1024 halves ([a|h])
constexpr size_t OFF_SAGH  = OFF_AHH + (size_t)NN * 512;      // NN x 2048 halves
constexpr size_t OFF_WMH   = OFF_SAGH + (size_t)NN * 1024;    // 2048x512 halves
constexpr size_t OFF_WIHT  = OFF_WMH + 524288;                // 512x1536 halves
constexpr size_t OFF_WHHT  = OFF_WIHT + 393216;
constexpr size_t OFF_FCH   = OFF_WHHT + 393216;               // 512x512 halves
constexpr size_t OFF_EL    = OFF_FCH + 131072;                // NN x 2
constexpr size_t OFF_ER    = OFF_EL + (size_t)NN * 2;
constexpr size_t OFF_HG    = OFF_ER + (size_t)NN * 2;         // GG x 512
constexpr size_t OFF_GCNT  = OFF_HG + (size_t)GG * 512;       // GG
// int regions
constexpr size_t OFF_DEG   = OFF_GCNT + GG;                   // NN ints
constexpr size_t OFF_RPTR  = OFF_DEG + NN;                    // NN+4 ints
constexpr size_t OFF_CUR   = OFF_RPTR + NN + 4;               // NN ints
constexpr size_t OFF_EIDX  = OFF_CUR + NN;                    // EE ints
constexpr size_t TOTAL_F   = OFF_EIDX + EE + 16;

__device__ __align__(16) float g_buf[TOTAL_F];

// ================= PTX helpers =================
__device__ __forceinline__ uint32_t smem_to_u32(const void* p) {
    uint32_t a;
    asm("{ .reg .u64 t; cvta.to.shared.u64 t, %1; cvt.u32.u64 %0, t; }" : "=r"(a) : "l"(p));
    return a;
}
__device__ __forceinline__ void ldsm_x4(uint32_t addr, uint32_t* r) {
    asm volatile("ldmatrix.sync.aligned.m8n8.x4.shared.b16 {%0,%1,%2,%3}, [%4];"
                 : "=r"(r[0]), "=r"(r[1]), "=r"(r[2]), "=r"(r[3]) : "r"(addr));
}
__device__ __forceinline__ void ldsm_x4_t(uint32_t addr, uint32_t* r) {
    asm volatile("ldmatrix.sync.aligned.m8n8.x4.trans.shared.b16 {%0,%1,%2,%3}, [%4];"
                 : "=r"(r[0]), "=r"(r[1]), "=r"(r[2]), "=r"(r[3]) : "r"(addr));
}
__device__ __forceinline__ void mma_f16(float* c, const uint32_t* a, const uint32_t* b) {
    asm volatile(
        "mma.sync.aligned.m16n8k16.row.col.f32.f16.f16.f32 "
        "{%0,%1,%2,%3},{%4,%5,%6,%7},{%8,%9},{%0,%1,%2,%3};"
        : "+f"(c[0]), "+f"(c[1]), "+f"(c[2]), "+f"(c[3])
        : "r"(a[0]), "r"(a[1]), "r"(a[2]), "r"(a[3]), "r"(b[0]), "r"(b[1]));
}
__device__ __forceinline__ __half2 h2rn(float x0, float x1) {
    return __halves2half2(__float2half_rn(x0), __float2half_rn(x1));
}
__device__ __forceinline__ void cpa16(uint32_t d, const void* g, int sz) {
    asm volatile("cp.async.cg.shared.global [%0], [%1], 16, %2;"
                 :: "r"(d), "l"(g), "r"(sz) : "memory");
}
__device__ __forceinline__ void cpa_commit() {
    asm volatile("cp.async.commit_group;" ::: "memory");
}
template <int N>
__device__ __forceinline__ void cpa_wait() {
    asm volatile("cp.async.wait_group %0;" :: "n"(N) : "memory");
}

// ================= SMEM layout for gemm (half-element offsets) =================
#define AS_PITCH 40
#define BS_PITCH 136
#define SM_AH(b) ((b) * 5120)
#define SM_BH(b) (10240 + (b) * 4352)
#define SMEM_HALFS 18944
#define SMEM_BYTES (SMEM_HALFS * 2)

// ================= pure-fp16 HMMA GEMM core =================
// MODE 1: v = Cadd + acc -> Oh fp16 ; MODE 2: Oh = fp16(acc)
template <int MODE>
__device__ __forceinline__ void gemm_core(
    const __half* __restrict__ A, int lda,
    const __half* __restrict__ B, int ldb,
    const float* __restrict__ Cadd, int ldc,
    __half* __restrict__ Oh, int ldo,
    int M, int K) {
    extern __shared__ __half smh[];
    const uint32_t sbase = smem_to_u32(smh);

    const int tid = threadIdx.x;
    const int lane = tid & 31;
    const int wid = tid >> 5;
    const int wm = wid >> 2;
    const int wn = wid & 3;
    const int blockM = blockIdx.x * 128;
    const int n0 = blockIdx.y * 128;

    const int ar = tid >> 1, ac = (tid & 1) * 16;
    const int bk = tid >> 3, bn = (tid & 7) * 16;
    const bool aval = (blockM + ar) < M;
    const int asz = aval ? 16 : 0;
    const __half* Ap = A + (size_t)(aval ? blockM + ar : 0) * lda + ac;
    const __half* Bp = B + (size_t)bk * ldb + n0 + bn;

    const uint32_t dA = sbase + 2 * (uint32_t)(ar * AS_PITCH + ac);
    const uint32_t dB = sbase + 2 * (uint32_t)(10240 + bk * BS_PITCH + bn);

    const int nC = K >> 5;

    float acc[4][4][4];
#pragma unroll
    for (int mi = 0; mi < 4; mi++)
#pragma unroll
        for (int ni = 0; ni < 4; ni++)
#pragma unroll
            for (int q = 0; q < 4; q++) acc[mi][ni][q] = 0.f;

    auto issue = [&](int c) {
        const int boffA = (c & 1) * 2 * 5120;
        const int boffB = (c & 1) * 2 * 4352;
        const __half* a = Ap + c * 32;
        const __half* b = Bp + (size_t)c * 32 * ldb;
        cpa16(dA + boffA, a, asz);
        cpa16(dA + boffA + 16, a + 8, asz);
        cpa16(dB + boffB, b, 16);
        cpa16(dB + boffB + 16, b + 8, 16);
        cpa_commit();
    };

    issue(0);

    const int lrow = lane & 15;
    const int lhalf = (lane >> 4) * 8;

    for (int c = 0; c < nC; c++) {
        const int b = c & 1;
        if (c + 1 < nC) {
            issue(c + 1);
            cpa_wait<1>();
        } else {
            cpa_wait<0>();
        }
        __syncthreads();

#pragma unroll
        for (int s = 0; s < 2; s++) {
            uint32_t bf[4][2];
#pragma unroll
            for (int np = 0; np < 2; np++) {
                uint32_t off = (uint32_t)((s * 16 + lrow) * BS_PITCH + wn * 32 + np * 16 + lhalf);
                uint32_t t[4];
                ldsm_x4_t(sbase + 2 * (SM_BH(b) + off), t);
                bf[2 * np][0] = t[0]; bf[2 * np][1] = t[1];
                bf[2 * np + 1][0] = t[2]; bf[2 * np + 1][1] = t[3];
            }
#pragma unroll
            for (int mi = 0; mi < 4; mi++) {
                uint32_t off = (uint32_t)((wm * 64 + mi * 16 + lrow) * AS_PITCH + s * 16 + lhalf);
                uint32_t af[4];
                ldsm_x4(sbase + 2 * (SM_AH(b) + off), af);
#pragma unroll
                for (int ni = 0; ni < 4; ni++) mma_f16(acc[mi][ni], af, bf[ni]);
            }
        }
        __syncthreads();
    }

    const int row0 = blockM + wm * 64;
    const int col0 = n0 + wn * 32;
#pragma unroll
    for (int mi = 0; mi < 4; mi++) {
        int r0 = row0 + mi * 16 + (lane >> 2);
        int r1 = r0 + 8;
#pragma unroll
        for (int ni = 0; ni < 4; ni++) {
            int cc = col0 + ni * 8 + (lane & 3) * 2;
#pragma unroll
            for (int h = 0; h < 2; h++) {
                int r = h ? r1 : r0;
                if (r >= M) continue;
                float v0 = acc[mi][ni][2 * h], v1 = acc[mi][ni][2 * h + 1];
                if (MODE == 1) {
                    float2 ci = *(const float2*)(Cadd + (size_t)r * ldc + cc);
                    v0 += ci.x; v1 += ci.y;
                }
                *(__half2*)(Oh + (size_t)r * ldo + cc) = h2rn(v0, v1);
            }
        }
    }
}

__global__ __launch_bounds__(256, 2)
void gemm_add(const __half* __restrict__ A, int lda, const __half* __restrict__ B, int ldb,
              const float* __restrict__ Cadd, int ldc, __half* __restrict__ Oh, int ldo,
              int M, int K) {
    gemm_core<1>(A, lda, B, ldb, Cadd, ldc, Oh, ldo, M, K);
}

__global__ __launch_bounds__(256, 2)
void gemm_p(const __half* __restrict__ A, int lda, const __half* __restrict__ B, int ldb,
            __half* __restrict__ Oh, int ldo, int M, int K) {
    gemm_core<2>(A, lda, B, ldb, nullptr, 0, Oh, ldo, M, K);
}

// ================= misc =================
__device__ __forceinline__ float sigm(float x) { return 1.f / (1.f + expf(-x)); }

__global__ void zero_f4(float4* p, size_t n4) {
    size_t i = (size_t)blockIdx.x * blockDim.x + threadIdx.x;
    size_t st = (size_t)gridDim.x * blockDim.x;
    for (; i < n4; i += st) p[i] = make_float4(0.f, 0.f, 0.f, 0.f);
}

__global__ void conv_h(const float* __restrict__ in, __half* __restrict__ hi, size_t n2) {
    size_t i = (size_t)blockIdx.x * blockDim.x + threadIdx.x;
    size_t st = (size_t)gridDim.x * blockDim.x;
    for (; i < n2; i += st) {
        float2 v = *(const float2*)(in + 2 * i);
        *(__half2*)(hi + 2 * i) = h2rn(v.x, v.y);
    }
}

// T[k][n] fp16 = W[n*512 + k], k in 0..511, n in 0..NROWS-1
__global__ void prep_tT_h(const float* __restrict__ W, int nrows, __half* __restrict__ hi) {
    int i = blockIdx.x * blockDim.x + threadIdx.x;
    int st = gridDim.x * blockDim.x;
    int tot = 512 * (nrows / 2);
    for (; i < tot; i += st) {
        int k = i / (nrows / 2);
        int n = (i % (nrows / 2)) * 2;
        float v0 = W[(size_t)n * 512 + k];
        float v1 = W[(size_t)(n + 1) * 512 + k];
        *(__half2*)(hi + (size_t)k * nrows + n) = h2rn(v0, v1);
    }
}

__global__ void pad_kernel(const float* __restrict__ x, float* __restrict__ hF,
                           __half* __restrict__ ahH) {
    int i = blockIdx.x * blockDim.x + threadIdx.x;
    int st = gridDim.x * blockDim.x;
    int tot = NN * 256;
    for (; i < tot; i += st) {
        int n = i >> 8;
        int c = (i & 255) * 2;
        float v0 = (c < INF_) ? x[(size_t)n * INF_ + c] : 0.f;
        float v1 = (c + 1 < INF_) ? x[(size_t)n * INF_ + c + 1] : 0.f;
        *(float2*)(hF + (size_t)n * 512 + c) = make_float2(v0, v1);
        *(__half2*)(ahH + (size_t)n * 1024 + 512 + c) = h2rn(v0, v1);
    }
}

// ================= CSR build =================
__global__ void csr_count(const int* __restrict__ dst, int* __restrict__ deg) {
    int e = blockIdx.x * blockDim.x + threadIdx.x;
    if (e < EE) atomicAdd(&deg[dst[e]], 1);
}

__global__ void csr_scan(const int* __restrict__ deg, int* __restrict__ rowptr,
                         int* __restrict__ cursor) {
    __shared__ int part[1024];
    int t = threadIdx.x;
    int b = t * 20;
    int loc[20];
    int s = 0;
#pragma unroll
    for (int i = 0; i < 20; i++) {
        int n = b + i;
        loc[i] = (n < NN) ? deg[n] : 0;
        s += loc[i];
    }
    part[t] = s;
    __syncthreads();
    for (int off = 1; off < 1024; off <<= 1) {
        int v = (t >= off) ? part[t - off] : 0;
        __syncthreads();
        part[t] += v;
        __syncthreads();
    }
    int run = part[t] - s;
#pragma unroll
    for (int i = 0; i < 20; i++) {
        int n = b + i;
        if (n < NN) {
            rowptr[n] = run;
            cursor[n] = run;
            run += loc[i];
        }
    }
    if (t == 0) rowptr[NN] = EE;
}

__global__ void csr_scatter(const int* __restrict__ dst, int* __restrict__ cursor,
                            int* __restrict__ eidx) {
    int e = blockIdx.x * blockDim.x + threadIdx.x;
    if (e < EE) {
        int pos = atomicAdd(&cursor[dst[e]], 1);
        eidx[pos] = e;
    }
}

// ================= per-dst aggregate gather + bias fold =================
__global__ __launch_bounds__(128)
void agg_gather(const __half* __restrict__ ahH, const int* __restrict__ src,
                const int* __restrict__ et, const int* __restrict__ rowptr,
                const int* __restrict__ eidx, const float* __restrict__ bmsg,
                __half* __restrict__ sH, float* __restrict__ aF) {
    int d = blockIdx.x;
    int t = threadIdx.x;
    int beg = rowptr[d], end = rowptr[d + 1];
    int c = t * 4;
    float4 acc[KT];
#pragma unroll
    for (int k = 0; k < KT; k++) acc[k] = make_float4(0.f, 0.f, 0.f, 0.f);
    int cn[KT] = {0, 0, 0, 0};

    __shared__ int ssrc[128];
    __shared__ int sket[128];
    for (int base = beg; base < end; base += 128) {
        int jj = base + t;
        if (jj < end) {
            int e = eidx[jj];
            ssrc[t] = src[e];
            sket[t] = et[e];
        }
        __syncthreads();
        int m = min(128, end - base);
#pragma unroll 2
        for (int q = 0; q < m; q++) {
            int s = ssrc[q];
            int k = sket[q];
            uint2 u = *(const uint2*)(ahH + (size_t)s * 1024 + 512 + c);
            float2 f0 = __half22float2(*(__half2*)&u.x);
            float2 f1 = __half22float2(*(__half2*)&u.y);
#pragma unroll
            for (int kk = 0; kk < KT; kk++) {
                if (k == kk) {
                    acc[kk].x += f0.x; acc[kk].y += f0.y;
                    acc[kk].z += f1.x; acc[kk].w += f1.y;
                    cn[kk]++;
                }
            }
        }
        __syncthreads();
    }
#pragma unroll
    for (int k = 0; k < KT; k++) {
        size_t o = (size_t)d * 2048 + k * 512 + c;
        *(__half2*)(sH + o) = h2rn(acc[k].x, acc[k].y);
        *(__half2*)(sH + o + 2) = h2rn(acc[k].z, acc[k].w);
    }
    float f0 = (float)cn[0], f1 = (float)cn[1], f2 = (float)cn[2], f3 = (float)cn[3];
#pragma unroll
    for (int j = 0; j < 4; j++) {
        float v = f0 * bmsg[c + j] + f1 * bmsg[512 + c + j] +
                  f2 * bmsg[1024 + c + j] + f3 * bmsg[1536 + c + j];
        aF[(size_t)d * 512 + c + j] = v;
    }
}

// GRU pointwise: reads fp16 Ya/Yh (stride 1536), writes hF fp32 + h fp16
__global__ void gru_kernel(const __half* __restrict__ Ya, const __half* __restrict__ Yh,
                           const float* __restrict__ b_ih, const float* __restrict__ b_hh,
                           float* __restrict__ hF, __half* __restrict__ ahH) {
    int i = blockIdx.x * blockDim.x + threadIdx.x;
    int st = gridDim.x * blockDim.x;
    int tot = NN * 256;
    for (; i < tot; i += st) {
        int n = i >> 8;
        int c = (i & 255) * 2;
        size_t yb = (size_t)n * 1536;
        float2 ir = __half22float2(*(const __half2*)(Ya + yb + c));
        float2 iz = __half22float2(*(const __half2*)(Ya + yb + 512 + c));
        float2 in_ = __half22float2(*(const __half2*)(Ya + yb + 1024 + c));
        float2 hr = __half22float2(*(const __half2*)(Yh + yb + c));
        float2 hz = __half22float2(*(const __half2*)(Yh + yb + 512 + c));
        float2 hn = __half22float2(*(const __half2*)(Yh + yb + 1024 + c));
        float irr[2] = {ir.x, ir.y}, izz[2] = {iz.x, iz.y}, inn[2] = {in_.x, in_.y};
        float hrr[2] = {hr.x, hr.y}, hzz[2] = {hz.x, hz.y}, hnn[2] = {hn.x, hn.y};
        float hv[2];
#pragma unroll
        for (int u = 0; u < 2; u++) {
            int cc = c + u;
            float r = sigm(irr[u] + hrr[u] + b_ih[cc] + b_hh[cc]);
            float z = sigm(izz[u] + hzz[u] + b_ih[512 + cc] + b_hh[512 + cc]);
            float nn = tanhf(inn[u] + b_ih[1024 + cc] + r * (hnn[u] + b_hh[1024 + cc]));
            float ho = hF[(size_t)n * 512 + cc];
            hv[u] = (1.f - z) * nn + z * ho;
        }
        *(float2*)(hF + (size_t)n * 512 + c) = make_float2(hv[0], hv[1]);
        *(__half2*)(ahH + (size_t)n * 1024 + 512 + c) = h2rn(hv[0], hv[1]);
    }
}

// L2-normalize + sigmoid; writes h fp16 only
__global__ void norm_sig_kernel(const float* __restrict__ hF, __half* __restrict__ ahH) {
    int n = blockIdx.x;
    int t = threadIdx.x;  // 128
    const float* row = hF + (size_t)n * 512;
    float4 v = *(const float4*)(row + t * 4);
    float s = v.x * v.x + v.y * v.y + v.z * v.z + v.w * v.w;
    __shared__ float sm[128];
    sm[t] = s;
    __syncthreads();
    for (int o = 64; o > 0; o >>= 1) {
        if (t < o) sm[t] += sm[t + o];
        __syncthreads();
    }
    float inv = 1.f / fmaxf(sqrtf(sm[0]), 1e-12f);
    size_t off = (size_t)n * 1024 + 512 + t * 4;
    *(__half2*)(ahH + off) = h2rn(sigm(v.x * inv), sigm(v.y * inv));
    *(__half2*)(ahH + off + 2) = h2rn(sigm(v.z * inv), sigm(v.w * inv));
}

__global__ void elr_kernel(const __half* __restrict__ featH, const float* __restrict__ attn_l,
                           const float* __restrict__ attn_r,
                           float* __restrict__ el, float* __restrict__ er) {
    int n = blockIdx.x;
    int t = threadIdx.x;  // 256
    float f0 = __half2float(featH[(size_t)n * H1 + t]);
    float f1 = __half2float(featH[(size_t)n * H1 + H2C + t]);
    float vals[4] = {f0 * attn_l[t], f0 * attn_r[t], f1 * attn_l[H2C + t], f1 * attn_r[H2C + t]};
    float outp[4];
    __shared__ float sm[256];
#pragma unroll
    for (int q = 0; q < 4; q++) {
        sm[t] = vals[q];
        __syncthreads();
        for (int o = 128; o > 0; o >>= 1) {
            if (t < o) sm[t] += sm[t + o];
            __syncthreads();
        }
        outp[q] = sm[0];
        __syncthreads();
    }
    if (t == 0) {
        el[n * 2] = outp[0];
        er[n * 2] = outp[1];
        el[n * 2 + 1] = outp[2];
        er[n * 2 + 1] = outp[3];
    }
}

// ================= single-pass fused GAT per-dst =================
__global__ __launch_bounds__(128)
void gat_fused(const int* __restrict__ src, const int* __restrict__ rowptr,
               const int* __restrict__ eidx, const float* __restrict__ el,
               const float* __restrict__ er, const __half* __restrict__ featH,
               const int* __restrict__ gid, const float* __restrict__ gat_bias,
               float* __restrict__ hg, float* __restrict__ gcnt) {
    int d = blockIdx.x;
    int t = threadIdx.x;
    int beg = rowptr[d], end = rowptr[d + 1];
    float er0 = er[2 * d], er1 = er[2 * d + 1];

    __shared__ float sal0[128], sal1[128];
    __shared__ int ssrc[128];
    int c = t * 4;
    bool head0 = c < H2C;
    float4 acc = make_float4(0.f, 0.f, 0.f, 0.f);
    float dsum = 0.f;
    for (int base = beg; base < end; base += 128) {
        int jj = base + t;
        if (jj < end) {
            int s = src[eidx[jj]];
            float v0 = el[2 * s] + er0;      v0 = v0 > 0.f ? v0 : 0.2f * v0;
            float v1 = el[2 * s + 1] + er1;  v1 = v1 > 0.f ? v1 : 0.2f * v1;
            sal0[t] = expf(v0);
            sal1[t] = expf(v1);
            ssrc[t] = s;
        }
        __syncthreads();
        int m = min(128, end - base);
        for (int q = 0; q < m; q++) {
            float w = head0 ? sal0[q] : sal1[q];
            dsum += w;
            uint2 u = *(const uint2*)(featH + (size_t)ssrc[q] * 512 + c);
            float2 f0 = __half22float2(*(__half2*)&u.x);
            float2 f1 = __half22float2(*(__half2*)&u.y);
            acc.x += w * f0.x; acc.y += w * f0.y;
            acc.z += w * f1.x; acc.w += w * f1.y;
        }
        __syncthreads();
    }
    float invd = (dsum > 0.f) ? 1.f / dsum : 0.f;
    float4 b = *(const float4*)(gat_bias + c);
    int g = gid[d];
    atomicAdd(&hg[(size_t)g * 512 + c + 0], fmaxf(acc.x * invd + b.x, 0.f));
    atomicAdd(&hg[(size_t)g * 512 + c + 1], fmaxf(acc.y * invd + b.y, 0.f));
    atomicAdd(&hg[(size_t)g * 512 + c + 2], fmaxf(acc.z * invd + b.z, 0.f));
    atomicAdd(&hg[(size_t)g * 512 + c + 3], fmaxf(acc.w * invd + b.w, 0.f));
    if (t == 0) atomicAdd(&gcnt[g], 1.f);
}

__global__ void final_kernel(const float* __restrict__ hg, const float* __restrict__ gcnt,
                             const float* __restrict__ cw, const float* __restrict__ cb,
                             float* __restrict__ out) {
    int g = blockIdx.x >> 1, hd = blockIdx.x & 1;
    int t = threadIdx.x;  // 256
    __shared__ float row[H2C];
    float inv = 1.f / fmaxf(gcnt[g], 1.f);
    row[t] = hg[(size_t)g * H1 + hd * H2C + t] * inv;
    __syncthreads();
    if (t < CC) {
        float s = cb[t];
        for (int j = 0; j < H2C; j++) s += row[j] * cw[t * H2C + j];
        out[((size_t)g * HEADS + hd) * CC + t] = s;
    }
}

// ================= launch =================
extern "C" void kernel_launch(void* const* d_in, const int* in_sizes, int n_in,
                              void* d_out, int out_size) {
    const float* in_feat  = (const float*)d_in[0];
    const int*   src      = (const int*)d_in[1];
    const int*   dst      = (const int*)d_in[2];
    const int*   etype    = (const int*)d_in[3];
    const int*   gid      = (const int*)d_in[4];
    const float* Wmsg     = (const float*)d_in[5];
    const float* bmsg     = (const float*)d_in[6];
    const float* w_ih     = (const float*)d_in[7];
    const float* w_hh     = (const float*)d_in[8];
    const float* b_ih     = (const float*)d_in[9];
    const float* b_hh     = (const float*)d_in[10];
    const float* fc_w     = (const float*)d_in[11];
    const float* attn_l   = (const float*)d_in[12];
    const float* attn_r   = (const float*)d_in[13];
    const float* gat_bias = (const float*)d_in[14];
    const float* cw       = (const float*)d_in[15];
    const float* cb       = (const float*)d_in[16];
    float* out = (float*)d_out;

    cudaFuncSetAttribute(gemm_add, cudaFuncAttributeMaxDynamicSharedMemorySize, SMEM_BYTES);
    cudaFuncSetAttribute(gemm_p, cudaFuncAttributeMaxDynamicSharedMemorySize, SMEM_BYTES);

    // one-time stream/event setup (host objects, no device memory)
    static cudaStream_t s2 = nullptr;
    static cudaEvent_t evFork = nullptr, evJoin = nullptr;
    if (!s2) {
        cudaStreamCreateWithFlags(&s2, cudaStreamNonBlocking);
        cudaEventCreateWithFlags(&evFork, cudaEventDisableTiming);
        cudaEventCreateWithFlags(&evJoin, cudaEventDisableTiming);
    }

    float* base = nullptr;
    cudaGetSymbolAddress((void**)&base, g_buf);

    float*  hF    = base + OFF_HF;
    float*  aF    = base + OFF_AF;
    __half* YaH   = (__half*)(base + OFF_YA);
    __half* YhH   = (__half*)(base + OFF_YH);
    __half* featH = (__half*)(base + OFF_FEATH);
    __half* ahH   = (__half*)(base + OFF_AHH);
    __half* sH    = (__half*)(base + OFF_SAGH);
    __half* WmH   = (__half*)(base + OFF_WMH);
    __half* WihT  = (__half*)(base + OFF_WIHT);
    __half* WhhT  = (__half*)(base + OFF_WHHT);
    __half* FcH   = (__half*)(base + OFF_FCH);
    float*  el    = base + OFF_EL;
    float*  er    = base + OFF_ER;
    float*  hg    = base + OFF_HG;
    float*  gcnt  = base + OFF_GCNT;
    int*    deg   = (int*)(base + OFF_DEG);
    int*    rptr  = (int*)(base + OFF_RPTR);
    int*    cur   = (int*)(base + OFF_CUR);
    int*    eidx  = (int*)(base + OFF_EIDX);

    conv_h<<<512, 256>>>(Wmsg, WmH, (size_t)2048 * 512 / 2);
    prep_tT_h<<<768, 256>>>(w_ih, 1536, WihT);
    prep_tT_h<<<768, 256>>>(w_hh, 1536, WhhT);
    prep_tT_h<<<256, 256>>>(fc_w, 512, FcH);
    pad_kernel<<<4096, 256>>>(in_feat, hF, ahH);

    zero_f4<<<32, 256>>>((float4*)deg, NN / 4);
    csr_count<<<(EE + 255) / 256, 256>>>(dst, deg);
    csr_scan<<<1, 1024>>>(deg, rptr, cur);
    csr_scatter<<<(EE + 255) / 256, 256>>>(dst, cur, eidx);

    const int GM = (NN + 127) / 128;  // 157

    for (int step = 0; step < NSTEPS; step++) {
        // fork: Yh = h @ w_hh^T on s2 (depends only on h)
        cudaEventRecord(evFork, 0);
        cudaStreamWaitEvent(s2, evFork, 0);
        gemm_p<<<dim3(GM, 12), 256, SMEM_BYTES, s2>>>(ahH + 512, 1024, WhhT, 1536,
                                                      YhH, 1536, NN, 512);
        cudaEventRecord(evJoin, s2);

        // main stream: aggregate, a-GEMM, Ya
        agg_gather<<<NN, 128>>>(ahH, src, etype, rptr, eidx, bmsg, sH, aF);
        gemm_add<<<dim3(GM, 4), 256, SMEM_BYTES>>>(sH, 2048, WmH, 512, aF, 512, ahH, 1024,
                                                   NN, 2048);
        gemm_p<<<dim3(GM, 12), 256, SMEM_BYTES>>>(ahH, 1024, WihT, 1536, YaH, 1536, NN, 512);

        // join before GRU (needs Yh)
        cudaStreamWaitEvent(0, evJoin, 0);
        gru_kernel<<<4096, 256>>>(YaH, YhH, b_ih, b_hh, hF, ahH);
    }

    norm_sig_kernel<<<NN, 128>>>(hF, ahH);
    gemm_p<<<dim3(GM, 4), 256, SMEM_BYTES>>>(ahH + 512, 1024, FcH, 512, featH, 512, NN, 512);
    elr_kernel<<<NN, 256>>>(featH, attn_l, attn_r, el, er);

    zero_f4<<<32, 256>>>((float4*)hg, ((size_t)GG * 512 + GG) / 4);
    gat_fused<<<NN, 128>>>(src, rptr, eidx, el, er, featH, gid, gat_bias, hg, gcnt);
    final_kernel<<<GG * HEADS, 256>>>(hg, gcnt, cw, cb, out);
}

// round 12
// speedup vs baseline: 7.5178x; 1.0402x over previous
#include <cuda_runtime.h>
#include <cuda_fp16.h>
#include <math.h>
#include <stdint.h>

#define NN 20000
#define EE 320000
#define GG 64
#define INF_ 256
#define H1 512
#define H2C 256
#define HEADS 2
#define CC 16
#define NSTEPS 4
#define KT 4

// ================= scratch layout (float units) =================
constexpr size_t OFF_HF    = 0;                               // NN x 512 f32 (h)
constexpr size_t OFF_AF    = OFF_HF + (size_t)NN * 512;       // NN x 512 f32 (a bias base)
constexpr size_t OFF_YA    = OFF_AF + (size_t)NN * 512;       // NN x 1536 halves
constexpr size_t OFF_YH    = OFF_YA + (size_t)NN * 768;       // NN x 1536 halves
constexpr size_t OFF_FEATH = OFF_YH + (size_t)NN * 768;       // NN x 512 halves
constexpr size_t OFF_AHH   = OFF_FEATH + (size_t)NN * 256;    // NN x 1024 halves ([a|h])
constexpr size_t OFF_SAGH  = OFF_AHH + (size_t)NN * 512;      // NN x 2048 halves
constexpr size_t OFF_WMH   = OFF_SAGH + (size_t)NN * 1024;    // 2048x512 halves
constexpr size_t OFF_WMH0  = OFF_WMH + 524288;                // 1024x512 halves (step-0 rows)
constexpr size_t OFF_WIHT  = OFF_WMH0 + 262144;               // 512x1536 halves
constexpr size_t OFF_WHHT  = OFF_WIHT + 393216;
constexpr size_t OFF_FCH   = OFF_WHHT + 393216;               // 512x512 halves
constexpr size_t OFF_EL    = OFF_FCH + 131072;                // NN x 2
constexpr size_t OFF_ER    = OFF_EL + (size_t)NN * 2;
constexpr size_t OFF_HG    = OFF_ER + (size_t)NN * 2;         // GG x 512
constexpr size_t OFF_GCNT  = OFF_HG + (size_t)GG * 512;       // GG
// int regions
constexpr size_t OFF_DEG   = OFF_GCNT + GG;                   // NN ints
constexpr size_t OFF_RPTR  = OFF_DEG + NN;                    // NN+4 ints
constexpr size_t OFF_CUR   = OFF_RPTR + NN + 4;               // NN ints
constexpr size_t OFF_EIDX  = OFF_CUR + NN;                    // EE ints
constexpr size_t TOTAL_F   = OFF_EIDX + EE + 16;

__device__ __align__(16) float g_buf[TOTAL_F];

// ================= PTX helpers =================
__device__ __forceinline__ uint32_t smem_to_u32(const void* p) {
    uint32_t a;
    asm("{ .reg .u64 t; cvta.to.shared.u64 t, %1; cvt.u32.u64 %0, t; }" : "=r"(a) : "l"(p));
    return a;
}
__device__ __forceinline__ void ldsm_x4(uint32_t addr, uint32_t* r) {
    asm volatile("ldmatrix.sync.aligned.m8n8.x4.shared.b16 {%0,%1,%2,%3}, [%4];"
                 : "=r"(r[0]), "=r"(r[1]), "=r"(r[2]), "=r"(r[3]) : "r"(addr));
}
__device__ __forceinline__ void ldsm_x4_t(uint32_t addr, uint32_t* r) {
    asm volatile("ldmatrix.sync.aligned.m8n8.x4.trans.shared.b16 {%0,%1,%2,%3}, [%4];"
                 : "=r"(r[0]), "=r"(r[1]), "=r"(r[2]), "=r"(r[3]) : "r"(addr));
}
__device__ __forceinline__ void mma_f16(float* c, const uint32_t* a, const uint32_t* b) {
    asm volatile(
        "mma.sync.aligned.m16n8k16.row.col.f32.f16.f16.f32 "
        "{%0,%1,%2,%3},{%4,%5,%6,%7},{%8,%9},{%0,%1,%2,%3};"
        : "+f"(c[0]), "+f"(c[1]), "+f"(c[2]), "+f"(c[3])
        : "r"(a[0]), "r"(a[1]), "r"(a[2]), "r"(a[3]), "r"(b[0]), "r"(b[1]));
}
__device__ __forceinline__ __half2 h2rn(float x0, float x1) {
    return __halves2half2(__float2half_rn(x0), __float2half_rn(x1));
}
__device__ __forceinline__ void cpa16(uint32_t d, const void* g, int sz) {
    asm volatile("cp.async.cg.shared.global [%0], [%1], 16, %2;"
                 :: "r"(d), "l"(g), "r"(sz) : "memory");
}
__device__ __forceinline__ void cpa_commit() {
    asm volatile("cp.async.commit_group;" ::: "memory");
}
template <int N>
__device__ __forceinline__ void cpa_wait() {
    asm volatile("cp.async.wait_group %0;" :: "n"(N) : "memory");
}

// ================= SMEM layout for gemm (half-element offsets) =================
#define AS_PITCH 40
#define BS_PITCH 136
#define SM_AH(b) ((b) * 5120)
#define SM_BH(b) (10240 + (b) * 4352)
#define SMEM_HALFS 18944
#define SMEM_BYTES (SMEM_HALFS * 2)

// ================= pure-fp16 HMMA GEMM core =================
template <int MODE>
__device__ __forceinline__ void gemm_core(
    const __half* __restrict__ A, int lda,
    const __half* __restrict__ B, int ldb,
    const float* __restrict__ Cadd, int ldc,
    __half* __restrict__ Oh, int ldo,
    int M, int K) {
    extern __shared__ __half smh[];
    const uint32_t sbase = smem_to_u32(smh);

    const int tid = threadIdx.x;
    const int lane = tid & 31;
    const int wid = tid >> 5;
    const int wm = wid >> 2;
    const int wn = wid & 3;
    const int blockM = blockIdx.x * 128;
    const int n0 = blockIdx.y * 128;

    const int ar = tid >> 1, ac = (tid & 1) * 16;
    const int bk = tid >> 3, bn = (tid & 7) * 16;
    const bool aval = (blockM + ar) < M;
    const int asz = aval ? 16 : 0;
    const __half* Ap = A + (size_t)(aval ? blockM + ar : 0) * lda + ac;
    const __half* Bp = B + (size_t)bk * ldb + n0 + bn;

    const uint32_t dA = sbase + 2 * (uint32_t)(ar * AS_PITCH + ac);
    const uint32_t dB = sbase + 2 * (uint32_t)(10240 + bk * BS_PITCH + bn);

    const int nC = K >> 5;

    float acc[4][4][4];
#pragma unroll
    for (int mi = 0; mi < 4; mi++)
#pragma unroll
        for (int ni = 0; ni < 4; ni++)
#pragma unroll
            for (int q = 0; q < 4; q++) acc[mi][ni][q] = 0.f;

    auto issue = [&](int c) {
        const int boffA = (c & 1) * 2 * 5120;
        const int boffB = (c & 1) * 2 * 4352;
        const __half* a = Ap + c * 32;
        const __half* b = Bp + (size_t)c * 32 * ldb;
        cpa16(dA + boffA, a, asz);
        cpa16(dA + boffA + 16, a + 8, asz);
        cpa16(dB + boffB, b, 16);
        cpa16(dB + boffB + 16, b + 8, 16);
        cpa_commit();
    };

    issue(0);

    const int lrow = lane & 15;
    const int lhalf = (lane >> 4) * 8;

    for (int c = 0; c < nC; c++) {
        const int b = c & 1;
        if (c + 1 < nC) {
            issue(c + 1);
            cpa_wait<1>();
        } else {
            cpa_wait<0>();
        }
        __syncthreads();

#pragma unroll
        for (int s = 0; s < 2; s++) {
            uint32_t bf[4][2];
#pragma unroll
            for (int np = 0; np < 2; np++) {
                uint32_t off = (uint32_t)((s * 16 + lrow) * BS_PITCH + wn * 32 + np * 16 + lhalf);
                uint32_t t[4];
                ldsm_x4_t(sbase + 2 * (SM_BH(b) + off), t);
                bf[2 * np][0] = t[0]; bf[2 * np][1] = t[1];
                bf[2 * np + 1][0] = t[2]; bf[2 * np + 1][1] = t[3];
            }
#pragma unroll
            for (int mi = 0; mi < 4; mi++) {
                uint32_t off = (uint32_t)((wm * 64 + mi * 16 + lrow) * AS_PITCH + s * 16 + lhalf);
                uint32_t af[4];
                ldsm_x4(sbase + 2 * (SM_AH(b) + off), af);
#pragma unroll
                for (int ni = 0; ni < 4; ni++) mma_f16(acc[mi][ni], af, bf[ni]);
            }
        }
        __syncthreads();
    }

    const int row0 = blockM + wm * 64;
    const int col0 = n0 + wn * 32;
#pragma unroll
    for (int mi = 0; mi < 4; mi++) {
        int r0 = row0 + mi * 16 + (lane >> 2);
        int r1 = r0 + 8;
#pragma unroll
        for (int ni = 0; ni < 4; ni++) {
            int cc = col0 + ni * 8 + (lane & 3) * 2;
#pragma unroll
            for (int h = 0; h < 2; h++) {
                int r = h ? r1 : r0;
                if (r >= M) continue;
                float v0 = acc[mi][ni][2 * h], v1 = acc[mi][ni][2 * h + 1];
                if (MODE == 1) {
                    float2 ci = *(const float2*)(Cadd + (size_t)r * ldc + cc);
                    v0 += ci.x; v1 += ci.y;
                }
                *(__half2*)(Oh + (size_t)r * ldo + cc) = h2rn(v0, v1);
            }
        }
    }
}

__global__ __launch_bounds__(256, 2)
void gemm_add(const __half* __restrict__ A, int lda, const __half* __restrict__ B, int ldb,
              const float* __restrict__ Cadd, int ldc, __half* __restrict__ Oh, int ldo,
              int M, int K) {
    gemm_core<1>(A, lda, B, ldb, Cadd, ldc, Oh, ldo, M, K);
}

__global__ __launch_bounds__(256, 2)
void gemm_p(const __half* __restrict__ A, int lda, const __half* __restrict__ B, int ldb,
            __half* __restrict__ Oh, int ldo, int M, int K) {
    gemm_core<2>(A, lda, B, ldb, nullptr, 0, Oh, ldo, M, K);
}

// ================= misc =================
__device__ __forceinline__ float sigm(float x) { return 1.f / (1.f + expf(-x)); }

__global__ void zero_f4(float4* p, size_t n4) {
    size_t i = (size_t)blockIdx.x * blockDim.x + threadIdx.x;
    size_t st = (size_t)gridDim.x * blockDim.x;
    for (; i < n4; i += st) p[i] = make_float4(0.f, 0.f, 0.f, 0.f);
}

__global__ void conv_h(const float* __restrict__ in, __half* __restrict__ hi, size_t n2) {
    size_t i = (size_t)blockIdx.x * blockDim.x + threadIdx.x;
    size_t st = (size_t)gridDim.x * blockDim.x;
    for (; i < n2; i += st) {
        float2 v = *(const float2*)(in + 2 * i);
        *(__half2*)(hi + 2 * i) = h2rn(v.x, v.y);
    }
}

// WmH0[k*256+c][n] = Wmsg[(k*512+c)*512 + n], c<256 (step-0 nonzero rows)
__global__ void prep_wm0(const float* __restrict__ Wmsg, __half* __restrict__ hi) {
    int i = blockIdx.x * blockDim.x + threadIdx.x;
    int st = gridDim.x * blockDim.x;
    for (; i < 1024 * 256; i += st) {  // 2 cols per iter
        int kp = i >> 8;               // 0..1023
        int n = (i & 255) * 2;
        int k = kp >> 8, c = kp & 255;
        const float* row = Wmsg + ((size_t)(k * 512 + c)) * 512;
        *(__half2*)(hi + (size_t)kp * 512 + n) = h2rn(row[n], row[n + 1]);
    }
}

// T[k][n] fp16 = W[n*512 + k], k in 0..511, n in 0..NROWS-1
__global__ void prep_tT_h(const float* __restrict__ W, int nrows, __half* __restrict__ hi) {
    int i = blockIdx.x * blockDim.x + threadIdx.x;
    int st = gridDim.x * blockDim.x;
    int tot = 512 * (nrows / 2);
    for (; i < tot; i += st) {
        int k = i / (nrows / 2);
        int n = (i % (nrows / 2)) * 2;
        float v0 = W[(size_t)n * 512 + k];
        float v1 = W[(size_t)(n + 1) * 512 + k];
        *(__half2*)(hi + (size_t)k * nrows + n) = h2rn(v0, v1);
    }
}

__global__ void pad_kernel(const float* __restrict__ x, float* __restrict__ hF,
                           __half* __restrict__ ahH) {
    int i = blockIdx.x * blockDim.x + threadIdx.x;
    int st = gridDim.x * blockDim.x;
    int tot = NN * 256;
    for (; i < tot; i += st) {
        int n = i >> 8;
        int c = (i & 255) * 2;
        float v0 = (c < INF_) ? x[(size_t)n * INF_ + c] : 0.f;
        float v1 = (c + 1 < INF_) ? x[(size_t)n * INF_ + c + 1] : 0.f;
        *(float2*)(hF + (size_t)n * 512 + c) = make_float2(v0, v1);
        *(__half2*)(ahH + (size_t)n * 1024 + 512 + c) = h2rn(v0, v1);
    }
}

// ================= CSR build =================
__global__ void csr_count(const int* __restrict__ dst, int* __restrict__ deg) {
    int e = blockIdx.x * blockDim.x + threadIdx.x;
    if (e < EE) atomicAdd(&deg[dst[e]], 1);
}

__global__ void csr_scan(const int* __restrict__ deg, int* __restrict__ rowptr,
                         int* __restrict__ cursor) {
    __shared__ int part[1024];
    int t = threadIdx.x;
    int b = t * 20;
    int loc[20];
    int s = 0;
#pragma unroll
    for (int i = 0; i < 20; i++) {
        int n = b + i;
        loc[i] = (n < NN) ? deg[n] : 0;
        s += loc[i];
    }
    part[t] = s;
    __syncthreads();
    for (int off = 1; off < 1024; off <<= 1) {
        int v = (t >= off) ? part[t - off] : 0;
        __syncthreads();
        part[t] += v;
        __syncthreads();
    }
    int run = part[t] - s;
#pragma unroll
    for (int i = 0; i < 20; i++) {
        int n = b + i;
        if (n < NN) {
            rowptr[n] = run;
            cursor[n] = run;
            run += loc[i];
        }
    }
    if (t == 0) rowptr[NN] = EE;
}

__global__ void csr_scatter(const int* __restrict__ dst, int* __restrict__ cursor,
                            int* __restrict__ eidx) {
    int e = blockIdx.x * blockDim.x + threadIdx.x;
    if (e < EE) {
        int pos = atomicAdd(&cursor[dst[e]], 1);
        eidx[pos] = e;
    }
}

// ================= per-dst aggregate gather + bias fold =================
// COMPACT==0: full 512-col gather -> sH [d][k*512+c] (2048 wide)
// COMPACT==1: step-0, h cols 0..255 only -> sH [d][k*256+c] (1024 wide)
template <int COMPACT>
__device__ __forceinline__ void agg_core(
    const __half* __restrict__ ahH, const int* __restrict__ src,
    const int* __restrict__ et, const int* __restrict__ rowptr,
    const int* __restrict__ eidx, const float* __restrict__ bmsg,
    __half* __restrict__ sH, float* __restrict__ aF) {
    int d = blockIdx.x;
    int t = threadIdx.x;
    int beg = rowptr[d], end = rowptr[d + 1];
    int c = t * 4;
    const bool active = COMPACT ? (c < 256) : true;
    float4 acc[KT];
#pragma unroll
    for (int k = 0; k < KT; k++) acc[k] = make_float4(0.f, 0.f, 0.f, 0.f);
    int cn[KT] = {0, 0, 0, 0};

    __shared__ int ssrc[128];
    __shared__ int sket[128];
    for (int base = beg; base < end; base += 128) {
        int jj = base + t;
        if (jj < end) {
            int e = eidx[jj];
            ssrc[t] = src[e];
            sket[t] = et[e];
        }
        __syncthreads();
        int m = min(128, end - base);
#pragma unroll 2
        for (int q = 0; q < m; q++) {
            int k = sket[q];
#pragma unroll
            for (int kk = 0; kk < KT; kk++)
                if (k == kk) cn[kk]++;
            if (active) {
                int s = ssrc[q];
                uint2 u = *(const uint2*)(ahH + (size_t)s * 1024 + 512 + c);
                float2 f0 = __half22float2(*(__half2*)&u.x);
                float2 f1 = __half22float2(*(__half2*)&u.y);
#pragma unroll
                for (int kk = 0; kk < KT; kk++) {
                    if (k == kk) {
                        acc[kk].x += f0.x; acc[kk].y += f0.y;
                        acc[kk].z += f1.x; acc[kk].w += f1.y;
                    }
                }
            }
        }
        __syncthreads();
    }
    if (active) {
#pragma unroll
        for (int k = 0; k < KT; k++) {
            size_t o = COMPACT ? ((size_t)d * 1024 + k * 256 + c)
                               : ((size_t)d * 2048 + k * 512 + c);
            *(__half2*)(sH + o) = h2rn(acc[k].x, acc[k].y);
            *(__half2*)(sH + o + 2) = h2rn(acc[k].z, acc[k].w);
        }
    }
    float f0 = (float)cn[0], f1 = (float)cn[1], f2 = (float)cn[2], f3 = (float)cn[3];
#pragma unroll
    for (int j = 0; j < 4; j++) {
        float v = f0 * bmsg[c + j] + f1 * bmsg[512 + c + j] +
                  f2 * bmsg[1024 + c + j] + f3 * bmsg[1536 + c + j];
        aF[(size_t)d * 512 + c + j] = v;
    }
}

__global__ __launch_bounds__(128)
void agg_gather(const __half* __restrict__ ahH, const int* __restrict__ src,
                const int* __restrict__ et, const int* __restrict__ rowptr,
                const int* __restrict__ eidx, const float* __restrict__ bmsg,
                __half* __restrict__ sH, float* __restrict__ aF) {
    agg_core<0>(ahH, src, et, rowptr, eidx, bmsg, sH, aF);
}

__global__ __launch_bounds__(128)
void agg_gather0(const __half* __restrict__ ahH, const int* __restrict__ src,
                 const int* __restrict__ et, const int* __restrict__ rowptr,
                 const int* __restrict__ eidx, const float* __restrict__ bmsg,
                 __half* __restrict__ sH, float* __restrict__ aF) {
    agg_core<1>(ahH, src, et, rowptr, eidx, bmsg, sH, aF);
}

// GRU pointwise: reads fp16 Ya/Yh (stride 1536), writes hF fp32 + h fp16
__global__ void gru_kernel(const __half* __restrict__ Ya, const __half* __restrict__ Yh,
                           const float* __restrict__ b_ih, const float* __restrict__ b_hh,
                           float* __restrict__ hF, __half* __restrict__ ahH) {
    int i = blockIdx.x * blockDim.x + threadIdx.x;
    int st = gridDim.x * blockDim.x;
    int tot = NN * 256;
    for (; i < tot; i += st) {
        int n = i >> 8;
        int c = (i & 255) * 2;
        size_t yb = (size_t)n * 1536;
        float2 ir = __half22float2(*(const __half2*)(Ya + yb + c));
        float2 iz = __half22float2(*(const __half2*)(Ya + yb + 512 + c));
        float2 in_ = __half22float2(*(const __half2*)(Ya + yb + 1024 + c));
        float2 hr = __half22float2(*(const __half2*)(Yh + yb + c));
        float2 hz = __half22float2(*(const __half2*)(Yh + yb + 512 + c));
        float2 hn = __half22float2(*(const __half2*)(Yh + yb + 1024 + c));
        float irr[2] = {ir.x, ir.y}, izz[2] = {iz.x, iz.y}, inn[2] = {in_.x, in_.y};
        float hrr[2] = {hr.x, hr.y}, hzz[2] = {hz.x, hz.y}, hnn[2] = {hn.x, hn.y};
        float hv[2];
#pragma unroll
        for (int u = 0; u < 2; u++) {
            int cc = c + u;
            float r = sigm(irr[u] + hrr[u] + b_ih[cc] + b_hh[cc]);
            float z = sigm(izz[u] + hzz[u] + b_ih[512 + cc] + b_hh[512 + cc]);
            float nn = tanhf(inn[u] + b_ih[1024 + cc] + r * (hnn[u] + b_hh[1024 + cc]));
            float ho = hF[(size_t)n * 512 + cc];
            hv[u] = (1.f - z) * nn + z * ho;
        }
        *(float2*)(hF + (size_t)n * 512 + c) = make_float2(hv[0], hv[1]);
        *(__half2*)(ahH + (size_t)n * 1024 + 512 + c) = h2rn(hv[0], hv[1]);
    }
}

// L2-normalize + sigmoid; writes h fp16 only
__global__ void norm_sig_kernel(const float* __restrict__ hF, __half* __restrict__ ahH) {
    int n = blockIdx.x;
    int t = threadIdx.x;  // 128
    const float* row = hF + (size_t)n * 512;
    float4 v = *(const float4*)(row + t * 4);
    float s = v.x * v.x + v.y * v.y + v.z * v.z + v.w * v.w;
    __shared__ float sm[128];
    sm[t] = s;
    __syncthreads();
    for (int o = 64; o > 0; o >>= 1) {
        if (t < o) sm[t] += sm[t + o];
        __syncthreads();
    }
    float inv = 1.f / fmaxf(sqrtf(sm[0]), 1e-12f);
    size_t off = (size_t)n * 1024 + 512 + t * 4;
    *(__half2*)(ahH + off) = h2rn(sigm(v.x * inv), sigm(v.y * inv));
    *(__half2*)(ahH + off + 2) = h2rn(sigm(v.z * inv), sigm(v.w * inv));
}

__global__ void elr_kernel(const __half* __restrict__ featH, const float* __restrict__ attn_l,
                           const float* __restrict__ attn_r,
                           float* __restrict__ el, float* __restrict__ er) {
    int n = blockIdx.x;
    int t = threadIdx.x;  // 256
    float f0 = __half2float(featH[(size_t)n * H1 + t]);
    float f1 = __half2float(featH[(size_t)n * H1 + H2C + t]);
    float vals[4] = {f0 * attn_l[t], f0 * attn_r[t], f1 * attn_l[H2C + t], f1 * attn_r[H2C + t]};
    float outp[4];
    __shared__ float sm[256];
#pragma unroll
    for (int q = 0; q < 4; q++) {
        sm[t] = vals[q];
        __syncthreads();
        for (int o = 128; o > 0; o >>= 1) {
            if (t < o) sm[t] += sm[t + o];
            __syncthreads();
        }
        outp[q] = sm[0];
        __syncthreads();
    }
    if (t == 0) {
        el[n * 2] = outp[0];
        er[n * 2] = outp[1];
        el[n * 2 + 1] = outp[2];
        er[n * 2 + 1] = outp[3];
    }
}

// ================= single-pass fused GAT per-dst =================
__global__ __launch_bounds__(128)
void gat_fused(const int* __restrict__ src, const int* __restrict__ rowptr,
               const int* __restrict__ eidx, const float* __restrict__ el,
               const float* __restrict__ er, const __half* __restrict__ featH,
               const int* __restrict__ gid, const float* __restrict__ gat_bias,
               float* __restrict__ hg, float* __restrict__ gcnt) {
    int d = blockIdx.x;
    int t = threadIdx.x;
    int beg = rowptr[d], end = rowptr[d + 1];
    float er0 = er[2 * d], er1 = er[2 * d + 1];

    __shared__ float sal0[128], sal1[128];
    __shared__ int ssrc[128];
    int c = t * 4;
    bool head0 = c < H2C;
    float4 acc = make_float4(0.f, 0.f, 0.f, 0.f);
    float dsum = 0.f;
    for (int base = beg; base < end; base += 128) {
        int jj = base + t;
        if (jj < end) {
            int s = src[eidx[jj]];
            float v0 = el[2 * s] + er0;      v0 = v0 > 0.f ? v0 : 0.2f * v0;
            float v1 = el[2 * s + 1] + er1;  v1 = v1 > 0.f ? v1 : 0.2f * v1;
            sal0[t] = expf(v0);
            sal1[t] = expf(v1);
            ssrc[t] = s;
        }
        __syncthreads();
        int m = min(128, end - base);
        for (int q = 0; q < m; q++) {
            float w = head0 ? sal0[q] : sal1[q];
            dsum += w;
            uint2 u = *(const uint2*)(featH + (size_t)ssrc[q] * 512 + c);
            float2 f0 = __half22float2(*(__half2*)&u.x);
            float2 f1 = __half22float2(*(__half2*)&u.y);
            acc.x += w * f0.x; acc.y += w * f0.y;
            acc.z += w * f1.x; acc.w += w * f1.y;
        }
        __syncthreads();
    }
    float invd = (dsum > 0.f) ? 1.f / dsum : 0.f;
    float4 b = *(const float4*)(gat_bias + c);
    int g = gid[d];
    atomicAdd(&hg[(size_t)g * 512 + c + 0], fmaxf(acc.x * invd + b.x, 0.f));
    atomicAdd(&hg[(size_t)g * 512 + c + 1], fmaxf(acc.y * invd + b.y, 0.f));
    atomicAdd(&hg[(size_t)g * 512 + c + 2], fmaxf(acc.z * invd + b.z, 0.f));
    atomicAdd(&hg[(size_t)g * 512 + c + 3], fmaxf(acc.w * invd + b.w, 0.f));
    if (t == 0) atomicAdd(&gcnt[g], 1.f);
}

__global__ void final_kernel(const float* __restrict__ hg, const float* __restrict__ gcnt,
                             const float* __restrict__ cw, const float* __restrict__ cb,
                             float* __restrict__ out) {
    int g = blockIdx.x >> 1, hd = blockIdx.x & 1;
    int t = threadIdx.x;  // 256
    __shared__ float row[H2C];
    float inv = 1.f / fmaxf(gcnt[g], 1.f);
    row[t] = hg[(size_t)g * H1 + hd * H2C + t] * inv;
    __syncthreads();
    if (t < CC) {
        float s = cb[t];
        for (int j = 0; j < H2C; j++) s += row[j] * cw[t * H2C + j];
        out[((size_t)g * HEADS + hd) * CC + t] = s;
    }
}

// ================= launch =================
extern "C" void kernel_launch(void* const* d_in, const int* in_sizes, int n_in,
                              void* d_out, int out_size) {
    const float* in_feat  = (const float*)d_in[0];
    const int*   src      = (const int*)d_in[1];
    const int*   dst      = (const int*)d_in[2];
    const int*   etype    = (const int*)d_in[3];
    const int*   gid      = (const int*)d_in[4];
    const float* Wmsg     = (const float*)d_in[5];
    const float* bmsg     = (const float*)d_in[6];
    const float* w_ih     = (const float*)d_in[7];
    const float* w_hh     = (const float*)d_in[8];
    const float* b_ih     = (const float*)d_in[9];
    const float* b_hh     = (const float*)d_in[10];
    const float* fc_w     = (const float*)d_in[11];
    const float* attn_l   = (const float*)d_in[12];
    const float* attn_r   = (const float*)d_in[13];
    const float* gat_bias = (const float*)d_in[14];
    const float* cw       = (const float*)d_in[15];
    const float* cb       = (const float*)d_in[16];
    float* out = (float*)d_out;

    cudaFuncSetAttribute(gemm_add, cudaFuncAttributeMaxDynamicSharedMemorySize, SMEM_BYTES);
    cudaFuncSetAttribute(gemm_p, cudaFuncAttributeMaxDynamicSharedMemorySize, SMEM_BYTES);

    static cudaStream_t s2 = nullptr;
    static cudaEvent_t evFork = nullptr, evJoin = nullptr;
    if (!s2) {
        cudaStreamCreateWithFlags(&s2, cudaStreamNonBlocking);
        cudaEventCreateWithFlags(&evFork, cudaEventDisableTiming);
        cudaEventCreateWithFlags(&evJoin, cudaEventDisableTiming);
    }

    float* base = nullptr;
    cudaGetSymbolAddress((void**)&base, g_buf);

    float*  hF    = base + OFF_HF;
    float*  aF    = base + OFF_AF;
    __half* YaH   = (__half*)(base + OFF_YA);
    __half* YhH   = (__half*)(base + OFF_YH);
    __half* featH = (__half*)(base + OFF_FEATH);
    __half* ahH   = (__half*)(base + OFF_AHH);
    __half* sH    = (__half*)(base + OFF_SAGH);
    __half* WmH   = (__half*)(base + OFF_WMH);
    __half* WmH0  = (__half*)(base + OFF_WMH0);
    __half* WihT  = (__half*)(base + OFF_WIHT);
    __half* WhhT  = (__half*)(base + OFF_WHHT);
    __half* FcH   = (__half*)(base + OFF_FCH);
    float*  el    = base + OFF_EL;
    float*  er    = base + OFF_ER;
    float*  hg    = base + OFF_HG;
    float*  gcnt  = base + OFF_GCNT;
    int*    deg   = (int*)(base + OFF_DEG);
    int*    rptr  = (int*)(base + OFF_RPTR);
    int*    cur   = (int*)(base + OFF_CUR);
    int*    eidx  = (int*)(base + OFF_EIDX);

    conv_h<<<512, 256>>>(Wmsg, WmH, (size_t)2048 * 512 / 2);
    prep_wm0<<<256, 256>>>(Wmsg, WmH0);
    prep_tT_h<<<768, 256>>>(w_ih, 1536, WihT);
    prep_tT_h<<<768, 256>>>(w_hh, 1536, WhhT);
    prep_tT_h<<<256, 256>>>(fc_w, 512, FcH);
    pad_kernel<<<4096, 256>>>(in_feat, hF, ahH);

    zero_f4<<<32, 256>>>((float4*)deg, NN / 4);
    csr_count<<<(EE + 255) / 256, 256>>>(dst, deg);
    csr_scan<<<1, 1024>>>(deg, rptr, cur);
    csr_scatter<<<(EE + 255) / 256, 256>>>(dst, cur, eidx);

    const int GM = (NN + 127) / 128;  // 157

    for (int step = 0; step < NSTEPS; step++) {
        // fork: Yh = h @ w_hh^T on s2 (depends only on h; step 0: h cols 256..511 are zero -> K=256)
        cudaEventRecord(evFork, 0);
        cudaStreamWaitEvent(s2, evFork, 0);
        if (step == 0)
            gemm_p<<<dim3(GM, 12), 256, SMEM_BYTES, s2>>>(ahH + 512, 1024, WhhT, 1536,
                                                          YhH, 1536, NN, 256);
        else
            gemm_p<<<dim3(GM, 12), 256, SMEM_BYTES, s2>>>(ahH + 512, 1024, WhhT, 1536,
                                                          YhH, 1536, NN, 512);
        cudaEventRecord(evJoin, s2);

        // main stream: aggregate, a-GEMM, Ya
        if (step == 0) {
            agg_gather0<<<NN, 128>>>(ahH, src, etype, rptr, eidx, bmsg, sH, aF);
            gemm_add<<<dim3(GM, 4), 256, SMEM_BYTES>>>(sH, 1024, WmH0, 512, aF, 512, ahH, 1024,
                                                       NN, 1024);
        } else {
            agg_gather<<<NN, 128>>>(ahH, src, etype, rptr, eidx, bmsg, sH, aF);
            gemm_add<<<dim3(GM, 4), 256, SMEM_BYTES>>>(sH, 2048, WmH, 512, aF, 512, ahH, 1024,
                                                       NN, 2048);
        }
        gemm_p<<<dim3(GM, 12), 256, SMEM_BYTES>>>(ahH, 1024, WihT, 1536, YaH, 1536, NN, 512);

        // join before GRU (needs Yh)
        cudaStreamWaitEvent(0, evJoin, 0);
        gru_kernel<<<4096, 256>>>(YaH, YhH, b_ih, b_hh, hF, ahH);
    }

    norm_sig_kernel<<<NN, 128>>>(hF, ahH);
    gemm_p<<<dim3(GM, 4), 256, SMEM_BYTES>>>(ahH + 512, 1024, FcH, 512, featH, 512, NN, 512);
    elr_kernel<<<NN, 256>>>(featH, attn_l, attn_r, el, er);

    zero_f4<<<32, 256>>>((float4*)hg, ((size_t)GG * 512 + GG) / 4);
    gat_fused<<<NN, 128>>>(src, rptr, eidx, el, er, featH, gid, gat_bias, hg, gcnt);
    final_kernel<<<GG * HEADS, 256>>>(hg, gcnt, cw, cb, out);
}

// round 15
// speedup vs baseline: 7.7248x; 1.0275x over previous
#include <cuda_runtime.h>
#include <cuda_fp16.h>
#include <math.h>
#include <stdint.h>

#define NN 20000
#define EE 320000
#define GG 64
#define INF_ 256
#define H1 512
#define H2C 256
#define HEADS 2
#define CC 16
#define NSTEPS 4
#define KT 4

// ================= scratch layout (float units) =================
constexpr size_t OFF_AH    = 0;                               // NN x 512 halves (a bias base)
constexpr size_t OFF_PH    = OFF_AH + (size_t)NN * 256;       // NN x 1024 halves (r/z sums)
constexpr size_t OFF_QIH   = OFF_PH + (size_t)NN * 512;       // NN x 512 halves
constexpr size_t OFF_QHH   = OFF_QIH + (size_t)NN * 256;
constexpr size_t OFF_FEATH = OFF_QHH + (size_t)NN * 256;      // NN x 512 halves
constexpr size_t OFF_AHH   = OFF_FEATH + (size_t)NN * 256;    // NN x 1024 halves ([a|h])
constexpr size_t OFF_SAGH  = OFF_AHH + (size_t)NN * 512;      // NN x 2048 halves
constexpr size_t OFF_WMH   = OFF_SAGH + (size_t)NN * 1024;    // 2048x512 halves
constexpr size_t OFF_WMH0  = OFF_WMH + 524288;                // 1024x512 halves (step-0 rows)
constexpr size_t OFF_B1H   = OFF_WMH0 + 262144;               // 1024x1024 halves (rz)
constexpr size_t OFF_WIHTN = OFF_B1H + 524288;                // 512x512 halves (n-gate)
constexpr size_t OFF_WHHTN = OFF_WIHTN + 131072;
constexpr size_t OFF_FCH   = OFF_WHHTN + 131072;              // 512x512 halves
constexpr size_t OFF_EL    = OFF_FCH + 131072;                // NN x 2
constexpr size_t OFF_ER    = OFF_EL + (size_t)NN * 2;
constexpr size_t OFF_HG    = OFF_ER + (size_t)NN * 2;         // GG x 512
constexpr size_t OFF_GCNT  = OFF_HG + (size_t)GG * 512;       // GG
// int regions
constexpr size_t OFF_DEG   = OFF_GCNT + GG;                   // NN ints
constexpr size_t OFF_RPTR  = OFF_DEG + NN;                    // NN+4 ints
constexpr size_t OFF_CUR   = OFF_RPTR + NN + 4;               // NN ints
constexpr size_t OFF_EIDX  = OFF_CUR + NN;                    // EE ints
constexpr size_t TOTAL_F   = OFF_EIDX + EE + 16;

__device__ __align__(16) float g_buf[TOTAL_F];

// ================= PTX helpers =================
__device__ __forceinline__ uint32_t smem_to_u32(const void* p) {
    uint32_t a;
    asm("{ .reg .u64 t; cvta.to.shared.u64 t, %1; cvt.u32.u64 %0, t; }" : "=r"(a) : "l"(p));
    return a;
}
__device__ __forceinline__ void ldsm_x4(uint32_t addr, uint32_t* r) {
    asm volatile("ldmatrix.sync.aligned.m8n8.x4.shared.b16 {%0,%1,%2,%3}, [%4];"
                 : "=r"(r[0]), "=r"(r[1]), "=r"(r[2]), "=r"(r[3]) : "r"(addr));
}
__device__ __forceinline__ void ldsm_x4_t(uint32_t addr, uint32_t* r) {
    asm volatile("ldmatrix.sync.aligned.m8n8.x4.trans.shared.b16 {%0,%1,%2,%3}, [%4];"
                 : "=r"(r[0]), "=r"(r[1]), "=r"(r[2]), "=r"(r[3]) : "r"(addr));
}
__device__ __forceinline__ void mma_f16(float* c, const uint32_t* a, const uint32_t* b) {
    asm volatile(
        "mma.sync.aligned.m16n8k16.row.col.f32.f16.f16.f32 "
        "{%0,%1,%2,%3},{%4,%5,%6,%7},{%8,%9},{%0,%1,%2,%3};"
        : "+f"(c[0]), "+f"(c[1]), "+f"(c[2]), "+f"(c[3])
        : "r"(a[0]), "r"(a[1]), "r"(a[2]), "r"(a[3]), "r"(b[0]), "r"(b[1]));
}
__device__ __forceinline__ __half2 h2rn(float x0, float x1) {
    return __halves2half2(__float2half_rn(x0), __float2half_rn(x1));
}
__device__ __forceinline__ void cpa16(uint32_t d, const void* g, int sz) {
    asm volatile("cp.async.cg.shared.global [%0], [%1], 16, %2;"
                 :: "r"(d), "l"(g), "r"(sz) : "memory");
}
__device__ __forceinline__ void cpa_commit() {
    asm volatile("cp.async.commit_group;" ::: "memory");
}
template <int N>
__device__ __forceinline__ void cpa_wait() {
    asm volatile("cp.async.wait_group %0;" :: "n"(N) : "memory");
}

// ================= SMEM layout for gemm (half-element offsets) =================
#define AS_PITCH 40
#define BS_PITCH 136
#define SM_AH(b) ((b) * 5120)
#define SM_BH(b) (10240 + (b) * 4352)
#define SMEM_HALFS 18944
#define SMEM_BYTES (SMEM_HALFS * 2)

// ================= pure-fp16 HMMA GEMM core =================
// MODE 1: v = half(Cadd) + acc -> Oh fp16 ; MODE 2: Oh = fp16(acc)
template <int MODE>
__device__ __forceinline__ void gemm_core(
    const __half* __restrict__ A, int lda,
    const __half* __restrict__ B, int ldb,
    const __half* __restrict__ Cadd, int ldc,
    __half* __restrict__ Oh, int ldo,
    int M, int K) {
    extern __shared__ __half smh[];
    const uint32_t sbase = smem_to_u32(smh);

    const int tid = threadIdx.x;
    const int lane = tid & 31;
    const int wid = tid >> 5;
    const int wm = wid >> 2;
    const int wn = wid & 3;
    const int blockM = blockIdx.x * 128;
    const int n0 = blockIdx.y * 128;

    const int ar = tid >> 1, ac = (tid & 1) * 16;
    const int bk = tid >> 3, bn = (tid & 7) * 16;
    const bool aval = (blockM + ar) < M;
    const int asz = aval ? 16 : 0;
    const __half* Ap = A + (size_t)(aval ? blockM + ar : 0) * lda + ac;
    const __half* Bp = B + (size_t)bk * ldb + n0 + bn;

    const uint32_t dA = sbase + 2 * (uint32_t)(ar * AS_PITCH + ac);
    const uint32_t dB = sbase + 2 * (uint32_t)(10240 + bk * BS_PITCH + bn);

    const int nC = K >> 5;

    float acc[4][4][4];
#pragma unroll
    for (int mi = 0; mi < 4; mi++)
#pragma unroll
        for (int ni = 0; ni < 4; ni++)
#pragma unroll
            for (int q = 0; q < 4; q++) acc[mi][ni][q] = 0.f;

    auto issue = [&](int c) {
        const int boffA = (c & 1) * 2 * 5120;
        const int boffB = (c & 1) * 2 * 4352;
        const __half* a = Ap + c * 32;
        const __half* b = Bp + (size_t)c * 32 * ldb;
        cpa16(dA + boffA, a, asz);
        cpa16(dA + boffA + 16, a + 8, asz);
        cpa16(dB + boffB, b, 16);
        cpa16(dB + boffB + 16, b + 8, 16);
        cpa_commit();
    };

    issue(0);

    const int lrow = lane & 15;
    const int lhalf = (lane >> 4) * 8;

    for (int c = 0; c < nC; c++) {
        const int b = c & 1;
        if (c + 1 < nC) {
            issue(c + 1);
            cpa_wait<1>();
        } else {
            cpa_wait<0>();
        }
        __syncthreads();

#pragma unroll
        for (int s = 0; s < 2; s++) {
            uint32_t bf[4][2];
#pragma unroll
            for (int np = 0; np < 2; np++) {
                uint32_t off = (uint32_t)((s * 16 + lrow) * BS_PITCH + wn * 32 + np * 16 + lhalf);
                uint32_t t[4];
                ldsm_x4_t(sbase + 2 * (SM_BH(b) + off), t);
                bf[2 * np][0] = t[0]; bf[2 * np][1] = t[1];
                bf[2 * np + 1][0] = t[2]; bf[2 * np + 1][1] = t[3];
            }
#pragma unroll
            for (int mi = 0; mi < 4; mi++) {
                uint32_t off = (uint32_t)((wm * 64 + mi * 16 + lrow) * AS_PITCH + s * 16 + lhalf);
                uint32_t af[4];
                ldsm_x4(sbase + 2 * (SM_AH(b) + off), af);
#pragma unroll
                for (int ni = 0; ni < 4; ni++) mma_f16(acc[mi][ni], af, bf[ni]);
            }
        }
        __syncthreads();
    }

    const int row0 = blockM + wm * 64;
    const int col0 = n0 + wn * 32;
#pragma unroll
    for (int mi = 0; mi < 4; mi++) {
        int r0 = row0 + mi * 16 + (lane >> 2);
        int r1 = r0 + 8;
#pragma unroll
        for (int ni = 0; ni < 4; ni++) {
            int cc = col0 + ni * 8 + (lane & 3) * 2;
#pragma unroll
            for (int h = 0; h < 2; h++) {
                int r = h ? r1 : r0;
                if (r >= M) continue;
                float v0 = acc[mi][ni][2 * h], v1 = acc[mi][ni][2 * h + 1];
                if (MODE == 1) {
                    float2 ci = __half22float2(*(const __half2*)(Cadd + (size_t)r * ldc + cc));
                    v0 += ci.x; v1 += ci.y;
                }
                *(__half2*)(Oh + (size_t)r * ldo + cc) = h2rn(v0, v1);
            }
        }
    }
}

__global__ __launch_bounds__(256, 2)
void gemm_add(const __half* __restrict__ A, int lda, const __half* __restrict__ B, int ldb,
              const __half* __restrict__ Cadd, int ldc, __half* __restrict__ Oh, int ldo,
              int M, int K) {
    gemm_core<1>(A, lda, B, ldb, Cadd, ldc, Oh, ldo, M, K);
}

__global__ __launch_bounds__(256, 2)
void gemm_p(const __half* __restrict__ A, int lda, const __half* __restrict__ B, int ldb,
            __half* __restrict__ Oh, int ldo, int M, int K) {
    gemm_core<2>(A, lda, B, ldb, nullptr, 0, Oh, ldo, M, K);
}

// ================= misc =================
__device__ __forceinline__ float sigm(float x) { return 1.f / (1.f + expf(-x)); }

__global__ void zero_f4(float4* p, size_t n4) {
    size_t i = (size_t)blockIdx.x * blockDim.x + threadIdx.x;
    size_t st = (size_t)gridDim.x * blockDim.x;
    for (; i < n4; i += st) p[i] = make_float4(0.f, 0.f, 0.f, 0.f);
}

__global__ void conv_h(const float* __restrict__ in, __half* __restrict__ hi, size_t n2) {
    size_t i = (size_t)blockIdx.x * blockDim.x + threadIdx.x;
    size_t st = (size_t)gridDim.x * blockDim.x;
    for (; i < n2; i += st) {
        float2 v = *(const float2*)(in + 2 * i);
        *(__half2*)(hi + 2 * i) = h2rn(v.x, v.y);
    }
}

// WmH0[k*256+c][n] = Wmsg[(k*512+c)*512 + n], c<256 (step-0 nonzero rows)
__global__ void prep_wm0(const float* __restrict__ Wmsg, __half* __restrict__ hi) {
    int i = blockIdx.x * blockDim.x + threadIdx.x;
    int st = gridDim.x * blockDim.x;
    for (; i < 1024 * 256; i += st) {
        int kp = i >> 8;
        int n = (i & 255) * 2;
        int k = kp >> 8, c = kp & 255;
        const float* row = Wmsg + ((size_t)(k * 512 + c)) * 512;
        *(__half2*)(hi + (size_t)kp * 512 + n) = h2rn(row[n], row[n + 1]);
    }
}

// B1[k][n] fp16: k<512 -> w_ih[n][k], else w_hh[n][k-512]; n in 0..1023 (r,z rows)
__global__ void prep_b1_h(const float* __restrict__ w_ih, const float* __restrict__ w_hh,
                          __half* __restrict__ hi) {
    int i = blockIdx.x * blockDim.x + threadIdx.x;
    int st = gridDim.x * blockDim.x;
    for (; i < 1024 * 512; i += st) {
        int k = i >> 9;
        int n = (i & 511) * 2;
        float v0 = (k < 512) ? w_ih[(size_t)n * 512 + k] : w_hh[(size_t)n * 512 + k - 512];
        float v1 = (k < 512) ? w_ih[(size_t)(n + 1) * 512 + k] : w_hh[(size_t)(n + 1) * 512 + k - 512];
        *(__half2*)(hi + (size_t)k * 1024 + n) = h2rn(v0, v1);
    }
}

// T[k][n] fp16 = W[(rowoff+n)*512 + k], 512x512
__global__ void prep_t512_h(const float* __restrict__ W, int rowoff, __half* __restrict__ hi) {
    int i = blockIdx.x * blockDim.x + threadIdx.x;
    int st = gridDim.x * blockDim.x;
    for (; i < 512 * 256; i += st) {
        int k = i >> 8;
        int n = (i & 255) * 2;
        float v0 = W[(size_t)(rowoff + n) * 512 + k];
        float v1 = W[(size_t)(rowoff + n + 1) * 512 + k];
        *(__half2*)(hi + (size_t)k * 512 + n) = h2rn(v0, v1);
    }
}

// pad input -> h fp16 (ah cols 512..1023)
__global__ void pad_kernel(const float* __restrict__ x, __half* __restrict__ ahH) {
    int i = blockIdx.x * blockDim.x + threadIdx.x;
    int st = gridDim.x * blockDim.x;
    int tot = NN * 256;
    for (; i < tot; i += st) {
        int n = i >> 8;
        int c = (i & 255) * 2;
        float v0 = (c < INF_) ? x[(size_t)n * INF_ + c] : 0.f;
        float v1 = (c + 1 < INF_) ? x[(size_t)n * INF_ + c + 1] : 0.f;
        *(__half2*)(ahH + (size_t)n * 1024 + 512 + c) = h2rn(v0, v1);
    }
}

// ================= CSR build =================
__global__ void csr_count(const int* __restrict__ dst, int* __restrict__ deg) {
    int e = blockIdx.x * blockDim.x + threadIdx.x;
    if (e < EE) atomicAdd(&deg[dst[e]], 1);
}

__global__ void csr_scan(const int* __restrict__ deg, int* __restrict__ rowptr,
                         int* __restrict__ cursor) {
    __shared__ int part[1024];
    int t = threadIdx.x;
    int b = t * 20;
    int loc[20];
    int s = 0;
#pragma unroll
    for (int i = 0; i < 20; i++) {
        int n = b + i;
        loc[i] = (n < NN) ? deg[n] : 0;
        s += loc[i];
    }
    part[t] = s;
    __syncthreads();
    for (int off = 1; off < 1024; off <<= 1) {
        int v = (t >= off) ? part[t - off] : 0;
        __syncthreads();
        part[t] += v;
        __syncthreads();
    }
    int run = part[t] - s;
#pragma unroll
    for (int i = 0; i < 20; i++) {
        int n = b + i;
        if (n < NN) {
            rowptr[n] = run;
            cursor[n] = run;
            run += loc[i];
        }
    }
    if (t == 0) rowptr[NN] = EE;
}

__global__ void csr_scatter(const int* __restrict__ dst, int* __restrict__ cursor,
                            int* __restrict__ eidx) {
    int e = blockIdx.x * blockDim.x + threadIdx.x;
    if (e < EE) {
        int pos = atomicAdd(&cursor[dst[e]], 1);
        eidx[pos] = e;
    }
}

// ================= per-dst aggregate gather + bias fold (fp16 out) =================
template <int COMPACT>
__device__ __forceinline__ void agg_core(
    const __half* __restrict__ ahH, const int* __restrict__ src,
    const int* __restrict__ et, const int* __restrict__ rowptr,
    const int* __restrict__ eidx, const float* __restrict__ bmsg,
    __half* __restrict__ sH, __half* __restrict__ aH) {
    int d = blockIdx.x;
    int t = threadIdx.x;
    int beg = rowptr[d], end = rowptr[d + 1];
    int c = t * 4;
    const bool active = COMPACT ? (c < 256) : true;
    float4 acc[KT];
#pragma unroll
    for (int k = 0; k < KT; k++) acc[k] = make_float4(0.f, 0.f, 0.f, 0.f);
    int cn[KT] = {0, 0, 0, 0};

    __shared__ int ssrc[128];
    __shared__ int sket[128];
    for (int base = beg; base < end; base += 128) {
        int jj = base + t;
        if (jj < end) {
            int e = eidx[jj];
            ssrc[t] = src[e];
            sket[t] = et[e];
        }
        __syncthreads();
        int m = min(128, end - base);
#pragma unroll 2
        for (int q = 0; q < m; q++) {
            int k = sket[q];
#pragma unroll
            for (int kk = 0; kk < KT; kk++)
                if (k == kk) cn[kk]++;
            if (active) {
                int s = ssrc[q];
                uint2 u = *(const uint2*)(ahH + (size_t)s * 1024 + 512 + c);
                float2 f0 = __half22float2(*(__half2*)&u.x);
                float2 f1 = __half22float2(*(__half2*)&u.y);
#pragma unroll
                for (int kk = 0; kk < KT; kk++) {
                    if (k == kk) {
                        acc[kk].x += f0.x; acc[kk].y += f0.y;
                        acc[kk].z += f1.x; acc[kk].w += f1.y;
                    }
                }
            }
        }
        __syncthreads();
    }
    if (active) {
#pragma unroll
        for (int k = 0; k < KT; k++) {
            size_t o = COMPACT ? ((size_t)d * 1024 + k * 256 + c)
                               : ((size_t)d * 2048 + k * 512 + c);
            *(__half2*)(sH + o) = h2rn(acc[k].x, acc[k].y);
            *(__half2*)(sH + o + 2) = h2rn(acc[k].z, acc[k].w);
        }
    }
    float f0 = (float)cn[0], f1 = (float)cn[1], f2 = (float)cn[2], f3 = (float)cn[3];
    float b0 = f0 * bmsg[c + 0] + f1 * bmsg[512 + c + 0] + f2 * bmsg[1024 + c + 0] + f3 * bmsg[1536 + c + 0];
    float b1 = f0 * bmsg[c + 1] + f1 * bmsg[512 + c + 1] + f2 * bmsg[1024 + c + 1] + f3 * bmsg[1536 + c + 1];
    float b2 = f0 * bmsg[c + 2] + f1 * bmsg[512 + c + 2] + f2 * bmsg[1024 + c + 2] + f3 * bmsg[1536 + c + 2];
    float b3 = f0 * bmsg[c + 3] + f1 * bmsg[512 + c + 3] + f2 * bmsg[1024 + c + 3] + f3 * bmsg[1536 + c + 3];
    *(__half2*)(aH + (size_t)d * 512 + c) = h2rn(b0, b1);
    *(__half2*)(aH + (size_t)d * 512 + c + 2) = h2rn(b2, b3);
}

__global__ __launch_bounds__(128)
void agg_gather(const __half* __restrict__ ahH, const int* __restrict__ src,
                const int* __restrict__ et, const int* __restrict__ rowptr,
                const int* __restrict__ eidx, const float* __restrict__ bmsg,
                __half* __restrict__ sH, __half* __restrict__ aH) {
    agg_core<0>(ahH, src, et, rowptr, eidx, bmsg, sH, aH);
}

__global__ __launch_bounds__(128)
void agg_gather0(const __half* __restrict__ ahH, const int* __restrict__ src,
                 const int* __restrict__ et, const int* __restrict__ rowptr,
                 const int* __restrict__ eidx, const float* __restrict__ bmsg,
                 __half* __restrict__ sH, __half* __restrict__ aH) {
    agg_core<1>(ahH, src, et, rowptr, eidx, bmsg, sH, aH);
}

// GRU pointwise: reads fp16 P (1024), Qi/Qh (512), old h from ahH; writes h fp16
__global__ void gru_kernel(const __half* __restrict__ PH, const __half* __restrict__ QiH,
                           const __half* __restrict__ QhH,
                           const float* __restrict__ b_ih, const float* __restrict__ b_hh,
                           __half* __restrict__ ahH) {
    int i = blockIdx.x * blockDim.x + threadIdx.x;
    int st = gridDim.x * blockDim.x;
    int tot = NN * 256;
    for (; i < tot; i += st) {
        int n = i >> 8;
        int c = (i & 255) * 2;
        float2 pr = __half22float2(*(const __half2*)(PH + (size_t)n * 1024 + c));
        float2 pz = __half22float2(*(const __half2*)(PH + (size_t)n * 1024 + 512 + c));
        float2 qi = __half22float2(*(const __half2*)(QiH + (size_t)n * 512 + c));
        float2 qh = __half22float2(*(const __half2*)(QhH + (size_t)n * 512 + c));
        __half2* hp = (__half2*)(ahH + (size_t)n * 1024 + 512 + c);
        float2 ho = __half22float2(*hp);
        float prr[2] = {pr.x, pr.y}, pzz[2] = {pz.x, pz.y};
        float qii[2] = {qi.x, qi.y}, qhh[2] = {qh.x, qh.y};
        float hoo[2] = {ho.x, ho.y};
        float hv[2];
#pragma unroll
        for (int u = 0; u < 2; u++) {
            int cc = c + u;
            float r = sigm(prr[u] + b_ih[cc] + b_hh[cc]);
            float z = sigm(pzz[u] + b_ih[512 + cc] + b_hh[512 + cc]);
            float nn = tanhf(qii[u] + b_ih[1024 + cc] + r * (qhh[u] + b_hh[1024 + cc]));
            hv[u] = (1.f - z) * nn + z * hoo[u];
        }
        *hp = h2rn(hv[0], hv[1]);
    }
}

// L2-normalize + sigmoid over h fp16 (in place)
__global__ void norm_sig_kernel(__half* __restrict__ ahH) {
    int n = blockIdx.x;
    int t = threadIdx.x;  // 128
    __half2* row = (__half2*)(ahH + (size_t)n * 1024 + 512);
    __half2 a = row[2 * t], b = row[2 * t + 1];
    float2 f0 = __half22float2(a), f1 = __half22float2(b);
    float s = f0.x * f0.x + f0.y * f0.y + f1.x * f1.x + f1.y * f1.y;
    __shared__ float sm[128];
    sm[t] = s;
    __syncthreads();
    for (int o = 64; o > 0; o >>= 1) {
        if (t < o) sm[t] += sm[t + o];
        __syncthreads();
    }
    float inv = 1.f / fmaxf(sqrtf(sm[0]), 1e-12f);
    row[2 * t] = h2rn(sigm(f0.x * inv), sigm(f0.y * inv));
    row[2 * t + 1] = h2rn(sigm(f1.x * inv), sigm(f1.y * inv));
}

__global__ void elr_kernel(const __half* __restrict__ featH, const float* __restrict__ attn_l,
                           const float* __restrict__ attn_r,
                           float* __restrict__ el, float* __restrict__ er) {
    int n = blockIdx.x;
    int t = threadIdx.x;  // 256
    float f0 = __half2float(featH[(size_t)n * H1 + t]);
    float f1 = __half2float(featH[(size_t)n * H1 + H2C + t]);
    float vals[4] = {f0 * attn_l[t], f0 * attn_r[t], f1 * attn_l[H2C + t], f1 * attn_r[H2C + t]};
    float outp[4];
    __shared__ float sm[256];
#pragma unroll
    for (int q = 0; q < 4; q++) {
        sm[t] = vals[q];
        __syncthreads();
        for (int o = 128; o > 0; o >>= 1) {
            if (t < o) sm[t] += sm[t + o];
            __syncthreads();
        }
        outp[q] = sm[0];
        __syncthreads();
    }
    if (t == 0) {
        el[n * 2] = outp[0];
        er[n * 2] = outp[1];
        el[n * 2 + 1] = outp[2];
        er[n * 2 + 1] = outp[3];
    }
}

// ================= single-pass fused GAT per-dst =================
__global__ __launch_bounds__(128)
void gat_fused(const int* __restrict__ src, const int* __restrict__ rowptr,
               const int* __restrict__ eidx, const float* __restrict__ el,
               const float* __restrict__ er, const __half* __restrict__ featH,
               const int* __restrict__ gid, const float* __restrict__ gat_bias,
               float* __restrict__ hg, float* __restrict__ gcnt) {
    int d = blockIdx.x;
    int t = threadIdx.x;
    int beg = rowptr[d], end = rowptr[d + 1];
    float er0 = er[2 * d], er1 = er[2 * d + 1];

    __shared__ float sal0[128], sal1[128];
    __shared__ int ssrc[128];
    int c = t * 4;
    bool head0 = c < H2C;
    float4 acc = make_float4(0.f, 0.f, 0.f, 0.f);
    float dsum = 0.f;
    for (int base = beg; base < end; base += 128) {
        int jj = base + t;
        if (jj < end) {
            int s = src[eidx[jj]];
            float v0 = el[2 * s] + er0;      v0 = v0 > 0.f ? v0 : 0.2f * v0;
            float v1 = el[2 * s + 1] + er1;  v1 = v1 > 0.f ? v1 : 0.2f * v1;
            sal0[t] = expf(v0);
            sal1[t] = expf(v1);
            ssrc[t] = s;
        }
        __syncthreads();
        int m = min(128, end - base);
        for (int q = 0; q < m; q++) {
            float w = head0 ? sal0[q] : sal1[q];
            dsum += w;
            uint2 u = *(const uint2*)(featH + (size_t)ssrc[q] * 512 + c);
            float2 f0 = __half22float2(*(__half2*)&u.x);
            float2 f1 = __half22float2(*(__half2*)&u.y);
            acc.x += w * f0.x; acc.y += w * f0.y;
            acc.z += w * f1.x; acc.w += w * f1.y;
        }
        __syncthreads();
    }
    float invd = (dsum > 0.f) ? 1.f / dsum : 0.f;
    float4 b = *(const float4*)(gat_bias + c);
    int g = gid[d];
    atomicAdd(&hg[(size_t)g * 512 + c + 0], fmaxf(acc.x * invd + b.x, 0.f));
    atomicAdd(&hg[(size_t)g * 512 + c + 1], fmaxf(acc.y * invd + b.y, 0.f));
    atomicAdd(&hg[(size_t)g * 512 + c + 2], fmaxf(acc.z * invd + b.z, 0.f));
    atomicAdd(&hg[(size_t)g * 512 + c + 3], fmaxf(acc.w * invd + b.w, 0.f));
    if (t == 0) atomicAdd(&gcnt[g], 1.f);
}

__global__ void final_kernel(const float* __restrict__ hg, const float* __restrict__ gcnt,
                             const float* __restrict__ cw, const float* __restrict__ cb,
                             float* __restrict__ out) {
    int g = blockIdx.x >> 1, hd = blockIdx.x & 1;
    int t = threadIdx.x;  // 256
    __shared__ float row[H2C];
    float inv = 1.f / fmaxf(gcnt[g], 1.f);
    row[t] = hg[(size_t)g * H1 + hd * H2C + t] * inv;
    __syncthreads();
    if (t < CC) {
        float s = cb[t];
        for (int j = 0; j < H2C; j++) s += row[j] * cw[t * H2C + j];
        out[((size_t)g * HEADS + hd) * CC + t] = s;
    }
}

// ================= launch =================
extern "C" void kernel_launch(void* const* d_in, const int* in_sizes, int n_in,
                              void* d_out, int out_size) {
    const float* in_feat  = (const float*)d_in[0];
    const int*   src      = (const int*)d_in[1];
    const int*   dst      = (const int*)d_in[2];
    const int*   etype    = (const int*)d_in[3];
    const int*   gid      = (const int*)d_in[4];
    const float* Wmsg     = (const float*)d_in[5];
    const float* bmsg     = (const float*)d_in[6];
    const float* w_ih     = (const float*)d_in[7];
    const float* w_hh     = (const float*)d_in[8];
    const float* b_ih     = (const float*)d_in[9];
    const float* b_hh     = (const float*)d_in[10];
    const float* fc_w     = (const float*)d_in[11];
    const float* attn_l   = (const float*)d_in[12];
    const float* attn_r   = (const float*)d_in[13];
    const float* gat_bias = (const float*)d_in[14];
    const float* cw       = (const float*)d_in[15];
    const float* cb       = (const float*)d_in[16];
    float* out = (float*)d_out;

    cudaFuncSetAttribute(gemm_add, cudaFuncAttributeMaxDynamicSharedMemorySize, SMEM_BYTES);
    cudaFuncSetAttribute(gemm_p, cudaFuncAttributeMaxDynamicSharedMemorySize, SMEM_BYTES);

    static cudaStream_t s2 = nullptr;
    static cudaEvent_t evFork = nullptr, evJoin = nullptr;
    if (!s2) {
        cudaStreamCreateWithFlags(&s2, cudaStreamNonBlocking);
        cudaEventCreateWithFlags(&evFork, cudaEventDisableTiming);
        cudaEventCreateWithFlags(&evJoin, cudaEventDisableTiming);
    }

    float* base = nullptr;
    cudaGetSymbolAddress((void**)&base, g_buf);

    __half* aH    = (__half*)(base + OFF_AH);
    __half* PH    = (__half*)(base + OFF_PH);
    __half* QiH   = (__half*)(base + OFF_QIH);
    __half* QhH   = (__half*)(base + OFF_QHH);
    __half* featH = (__half*)(base + OFF_FEATH);
    __half* ahH   = (__half*)(base + OFF_AHH);
    __half* sH    = (__half*)(base + OFF_SAGH);
    __half* WmH   = (__half*)(base + OFF_WMH);
    __half* WmH0  = (__half*)(base + OFF_WMH0);
    __half* B1H   = (__half*)(base + OFF_B1H);
    __half* WihTn = (__half*)(base + OFF_WIHTN);
    __half* WhhTn = (__half*)(base + OFF_WHHTN);
    __half* FcH   = (__half*)(base + OFF_FCH);
    float*  el    = base + OFF_EL;
    float*  er    = base + OFF_ER;
    float*  hg    = base + OFF_HG;
    float*  gcnt  = base + OFF_GCNT;
    int*    deg   = (int*)(base + OFF_DEG);
    int*    rptr  = (int*)(base + OFF_RPTR);
    int*    cur   = (int*)(base + OFF_CUR);
    int*    eidx  = (int*)(base + OFF_EIDX);

    conv_h<<<512, 256>>>(Wmsg, WmH, (size_t)2048 * 512 / 2);
    prep_wm0<<<256, 256>>>(Wmsg, WmH0);
    prep_b1_h<<<512, 256>>>(w_ih, w_hh, B1H);
    prep_t512_h<<<256, 256>>>(w_ih, 1024, WihTn);
    prep_t512_h<<<256, 256>>>(w_hh, 1024, WhhTn);
    prep_t512_h<<<256, 256>>>(fc_w, 0, FcH);
    pad_kernel<<<4096, 256>>>(in_feat, ahH);

    zero_f4<<<32, 256>>>((float4*)deg, NN / 4);
    csr_count<<<(EE + 255) / 256, 256>>>(dst, deg);
    csr_scan<<<1, 1024>>>(deg, rptr, cur);
    csr_scatter<<<(EE + 255) / 256, 256>>>(dst, cur, eidx);

    const int GM = (NN + 127) / 128;  // 157

    for (int step = 0; step < NSTEPS; step++) {
        // fork: Qh = h @ w_hh_n^T (depends on h only; step 0: K=256)
        cudaEventRecord(evFork, 0);
        cudaStreamWaitEvent(s2, evFork, 0);
        gemm_p<<<dim3(GM, 4), 256, SMEM_BYTES, s2>>>(ahH + 512, 1024, WhhTn, 512, QhH, 512,
                                                     NN, step == 0 ? 256 : 512);
        cudaEventRecord(evJoin, s2);

        // main stream: aggregate, a-GEMM, P, Qi
        if (step == 0) {
            agg_gather0<<<NN, 128>>>(ahH, src, etype, rptr, eidx, bmsg, sH, aH);
            gemm_add<<<dim3(GM, 4), 256, SMEM_BYTES>>>(sH, 1024, WmH0, 512, aH, 512, ahH, 1024,
                                                       NN, 1024);
        } else {
            agg_gather<<<NN, 128>>>(ahH, src, etype, rptr, eidx, bmsg, sH, aH);
            gemm_add<<<dim3(GM, 4), 256, SMEM_BYTES>>>(sH, 2048, WmH, 512, aH, 512, ahH, 1024,
                                                       NN, 2048);
        }
        // P = [a|h] @ B1 (r/z gate sums); step 0: h cols 256..511 zero -> K=768
        gemm_p<<<dim3(GM, 8), 256, SMEM_BYTES>>>(ahH, 1024, B1H, 1024, PH, 1024,
                                                 NN, step == 0 ? 768 : 1024);
        // Qi = a @ w_ih_n^T
        gemm_p<<<dim3(GM, 4), 256, SMEM_BYTES>>>(ahH, 1024, WihTn, 512, QiH, 512, NN, 512);

        cudaStreamWaitEvent(0, evJoin, 0);
        gru_kernel<<<4096, 256>>>(PH, QiH, QhH, b_ih, b_hh, ahH);
    }

    norm_sig_kernel<<<NN, 128>>>(ahH);
    gemm_p<<<dim3(GM, 4), 256, SMEM_BYTES>>>(ahH + 512, 1024, FcH, 512, featH, 512, NN, 512);
    elr_kernel<<<NN, 256>>>(featH, attn_l, attn_r, el, er);

    zero_f4<<<32, 256>>>((float4*)hg, ((size_t)GG * 512 + GG) / 4);
    gat_fused<<<NN, 128>>>(src, rptr, eidx, el, er, featH, gid, gat_bias, hg, gcnt);
    final_kernel<<<GG * HEADS, 256>>>(hg, gcnt, cw, cb, out);
}

// round 16
// speedup vs baseline: 7.8364x; 1.0145x over previous
#include <cuda_runtime.h>
#include <cuda_fp16.h>
#include <math.h>
#include <stdint.h>

#define NN 20000
#define EE 320000
#define GG 64
#define INF_ 256
#define H1 512
#define H2C 256
#define HEADS 2
#define CC 16
#define NSTEPS 4
#define KT 4

// ================= scratch layout (float units) =================
constexpr size_t OFF_AH    = 0;                               // NN x 512 halves (a bias base)
constexpr size_t OFF_PH    = OFF_AH + (size_t)NN * 256;       // NN x 1024 halves (r/z sums)
constexpr size_t OFF_QIH   = OFF_PH + (size_t)NN * 512;       // NN x 512 halves
constexpr size_t OFF_QHH   = OFF_QIH + (size_t)NN * 256;
constexpr size_t OFF_FEATH = OFF_QHH + (size_t)NN * 256;      // NN x 512 halves
constexpr size_t OFF_AHH   = OFF_FEATH + (size_t)NN * 256;    // NN x 1024 halves ([a|h])
constexpr size_t OFF_SAGH  = OFF_AHH + (size_t)NN * 512;      // NN x 2048 halves
constexpr size_t OFF_WMH   = OFF_SAGH + (size_t)NN * 1024;    // 2048x512 halves
constexpr size_t OFF_WMH0  = OFF_WMH + 524288;                // 1024x512 halves (step-0 rows)
constexpr size_t OFF_B1H   = OFF_WMH0 + 262144;               // 1024x1024 halves (rz)
constexpr size_t OFF_WIHTN = OFF_B1H + 524288;                // 512x512 halves (n-gate)
constexpr size_t OFF_WHHTN = OFF_WIHTN + 131072;
constexpr size_t OFF_FCH   = OFF_WHHTN + 131072;              // 512x512 halves
constexpr size_t OFF_EL    = OFF_FCH + 131072;                // NN x 2
constexpr size_t OFF_ER    = OFF_EL + (size_t)NN * 2;
constexpr size_t OFF_HG    = OFF_ER + (size_t)NN * 2;         // GG x 512
constexpr size_t OFF_GCNT  = OFF_HG + (size_t)GG * 512;       // GG
// int regions
constexpr size_t OFF_DEG   = OFF_GCNT + GG;                   // NN ints
constexpr size_t OFF_RPTR  = OFF_DEG + NN;                    // NN+4 ints
constexpr size_t OFF_CUR   = OFF_RPTR + NN + 4;               // NN ints
constexpr size_t OFF_EIDX  = OFF_CUR + NN;                    // EE ints
constexpr size_t TOTAL_F   = OFF_EIDX + EE + 16;

__device__ __align__(16) float g_buf[TOTAL_F];

// ================= PTX helpers =================
__device__ __forceinline__ uint32_t smem_to_u32(const void* p) {
    uint32_t a;
    asm("{ .reg .u64 t; cvta.to.shared.u64 t, %1; cvt.u32.u64 %0, t; }" : "=r"(a) : "l"(p));
    return a;
}
__device__ __forceinline__ void ldsm_x4(uint32_t addr, uint32_t* r) {
    asm volatile("ldmatrix.sync.aligned.m8n8.x4.shared.b16 {%0,%1,%2,%3}, [%4];"
                 : "=r"(r[0]), "=r"(r[1]), "=r"(r[2]), "=r"(r[3]) : "r"(addr));
}
__device__ __forceinline__ void ldsm_x4_t(uint32_t addr, uint32_t* r) {
    asm volatile("ldmatrix.sync.aligned.m8n8.x4.trans.shared.b16 {%0,%1,%2,%3}, [%4];"
                 : "=r"(r[0]), "=r"(r[1]), "=r"(r[2]), "=r"(r[3]) : "r"(addr));
}
__device__ __forceinline__ void mma_f16(float* c, const uint32_t* a, const uint32_t* b) {
    asm volatile(
        "mma.sync.aligned.m16n8k16.row.col.f32.f16.f16.f32 "
        "{%0,%1,%2,%3},{%4,%5,%6,%7},{%8,%9},{%0,%1,%2,%3};"
        : "+f"(c[0]), "+f"(c[1]), "+f"(c[2]), "+f"(c[3])
        : "r"(a[0]), "r"(a[1]), "r"(a[2]), "r"(a[3]), "r"(b[0]), "r"(b[1]));
}
__device__ __forceinline__ __half2 h2rn(float x0, float x1) {
    return __halves2half2(__float2half_rn(x0), __float2half_rn(x1));
}
__device__ __forceinline__ void cpa16(uint32_t d, const void* g, int sz) {
    asm volatile("cp.async.cg.shared.global [%0], [%1], 16, %2;"
                 :: "r"(d), "l"(g), "r"(sz) : "memory");
}
__device__ __forceinline__ void cpa_commit() {
    asm volatile("cp.async.commit_group;" ::: "memory");
}
template <int N>
__device__ __forceinline__ void cpa_wait() {
    asm volatile("cp.async.wait_group %0;" :: "n"(N) : "memory");
}

// ================= SMEM layout for gemm (half-element offsets) =================
#define AS_PITCH 40
#define BS_PITCH 136
#define SM_AH(b) ((b) * 5120)
#define SM_BH(b) (10240 + (b) * 4352)
#define SMEM_HALFS 18944
#define SMEM_BYTES (SMEM_HALFS * 2)

// ================= pure-fp16 HMMA GEMM core =================
// MODE 1: v = half(Cadd) + acc -> Oh fp16 ; MODE 2: Oh = fp16(acc)
template <int MODE>
__device__ __forceinline__ void gemm_core(
    const __half* __restrict__ A, int lda,
    const __half* __restrict__ B, int ldb,
    const __half* __restrict__ Cadd, int ldc,
    __half* __restrict__ Oh, int ldo,
    int M, int K, int n0) {
    extern __shared__ __half smh[];
    const uint32_t sbase = smem_to_u32(smh);

    const int tid = threadIdx.x;
    const int lane = tid & 31;
    const int wid = tid >> 5;
    const int wm = wid >> 2;
    const int wn = wid & 3;
    const int blockM = blockIdx.x * 128;

    const int ar = tid >> 1, ac = (tid & 1) * 16;
    const int bk = tid >> 3, bn = (tid & 7) * 16;
    const bool aval = (blockM + ar) < M;
    const int asz = aval ? 16 : 0;
    const __half* Ap = A + (size_t)(aval ? blockM + ar : 0) * lda + ac;
    const __half* Bp = B + (size_t)bk * ldb + n0 + bn;

    const uint32_t dA = sbase + 2 * (uint32_t)(ar * AS_PITCH + ac);
    const uint32_t dB = sbase + 2 * (uint32_t)(10240 + bk * BS_PITCH + bn);

    const int nC = K >> 5;

    float acc[4][4][4];
#pragma unroll
    for (int mi = 0; mi < 4; mi++)
#pragma unroll
        for (int ni = 0; ni < 4; ni++)
#pragma unroll
            for (int q = 0; q < 4; q++) acc[mi][ni][q] = 0.f;

    auto issue = [&](int c) {
        const int boffA = (c & 1) * 2 * 5120;
        const int boffB = (c & 1) * 2 * 4352;
        const __half* a = Ap + c * 32;
        const __half* b = Bp + (size_t)c * 32 * ldb;
        cpa16(dA + boffA, a, asz);
        cpa16(dA + boffA + 16, a + 8, asz);
        cpa16(dB + boffB, b, 16);
        cpa16(dB + boffB + 16, b + 8, 16);
        cpa_commit();
    };

    issue(0);

    const int lrow = lane & 15;
    const int lhalf = (lane >> 4) * 8;

    for (int c = 0; c < nC; c++) {
        const int b = c & 1;
        if (c + 1 < nC) {
            issue(c + 1);
            cpa_wait<1>();
        } else {
            cpa_wait<0>();
        }
        __syncthreads();

#pragma unroll
        for (int s = 0; s < 2; s++) {
            uint32_t bf[4][2];
#pragma unroll
            for (int np = 0; np < 2; np++) {
                uint32_t off = (uint32_t)((s * 16 + lrow) * BS_PITCH + wn * 32 + np * 16 + lhalf);
                uint32_t t[4];
                ldsm_x4_t(sbase + 2 * (SM_BH(b) + off), t);
                bf[2 * np][0] = t[0]; bf[2 * np][1] = t[1];
                bf[2 * np + 1][0] = t[2]; bf[2 * np + 1][1] = t[3];
            }
#pragma unroll
            for (int mi = 0; mi < 4; mi++) {
                uint32_t off = (uint32_t)((wm * 64 + mi * 16 + lrow) * AS_PITCH + s * 16 + lhalf);
                uint32_t af[4];
                ldsm_x4(sbase + 2 * (SM_AH(b) + off), af);
#pragma unroll
                for (int ni = 0; ni < 4; ni++) mma_f16(acc[mi][ni], af, bf[ni]);
            }
        }
        __syncthreads();
    }

    const int row0 = blockM + wm * 64;
    const int col0 = n0 + wn * 32;
#pragma unroll
    for (int mi = 0; mi < 4; mi++) {
        int r0 = row0 + mi * 16 + (lane >> 2);
        int r1 = r0 + 8;
#pragma unroll
        for (int ni = 0; ni < 4; ni++) {
            int cc = col0 + ni * 8 + (lane & 3) * 2;
#pragma unroll
            for (int h = 0; h < 2; h++) {
                int r = h ? r1 : r0;
                if (r >= M) continue;
                float v0 = acc[mi][ni][2 * h], v1 = acc[mi][ni][2 * h + 1];
                if (MODE == 1) {
                    float2 ci = __half22float2(*(const __half2*)(Cadd + (size_t)r * ldc + cc));
                    v0 += ci.x; v1 += ci.y;
                }
                *(__half2*)(Oh + (size_t)r * ldo + cc) = h2rn(v0, v1);
            }
        }
    }
}

__global__ __launch_bounds__(256, 2)
void gemm_add(const __half* __restrict__ A, int lda, const __half* __restrict__ B, int ldb,
              const __half* __restrict__ Cadd, int ldc, __half* __restrict__ Oh, int ldo,
              int M, int K) {
    gemm_core<1>(A, lda, B, ldb, Cadd, ldc, Oh, ldo, M, K, blockIdx.y * 128);
}

__global__ __launch_bounds__(256, 2)
void gemm_p(const __half* __restrict__ A, int lda, const __half* __restrict__ B, int ldb,
            __half* __restrict__ Oh, int ldo, int M, int K) {
    gemm_core<2>(A, lda, B, ldb, nullptr, 0, Oh, ldo, M, K, blockIdx.y * 128);
}

// merged P (y<8) + Qi (y>=8) launch; Kp = K for P (768 at step 0, else 1024)
__global__ __launch_bounds__(256, 2)
void gemm_pq(const __half* __restrict__ ahH, const __half* __restrict__ B1H,
             const __half* __restrict__ WihTn, __half* __restrict__ PH,
             __half* __restrict__ QiH, int M, int Kp) {
    if (blockIdx.y < 8) {
        gemm_core<2>(ahH, 1024, B1H, 1024, nullptr, 0, PH, 1024, M, Kp, blockIdx.y * 128);
    } else {
        gemm_core<2>(ahH, 1024, WihTn, 512, nullptr, 0, QiH, 512, M, 512,
                     (blockIdx.y - 8) * 128);
    }
}

// ================= misc =================
__device__ __forceinline__ float sigm(float x) { return 1.f / (1.f + expf(-x)); }

__global__ void zero_f4(float4* p, size_t n4) {
    size_t i = (size_t)blockIdx.x * blockDim.x + threadIdx.x;
    size_t st = (size_t)gridDim.x * blockDim.x;
    for (; i < n4; i += st) p[i] = make_float4(0.f, 0.f, 0.f, 0.f);
}

__global__ void conv_h(const float* __restrict__ in, __half* __restrict__ hi, size_t n2) {
    size_t i = (size_t)blockIdx.x * blockDim.x + threadIdx.x;
    size_t st = (size_t)gridDim.x * blockDim.x;
    for (; i < n2; i += st) {
        float2 v = *(const float2*)(in + 2 * i);
        *(__half2*)(hi + 2 * i) = h2rn(v.x, v.y);
    }
}

// WmH0[k*256+c][n] = Wmsg[(k*512+c)*512 + n], c<256 (step-0 nonzero rows)
__global__ void prep_wm0(const float* __restrict__ Wmsg, __half* __restrict__ hi) {
    int i = blockIdx.x * blockDim.x + threadIdx.x;
    int st = gridDim.x * blockDim.x;
    for (; i < 1024 * 256; i += st) {
        int kp = i >> 8;
        int n = (i & 255) * 2;
        int k = kp >> 8, c = kp & 255;
        const float* row = Wmsg + ((size_t)(k * 512 + c)) * 512;
        *(__half2*)(hi + (size_t)kp * 512 + n) = h2rn(row[n], row[n + 1]);
    }
}

// B1[k][n] fp16: k<512 -> w_ih[n][k], else w_hh[n][k-512]; n in 0..1023 (r,z rows)
__global__ void prep_b1_h(const float* __restrict__ w_ih, const float* __restrict__ w_hh,
                          __half* __restrict__ hi) {
    int i = blockIdx.x * blockDim.x + threadIdx.x;
    int st = gridDim.x * blockDim.x;
    for (; i < 1024 * 512; i += st) {
        int k = i >> 9;
        int n = (i & 511) * 2;
        float v0 = (k < 512) ? w_ih[(size_t)n * 512 + k] : w_hh[(size_t)n * 512 + k - 512];
        float v1 = (k < 512) ? w_ih[(size_t)(n + 1) * 512 + k] : w_hh[(size_t)(n + 1) * 512 + k - 512];
        *(__half2*)(hi + (size_t)k * 1024 + n) = h2rn(v0, v1);
    }
}

// T[k][n] fp16 = W[(rowoff+n)*512 + k], 512x512
__global__ void prep_t512_h(const float* __restrict__ W, int rowoff, __half* __restrict__ hi) {
    int i = blockIdx.x * blockDim.x + threadIdx.x;
    int st = gridDim.x * blockDim.x;
    for (; i < 512 * 256; i += st) {
        int k = i >> 8;
        int n = (i & 255) * 2;
        float v0 = W[(size_t)(rowoff + n) * 512 + k];
        float v1 = W[(size_t)(rowoff + n + 1) * 512 + k];
        *(__half2*)(hi + (size_t)k * 512 + n) = h2rn(v0, v1);
    }
}

// pad input -> h fp16 (ah cols 512..1023)
__global__ void pad_kernel(const float* __restrict__ x, __half* __restrict__ ahH) {
    int i = blockIdx.x * blockDim.x + threadIdx.x;
    int st = gridDim.x * blockDim.x;
    int tot = NN * 256;
    for (; i < tot; i += st) {
        int n = i >> 8;
        int c = (i & 255) * 2;
        float v0 = (c < INF_) ? x[(size_t)n * INF_ + c] : 0.f;
        float v1 = (c + 1 < INF_) ? x[(size_t)n * INF_ + c + 1] : 0.f;
        *(__half2*)(ahH + (size_t)n * 1024 + 512 + c) = h2rn(v0, v1);
    }
}

// ================= CSR build =================
__global__ void csr_count(const int* __restrict__ dst, int* __restrict__ deg) {
    int e = blockIdx.x * blockDim.x + threadIdx.x;
    if (e < EE) atomicAdd(&deg[dst[e]], 1);
}

__global__ void csr_scan(const int* __restrict__ deg, int* __restrict__ rowptr,
                         int* __restrict__ cursor) {
    __shared__ int part[1024];
    int t = threadIdx.x;
    int b = t * 20;
    int loc[20];
    int s = 0;
#pragma unroll
    for (int i = 0; i < 20; i++) {
        int n = b + i;
        loc[i] = (n < NN) ? deg[n] : 0;
        s += loc[i];
    }
    part[t] = s;
    __syncthreads();
    for (int off = 1; off < 1024; off <<= 1) {
        int v = (t >= off) ? part[t - off] : 0;
        __syncthreads();
        part[t] += v;
        __syncthreads();
    }
    int run = part[t] - s;
#pragma unroll
    for (int i = 0; i < 20; i++) {
        int n = b + i;
        if (n < NN) {
            rowptr[n] = run;
            cursor[n] = run;
            run += loc[i];
        }
    }
    if (t == 0) rowptr[NN] = EE;
}

__global__ void csr_scatter(const int* __restrict__ dst, int* __restrict__ cursor,
                            int* __restrict__ eidx) {
    int e = blockIdx.x * blockDim.x + threadIdx.x;
    if (e < EE) {
        int pos = atomicAdd(&cursor[dst[e]], 1);
        eidx[pos] = e;
    }
}

// ================= per-dst aggregate gather + bias fold (fp16 out) =================
template <int COMPACT>
__device__ __forceinline__ void agg_core(
    const __half* __restrict__ ahH, const int* __restrict__ src,
    const int* __restrict__ et, const int* __restrict__ rowptr,
    const int* __restrict__ eidx, const float* __restrict__ bmsg,
    __half* __restrict__ sH, __half* __restrict__ aH) {
    int d = blockIdx.x;
    int t = threadIdx.x;
    int beg = rowptr[d], end = rowptr[d + 1];
    int c = t * 4;
    const bool active = COMPACT ? (c < 256) : true;
    float4 acc[KT];
#pragma unroll
    for (int k = 0; k < KT; k++) acc[k] = make_float4(0.f, 0.f, 0.f, 0.f);
    int cn[KT] = {0, 0, 0, 0};

    __shared__ int ssrc[128];
    __shared__ int sket[128];
    for (int base = beg; base < end; base += 128) {
        int jj = base + t;
        if (jj < end) {
            int e = eidx[jj];
            ssrc[t] = src[e];
            sket[t] = et[e];
        }
        __syncthreads();
        int m = min(128, end - base);
#pragma unroll 2
        for (int q = 0; q < m; q++) {
            int k = sket[q];
#pragma unroll
            for (int kk = 0; kk < KT; kk++)
                if (k == kk) cn[kk]++;
            if (active) {
                int s = ssrc[q];
                uint2 u = *(const uint2*)(ahH + (size_t)s * 1024 + 512 + c);
                float2 f0 = __half22float2(*(__half2*)&u.x);
                float2 f1 = __half22float2(*(__half2*)&u.y);
#pragma unroll
                for (int kk = 0; kk < KT; kk++) {
                    if (k == kk) {
                        acc[kk].x += f0.x; acc[kk].y += f0.y;
                        acc[kk].z += f1.x; acc[kk].w += f1.y;
                    }
                }
            }
        }
        __syncthreads();
    }
    if (active) {
#pragma unroll
        for (int k = 0; k < KT; k++) {
            size_t o = COMPACT ? ((size_t)d * 1024 + k * 256 + c)
                               : ((size_t)d * 2048 + k * 512 + c);
            *(__half2*)(sH + o) = h2rn(acc[k].x, acc[k].y);
            *(__half2*)(sH + o + 2) = h2rn(acc[k].z, acc[k].w);
        }
    }
    float f0 = (float)cn[0], f1 = (float)cn[1], f2 = (float)cn[2], f3 = (float)cn[3];
    float b0 = f0 * bmsg[c + 0] + f1 * bmsg[512 + c + 0] + f2 * bmsg[1024 + c + 0] + f3 * bmsg[1536 + c + 0];
    float b1 = f0 * bmsg[c + 1] + f1 * bmsg[512 + c + 1] + f2 * bmsg[1024 + c + 1] + f3 * bmsg[1536 + c + 1];
    float b2 = f0 * bmsg[c + 2] + f1 * bmsg[512 + c + 2] + f2 * bmsg[1024 + c + 2] + f3 * bmsg[1536 + c + 2];
    float b3 = f0 * bmsg[c + 3] + f1 * bmsg[512 + c + 3] + f2 * bmsg[1024 + c + 3] + f3 * bmsg[1536 + c + 3];
    *(__half2*)(aH + (size_t)d * 512 + c) = h2rn(b0, b1);
    *(__half2*)(aH + (size_t)d * 512 + c + 2) = h2rn(b2, b3);
}

__global__ __launch_bounds__(128)
void agg_gather(const __half* __restrict__ ahH, const int* __restrict__ src,
                const int* __restrict__ et, const int* __restrict__ rowptr,
                const int* __restrict__ eidx, const float* __restrict__ bmsg,
                __half* __restrict__ sH, __half* __restrict__ aH) {
    agg_core<0>(ahH, src, et, rowptr, eidx, bmsg, sH, aH);
}

__global__ __launch_bounds__(128)
void agg_gather0(const __half* __restrict__ ahH, const int* __restrict__ src,
                 const int* __restrict__ et, const int* __restrict__ rowptr,
                 const int* __restrict__ eidx, const float* __restrict__ bmsg,
                 __half* __restrict__ sH, __half* __restrict__ aH) {
    agg_core<1>(ahH, src, et, rowptr, eidx, bmsg, sH, aH);
}

// GRU pointwise: reads fp16 P (1024), Qi/Qh (512), old h from ahH; writes h fp16
__global__ void gru_kernel(const __half* __restrict__ PH, const __half* __restrict__ QiH,
                           const __half* __restrict__ QhH,
                           const float* __restrict__ b_ih, const float* __restrict__ b_hh,
                           __half* __restrict__ ahH) {
    int i = blockIdx.x * blockDim.x + threadIdx.x;
    int st = gridDim.x * blockDim.x;
    int tot = NN * 256;
    for (; i < tot; i += st) {
        int n = i >> 8;
        int c = (i & 255) * 2;
        float2 pr = __half22float2(*(const __half2*)(PH + (size_t)n * 1024 + c));
        float2 pz = __half22float2(*(const __half2*)(PH + (size_t)n * 1024 + 512 + c));
        float2 qi = __half22float2(*(const __half2*)(QiH + (size_t)n * 512 + c));
        float2 qh = __half22float2(*(const __half2*)(QhH + (size_t)n * 512 + c));
        __half2* hp = (__half2*)(ahH + (size_t)n * 1024 + 512 + c);
        float2 ho = __half22float2(*hp);
        float prr[2] = {pr.x, pr.y}, pzz[2] = {pz.x, pz.y};
        float qii[2] = {qi.x, qi.y}, qhh[2] = {qh.x, qh.y};
        float hoo[2] = {ho.x, ho.y};
        float hv[2];
#pragma unroll
        for (int u = 0; u < 2; u++) {
            int cc = c + u;
            float r = sigm(prr[u] + b_ih[cc] + b_hh[cc]);
            float z = sigm(pzz[u] + b_ih[512 + cc] + b_hh[512 + cc]);
            float nn = tanhf(qii[u] + b_ih[1024 + cc] + r * (qhh[u] + b_hh[1024 + cc]));
            hv[u] = (1.f - z) * nn + z * hoo[u];
        }
        *hp = h2rn(hv[0], hv[1]);
    }
}

// L2-normalize + sigmoid over h fp16 (in place)
__global__ void norm_sig_kernel(__half* __restrict__ ahH) {
    int n = blockIdx.x;
    int t = threadIdx.x;  // 128
    __half2* row = (__half2*)(ahH + (size_t)n * 1024 + 512);
    __half2 a = row[2 * t], b = row[2 * t + 1];
    float2 f0 = __half22float2(a), f1 = __half22float2(b);
    float s = f0.x * f0.x + f0.y * f0.y + f1.x * f1.x + f1.y * f1.y;
    __shared__ float sm[128];
    sm[t] = s;
    __syncthreads();
    for (int o = 64; o > 0; o >>= 1) {
        if (t < o) sm[t] += sm[t + o];
        __syncthreads();
    }
    float inv = 1.f / fmaxf(sqrtf(sm[0]), 1e-12f);
    row[2 * t] = h2rn(sigm(f0.x * inv), sigm(f0.y * inv));
    row[2 * t + 1] = h2rn(sigm(f1.x * inv), sigm(f1.y * inv));
}

__global__ void elr_kernel(const __half* __restrict__ featH, const float* __restrict__ attn_l,
                           const float* __restrict__ attn_r,
                           float* __restrict__ el, float* __restrict__ er) {
    int n = blockIdx.x;
    int t = threadIdx.x;  // 256
    float f0 = __half2float(featH[(size_t)n * H1 + t]);
    float f1 = __half2float(featH[(size_t)n * H1 + H2C + t]);
    float vals[4] = {f0 * attn_l[t], f0 * attn_r[t], f1 * attn_l[H2C + t], f1 * attn_r[H2C + t]};
    float outp[4];
    __shared__ float sm[256];
#pragma unroll
    for (int q = 0; q < 4; q++) {
        sm[t] = vals[q];
        __syncthreads();
        for (int o = 128; o > 0; o >>= 1) {
            if (t < o) sm[t] += sm[t + o];
            __syncthreads();
        }
        outp[q] = sm[0];
        __syncthreads();
    }
    if (t == 0) {
        el[n * 2] = outp[0];
        er[n * 2] = outp[1];
        el[n * 2 + 1] = outp[2];
        er[n * 2 + 1] = outp[3];
    }
}

// ================= single-pass fused GAT per-dst =================
__global__ __launch_bounds__(128)
void gat_fused(const int* __restrict__ src, const int* __restrict__ rowptr,
               const int* __restrict__ eidx, const float* __restrict__ el,
               const float* __restrict__ er, const __half* __restrict__ featH,
               const int* __restrict__ gid, const float* __restrict__ gat_bias,
               float* __restrict__ hg, float* __restrict__ gcnt) {
    int d = blockIdx.x;
    int t = threadIdx.x;
    int beg = rowptr[d], end = rowptr[d + 1];
    float er0 = er[2 * d], er1 = er[2 * d + 1];

    __shared__ float sal0[128], sal1[128];
    __shared__ int ssrc[128];
    int c = t * 4;
    bool head0 = c < H2C;
    float4 acc = make_float4(0.f, 0.f, 0.f, 0.f);
    float dsum = 0.f;
    for (int base = beg; base < end; base += 128) {
        int jj = base + t;
        if (jj < end) {
            int s = src[eidx[jj]];
            float v0 = el[2 * s] + er0;      v0 = v0 > 0.f ? v0 : 0.2f * v0;
            float v1 = el[2 * s + 1] + er1;  v1 = v1 > 0.f ? v1 : 0.2f * v1;
            sal0[t] = expf(v0);
            sal1[t] = expf(v1);
            ssrc[t] = s;
        }
        __syncthreads();
        int m = min(128, end - base);
        for (int q = 0; q < m; q++) {
            float w = head0 ? sal0[q] : sal1[q];
            dsum += w;
            uint2 u = *(const uint2*)(featH + (size_t)ssrc[q] * 512 + c);
            float2 f0 = __half22float2(*(__half2*)&u.x);
            float2 f1 = __half22float2(*(__half2*)&u.y);
            acc.x += w * f0.x; acc.y += w * f0.y;
            acc.z += w * f1.x; acc.w += w * f1.y;
        }
        __syncthreads();
    }
    float invd = (dsum > 0.f) ? 1.f / dsum : 0.f;
    float4 b = *(const float4*)(gat_bias + c);
    int g = gid[d];
    atomicAdd(&hg[(size_t)g * 512 + c + 0], fmaxf(acc.x * invd + b.x, 0.f));
    atomicAdd(&hg[(size_t)g * 512 + c + 1], fmaxf(acc.y * invd + b.y, 0.f));
    atomicAdd(&hg[(size_t)g * 512 + c + 2], fmaxf(acc.z * invd + b.z, 0.f));
    atomicAdd(&hg[(size_t)g * 512 + c + 3], fmaxf(acc.w * invd + b.w, 0.f));
    if (t == 0) atomicAdd(&gcnt[g], 1.f);
}

__global__ void final_kernel(const float* __restrict__ hg, const float* __restrict__ gcnt,
                             const float* __restrict__ cw, const float* __restrict__ cb,
                             float* __restrict__ out) {
    int g = blockIdx.x >> 1, hd = blockIdx.x & 1;
    int t = threadIdx.x;  // 256
    __shared__ float row[H2C];
    float inv = 1.f / fmaxf(gcnt[g], 1.f);
    row[t] = hg[(size_t)g * H1 + hd * H2C + t] * inv;
    __syncthreads();
    if (t < CC) {
        float s = cb[t];
        for (int j = 0; j < H2C; j++) s += row[j] * cw[t * H2C + j];
        out[((size_t)g * HEADS + hd) * CC + t] = s;
    }
}

// ================= launch =================
extern "C" void kernel_launch(void* const* d_in, const int* in_sizes, int n_in,
                              void* d_out, int out_size) {
    const float* in_feat  = (const float*)d_in[0];
    const int*   src      = (const int*)d_in[1];
    const int*   dst      = (const int*)d_in[2];
    const int*   etype    = (const int*)d_in[3];
    const int*   gid      = (const int*)d_in[4];
    const float* Wmsg     = (const float*)d_in[5];
    const float* bmsg     = (const float*)d_in[6];
    const float* w_ih     = (const float*)d_in[7];
    const float* w_hh     = (const float*)d_in[8];
    const float* b_ih     = (const float*)d_in[9];
    const float* b_hh     = (const float*)d_in[10];
    const float* fc_w     = (const float*)d_in[11];
    const float* attn_l   = (const float*)d_in[12];
    const float* attn_r   = (const float*)d_in[13];
    const float* gat_bias = (const float*)d_in[14];
    const float* cw       = (const float*)d_in[15];
    const float* cb       = (const float*)d_in[16];
    float* out = (float*)d_out;

    cudaFuncSetAttribute(gemm_add, cudaFuncAttributeMaxDynamicSharedMemorySize, SMEM_BYTES);
    cudaFuncSetAttribute(gemm_p, cudaFuncAttributeMaxDynamicSharedMemorySize, SMEM_BYTES);
    cudaFuncSetAttribute(gemm_pq, cudaFuncAttributeMaxDynamicSharedMemorySize, SMEM_BYTES);

    static cudaStream_t s2 = nullptr;
    static cudaEvent_t evFork = nullptr, evJoin = nullptr;
    if (!s2) {
        cudaStreamCreateWithFlags(&s2, cudaStreamNonBlocking);
        cudaEventCreateWithFlags(&evFork, cudaEventDisableTiming);
        cudaEventCreateWithFlags(&evJoin, cudaEventDisableTiming);
    }

    float* base = nullptr;
    cudaGetSymbolAddress((void**)&base, g_buf);

    __half* aH    = (__half*)(base + OFF_AH);
    __half* PH    = (__half*)(base + OFF_PH);
    __half* QiH   = (__half*)(base + OFF_QIH);
    __half* QhH   = (__half*)(base + OFF_QHH);
    __half* featH = (__half*)(base + OFF_FEATH);
    __half* ahH   = (__half*)(base + OFF_AHH);
    __half* sH    = (__half*)(base + OFF_SAGH);
    __half* WmH   = (__half*)(base + OFF_WMH);
    __half* WmH0  = (__half*)(base + OFF_WMH0);
    __half* B1H   = (__half*)(base + OFF_B1H);
    __half* WihTn = (__half*)(base + OFF_WIHTN);
    __half* WhhTn = (__half*)(base + OFF_WHHTN);
    __half* FcH   = (__half*)(base + OFF_FCH);
    float*  el    = base + OFF_EL;
    float*  er    = base + OFF_ER;
    float*  hg    = base + OFF_HG;
    float*  gcnt  = base + OFF_GCNT;
    int*    deg   = (int*)(base + OFF_DEG);
    int*    rptr  = (int*)(base + OFF_RPTR);
    int*    cur   = (int*)(base + OFF_CUR);
    int*    eidx  = (int*)(base + OFF_EIDX);

    conv_h<<<512, 256>>>(Wmsg, WmH, (size_t)2048 * 512 / 2);
    prep_wm0<<<256, 256>>>(Wmsg, WmH0);
    prep_b1_h<<<512, 256>>>(w_ih, w_hh, B1H);
    prep_t512_h<<<256, 256>>>(w_ih, 1024, WihTn);
    prep_t512_h<<<256, 256>>>(w_hh, 1024, WhhTn);
    prep_t512_h<<<256, 256>>>(fc_w, 0, FcH);
    pad_kernel<<<4096, 256>>>(in_feat, ahH);

    zero_f4<<<32, 256>>>((float4*)deg, NN / 4);
    csr_count<<<(EE + 255) / 256, 256>>>(dst, deg);
    csr_scan<<<1, 1024>>>(deg, rptr, cur);
    csr_scatter<<<(EE + 255) / 256, 256>>>(dst, cur, eidx);

    const int GM = (NN + 127) / 128;  // 157

    for (int step = 0; step < NSTEPS; step++) {
        // fork: Qh = h @ w_hh_n^T (depends on h only; step 0: K=256)
        cudaEventRecord(evFork, 0);
        cudaStreamWaitEvent(s2, evFork, 0);
        gemm_p<<<dim3(GM, 4), 256, SMEM_BYTES, s2>>>(ahH + 512, 1024, WhhTn, 512, QhH, 512,
                                                     NN, step == 0 ? 256 : 512);
        cudaEventRecord(evJoin, s2);

        // main stream: aggregate, a-GEMM, merged P+Qi
        if (step == 0) {
            agg_gather0<<<NN, 128>>>(ahH, src, etype, rptr, eidx, bmsg, sH, aH);
            gemm_add<<<dim3(GM, 4), 256, SMEM_BYTES>>>(sH, 1024, WmH0, 512, aH, 512, ahH, 1024,
                                                       NN, 1024);
        } else {
            agg_gather<<<NN, 128>>>(ahH, src, etype, rptr, eidx, bmsg, sH, aH);
            gemm_add<<<dim3(GM, 4), 256, SMEM_BYTES>>>(sH, 2048, WmH, 512, aH, 512, ahH, 1024,
                                                       NN, 2048);
        }
        // merged: P (y<8, K=768/1024) + Qi (y>=8, K=512) in one launch
        gemm_pq<<<dim3(GM, 12), 256, SMEM_BYTES>>>(ahH, B1H, WihTn, PH, QiH, NN,
                                                   step == 0 ? 768 : 1024);

        cudaStreamWaitEvent(0, evJoin, 0);
        gru_kernel<<<4096, 256>>>(PH, QiH, QhH, b_ih, b_hh, ahH);
    }

    norm_sig_kernel<<<NN, 128>>>(ahH);
    gemm_p<<<dim3(GM, 4), 256, SMEM_BYTES>>>(ahH + 512, 1024, FcH, 512, featH, 512, NN, 512);
    elr_kernel<<<NN, 256>>>(featH, attn_l, attn_r, el, er);

    zero_f4<<<32, 256>>>((float4*)hg, ((size_t)GG * 512 + GG) / 4);
    gat_fused<<<NN, 128>>>(src, rptr, eidx, el, er, featH, gid, gat_bias, hg, gcnt);
    final_kernel<<<GG * HEADS, 256>>>(hg, gcnt, cw, cb, out);
}

// round 17
// speedup vs baseline: 8.3339x; 1.0635x over previous
#include <cuda_runtime.h>
#include <cuda_fp16.h>
#include <math.h>
#include <stdint.h>

#define NN 20000
#define EE 320000
#define GG 64
#define INF_ 256
#define H1 512
#define H2C 256
#define HEADS 2
#define CC 16
#define NSTEPS 4
#define KT 4

// ================= scratch layout (float units) =================
constexpr size_t OFF_AH    = 0;                               // NN x 512 halves (a bias base)
constexpr size_t OFF_PH    = OFF_AH + (size_t)NN * 256;       // NN x 1024 halves (r/z sums)
constexpr size_t OFF_QIH   = OFF_PH + (size_t)NN * 512;       // NN x 512 halves
constexpr size_t OFF_QHH   = OFF_QIH + (size_t)NN * 256;
constexpr size_t OFF_FEATH = OFF_QHH + (size_t)NN * 256;      // NN x 512 halves
constexpr size_t OFF_AHH   = OFF_FEATH + (size_t)NN * 256;    // NN x 1024 halves ([a|h])
constexpr size_t OFF_SAGH  = OFF_AHH + (size_t)NN * 512;      // NN x 2048 halves
constexpr size_t OFF_WMH   = OFF_SAGH + (size_t)NN * 1024;    // 2048x512 halves
constexpr size_t OFF_WMH0  = OFF_WMH + 524288;                // 1024x512 halves (step-0 rows)
constexpr size_t OFF_B1H   = OFF_WMH0 + 262144;               // 1024x1024 halves (rz)
constexpr size_t OFF_WIHTN = OFF_B1H + 524288;                // 512x512 halves (n-gate)
constexpr size_t OFF_WHHTN = OFF_WIHTN + 131072;
constexpr size_t OFF_FCH   = OFF_WHHTN + 131072;              // 512x512 halves
constexpr size_t OFF_EL    = OFF_FCH + 131072;                // NN x 2
constexpr size_t OFF_ER    = OFF_EL + (size_t)NN * 2;
constexpr size_t OFF_HG    = OFF_ER + (size_t)NN * 2;         // GG x 512
constexpr size_t OFF_GCNT  = OFF_HG + (size_t)GG * 512;       // GG
// int regions
constexpr size_t OFF_DEG   = OFF_GCNT + GG;                   // NN ints
constexpr size_t OFF_RPTR  = OFF_DEG + NN;                    // NN+4 ints
constexpr size_t OFF_CUR   = OFF_RPTR + NN + 4;               // NN ints
constexpr size_t OFF_EIDX  = OFF_CUR + NN;                    // EE ints
constexpr size_t TOTAL_F   = OFF_EIDX + EE + 16;

__device__ __align__(16) float g_buf[TOTAL_F];

// ================= PTX helpers =================
__device__ __forceinline__ uint32_t smem_to_u32(const void* p) {
    uint32_t a;
    asm("{ .reg .u64 t; cvta.to.shared.u64 t, %1; cvt.u32.u64 %0, t; }" : "=r"(a) : "l"(p));
    return a;
}
__device__ __forceinline__ void ldsm_x4(uint32_t addr, uint32_t* r) {
    asm volatile("ldmatrix.sync.aligned.m8n8.x4.shared.b16 {%0,%1,%2,%3}, [%4];"
                 : "=r"(r[0]), "=r"(r[1]), "=r"(r[2]), "=r"(r[3]) : "r"(addr));
}
__device__ __forceinline__ void ldsm_x4_t(uint32_t addr, uint32_t* r) {
    asm volatile("ldmatrix.sync.aligned.m8n8.x4.trans.shared.b16 {%0,%1,%2,%3}, [%4];"
                 : "=r"(r[0]), "=r"(r[1]), "=r"(r[2]), "=r"(r[3]) : "r"(addr));
}
__device__ __forceinline__ void mma_f16(float* c, const uint32_t* a, const uint32_t* b) {
    asm volatile(
        "mma.sync.aligned.m16n8k16.row.col.f32.f16.f16.f32 "
        "{%0,%1,%2,%3},{%4,%5,%6,%7},{%8,%9},{%0,%1,%2,%3};"
        : "+f"(c[0]), "+f"(c[1]), "+f"(c[2]), "+f"(c[3])
        : "r"(a[0]), "r"(a[1]), "r"(a[2]), "r"(a[3]), "r"(b[0]), "r"(b[1]));
}
__device__ __forceinline__ __half2 h2rn(float x0, float x1) {
    return __halves2half2(__float2half_rn(x0), __float2half_rn(x1));
}
__device__ __forceinline__ void cpa16(uint32_t d, const void* g, int sz) {
    asm volatile("cp.async.cg.shared.global [%0], [%1], 16, %2;"
                 :: "r"(d), "l"(g), "r"(sz) : "memory");
}
__device__ __forceinline__ void cpa_commit() {
    asm volatile("cp.async.commit_group;" ::: "memory");
}
template <int N>
__device__ __forceinline__ void cpa_wait() {
    asm volatile("cp.async.wait_group %0;" :: "n"(N) : "memory");
}

// ================= SMEM layout for gemm (half-element offsets, 3 stages) =================
#define AS_PITCH 40
#define BS_PITCH 136
#define SM_AH(b) ((b) * 5120)                 // 3 x 5120 halves
#define SM_BH(b) (15360 + (b) * 4352)         // 3 x 4352 halves
#define SMEM_HALFS 28416
#define SMEM_BYTES (SMEM_HALFS * 2)

// ================= pure-fp16 HMMA GEMM core (3-stage cp.async) =================
// MODE 1: v = half(Cadd) + acc -> Oh fp16 ; MODE 2: Oh = fp16(acc)
template <int MODE>
__device__ __forceinline__ void gemm_core(
    const __half* __restrict__ A, int lda,
    const __half* __restrict__ B, int ldb,
    const __half* __restrict__ Cadd, int ldc,
    __half* __restrict__ Oh, int ldo,
    int M, int K, int n0) {
    extern __shared__ __half smh[];
    const uint32_t sbase = smem_to_u32(smh);

    const int tid = threadIdx.x;
    const int lane = tid & 31;
    const int wid = tid >> 5;
    const int wm = wid >> 2;
    const int wn = wid & 3;
    const int blockM = blockIdx.x * 128;

    const int ar = tid >> 1, ac = (tid & 1) * 16;
    const int bk = tid >> 3, bn = (tid & 7) * 16;
    const bool aval = (blockM + ar) < M;
    const int asz = aval ? 16 : 0;
    const __half* Ap = A + (size_t)(aval ? blockM + ar : 0) * lda + ac;
    const __half* Bp = B + (size_t)bk * ldb + n0 + bn;

    const uint32_t dA = sbase + 2 * (uint32_t)(ar * AS_PITCH + ac);
    const uint32_t dB = sbase + 2 * (uint32_t)(15360 + bk * BS_PITCH + bn);

    const int nC = K >> 5;

    float acc[4][4][4];
#pragma unroll
    for (int mi = 0; mi < 4; mi++)
#pragma unroll
        for (int ni = 0; ni < 4; ni++)
#pragma unroll
            for (int q = 0; q < 4; q++) acc[mi][ni][q] = 0.f;

    auto issue = [&](int c, int buf) {
        const int boffA = buf * 2 * 5120;
        const int boffB = buf * 2 * 4352;
        const __half* a = Ap + c * 32;
        const __half* b = Bp + (size_t)c * 32 * ldb;
        cpa16(dA + boffA, a, asz);
        cpa16(dA + boffA + 16, a + 8, asz);
        cpa16(dB + boffB, b, 16);
        cpa16(dB + boffB + 16, b + 8, 16);
        cpa_commit();
    };

    // prologue: prefetch chunks 0 and 1
    issue(0, 0);
    if (nC > 1) issue(1, 1);

    const int lrow = lane & 15;
    const int lhalf = (lane >> 4) * 8;

    int buf = 0;
    for (int c = 0; c < nC; c++) {
        if (c + 1 < nC) cpa_wait<1>();
        else cpa_wait<0>();
        __syncthreads();   // also separates last iter's compute from the issue below

        if (c + 2 < nC) {
            int nb = buf + 2;
            if (nb >= 3) nb -= 3;
            issue(c + 2, nb);
        }

        const int b = buf;
#pragma unroll
        for (int s = 0; s < 2; s++) {
            uint32_t bf[4][2];
#pragma unroll
            for (int np = 0; np < 2; np++) {
                uint32_t off = (uint32_t)((s * 16 + lrow) * BS_PITCH + wn * 32 + np * 16 + lhalf);
                uint32_t t[4];
                ldsm_x4_t(sbase + 2 * (SM_BH(b) + off), t);
                bf[2 * np][0] = t[0]; bf[2 * np][1] = t[1];
                bf[2 * np + 1][0] = t[2]; bf[2 * np + 1][1] = t[3];
            }
#pragma unroll
            for (int mi = 0; mi < 4; mi++) {
                uint32_t off = (uint32_t)((wm * 64 + mi * 16 + lrow) * AS_PITCH + s * 16 + lhalf);
                uint32_t af[4];
                ldsm_x4(sbase + 2 * (SM_AH(b) + off), af);
#pragma unroll
                for (int ni = 0; ni < 4; ni++) mma_f16(acc[mi][ni], af, bf[ni]);
            }
        }
        if (++buf == 3) buf = 0;
    }

    const int row0 = blockM + wm * 64;
    const int col0 = n0 + wn * 32;
#pragma unroll
    for (int mi = 0; mi < 4; mi++) {
        int r0 = row0 + mi * 16 + (lane >> 2);
        int r1 = r0 + 8;
#pragma unroll
        for (int ni = 0; ni < 4; ni++) {
            int cc = col0 + ni * 8 + (lane & 3) * 2;
#pragma unroll
            for (int h = 0; h < 2; h++) {
                int r = h ? r1 : r0;
                if (r >= M) continue;
                float v0 = acc[mi][ni][2 * h], v1 = acc[mi][ni][2 * h + 1];
                if (MODE == 1) {
                    float2 ci = __half22float2(*(const __half2*)(Cadd + (size_t)r * ldc + cc));
                    v0 += ci.x; v1 += ci.y;
                }
                *(__half2*)(Oh + (size_t)r * ldo + cc) = h2rn(v0, v1);
            }
        }
    }
}

__global__ __launch_bounds__(256, 2)
void gemm_add(const __half* __restrict__ A, int lda, const __half* __restrict__ B, int ldb,
              const __half* __restrict__ Cadd, int ldc, __half* __restrict__ Oh, int ldo,
              int M, int K) {
    gemm_core<1>(A, lda, B, ldb, Cadd, ldc, Oh, ldo, M, K, blockIdx.y * 128);
}

__global__ __launch_bounds__(256, 2)
void gemm_p(const __half* __restrict__ A, int lda, const __half* __restrict__ B, int ldb,
            __half* __restrict__ Oh, int ldo, int M, int K) {
    gemm_core<2>(A, lda, B, ldb, nullptr, 0, Oh, ldo, M, K, blockIdx.y * 128);
}

// merged P (y<8) + Qi (y>=8) launch; Kp = K for P (768 at step 0, else 1024)
__global__ __launch_bounds__(256, 2)
void gemm_pq(const __half* __restrict__ ahH, const __half* __restrict__ B1H,
             const __half* __restrict__ WihTn, __half* __restrict__ PH,
             __half* __restrict__ QiH, int M, int Kp) {
    if (blockIdx.y < 8) {
        gemm_core<2>(ahH, 1024, B1H, 1024, nullptr, 0, PH, 1024, M, Kp, blockIdx.y * 128);
    } else {
        gemm_core<2>(ahH, 1024, WihTn, 512, nullptr, 0, QiH, 512, M, 512,
                     (blockIdx.y - 8) * 128);
    }
}

// ================= misc =================
__device__ __forceinline__ float sigm(float x) { return 1.f / (1.f + expf(-x)); }

__global__ void zero_f4(float4* p, size_t n4) {
    size_t i = (size_t)blockIdx.x * blockDim.x + threadIdx.x;
    size_t st = (size_t)gridDim.x * blockDim.x;
    for (; i < n4; i += st) p[i] = make_float4(0.f, 0.f, 0.f, 0.f);
}

__global__ void conv_h(const float* __restrict__ in, __half* __restrict__ hi, size_t n2) {
    size_t i = (size_t)blockIdx.x * blockDim.x + threadIdx.x;
    size_t st = (size_t)gridDim.x * blockDim.x;
    for (; i < n2; i += st) {
        float2 v = *(const float2*)(in + 2 * i);
        *(__half2*)(hi + 2 * i) = h2rn(v.x, v.y);
    }
}

// WmH0[k*256+c][n] = Wmsg[(k*512+c)*512 + n], c<256 (step-0 nonzero rows)
__global__ void prep_wm0(const float* __restrict__ Wmsg, __half* __restrict__ hi) {
    int i = blockIdx.x * blockDim.x + threadIdx.x;
    int st = gridDim.x * blockDim.x;
    for (; i < 1024 * 256; i += st) {
        int kp = i >> 8;
        int n = (i & 255) * 2;
        int k = kp >> 8, c = kp & 255;
        const float* row = Wmsg + ((size_t)(k * 512 + c)) * 512;
        *(__half2*)(hi + (size_t)kp * 512 + n) = h2rn(row[n], row[n + 1]);
    }
}

// B1[k][n] fp16: k<512 -> w_ih[n][k], else w_hh[n][k-512]; n in 0..1023 (r,z rows)
__global__ void prep_b1_h(const float* __restrict__ w_ih, const float* __restrict__ w_hh,
                          __half* __restrict__ hi) {
    int i = blockIdx.x * blockDim.x + threadIdx.x;
    int st = gridDim.x * blockDim.x;
    for (; i < 1024 * 512; i += st) {
        int k = i >> 9;
        int n = (i & 511) * 2;
        float v0 = (k < 512) ? w_ih[(size_t)n * 512 + k] : w_hh[(size_t)n * 512 + k - 512];
        float v1 = (k < 512) ? w_ih[(size_t)(n + 1) * 512 + k] : w_hh[(size_t)(n + 1) * 512 + k - 512];
        *(__half2*)(hi + (size_t)k * 1024 + n) = h2rn(v0, v1);
    }
}

// T[k][n] fp16 = W[(rowoff+n)*512 + k], 512x512
__global__ void prep_t512_h(const float* __restrict__ W, int rowoff, __half* __restrict__ hi) {
    int i = blockIdx.x * blockDim.x + threadIdx.x;
    int st = gridDim.x * blockDim.x;
    for (; i < 512 * 256; i += st) {
        int k = i >> 8;
        int n = (i & 255) * 2;
        float v0 = W[(size_t)(rowoff + n) * 512 + k];
        float v1 = W[(size_t)(rowoff + n + 1) * 512 + k];
        *(__half2*)(hi + (size_t)k * 512 + n) = h2rn(v0, v1);
    }
}

// pad input -> h fp16 (ah cols 512..1023)
__global__ void pad_kernel(const float* __restrict__ x, __half* __restrict__ ahH) {
    int i = blockIdx.x * blockDim.x + threadIdx.x;
    int st = gridDim.x * blockDim.x;
    int tot = NN * 256;
    for (; i < tot; i += st) {
        int n = i >> 8;
        int c = (i & 255) * 2;
        float v0 = (c < INF_) ? x[(size_t)n * INF_ + c] : 0.f;
        float v1 = (c + 1 < INF_) ? x[(size_t)n * INF_ + c + 1] : 0.f;
        *(__half2*)(ahH + (size_t)n * 1024 + 512 + c) = h2rn(v0, v1);
    }
}

// ================= CSR build =================
__global__ void csr_count(const int* __restrict__ dst, int* __restrict__ deg) {
    int e = blockIdx.x * blockDim.x + threadIdx.x;
    if (e < EE) atomicAdd(&deg[dst[e]], 1);
}

__global__ void csr_scan(const int* __restrict__ deg, int* __restrict__ rowptr,
                         int* __restrict__ cursor) {
    __shared__ int part[1024];
    int t = threadIdx.x;
    int b = t * 20;
    int loc[20];
    int s = 0;
#pragma unroll
    for (int i = 0; i < 20; i++) {
        int n = b + i;
        loc[i] = (n < NN) ? deg[n] : 0;
        s += loc[i];
    }
    part[t] = s;
    __syncthreads();
    for (int off = 1; off < 1024; off <<= 1) {
        int v = (t >= off) ? part[t - off] : 0;
        __syncthreads();
        part[t] += v;
        __syncthreads();
    }
    int run = part[t] - s;
#pragma unroll
    for (int i = 0; i < 20; i++) {
        int n = b + i;
        if (n < NN) {
            rowptr[n] = run;
            cursor[n] = run;
            run += loc[i];
        }
    }
    if (t == 0) rowptr[NN] = EE;
}

__global__ void csr_scatter(const int* __restrict__ dst, int* __restrict__ cursor,
                            int* __restrict__ eidx) {
    int e = blockIdx.x * blockDim.x + threadIdx.x;
    if (e < EE) {
        int pos = atomicAdd(&cursor[dst[e]], 1);
        eidx[pos] = e;
    }
}

// ================= per-dst aggregate gather + bias fold (fp16 out) =================
template <int COMPACT>
__device__ __forceinline__ void agg_core(
    const __half* __restrict__ ahH, const int* __restrict__ src,
    const int* __restrict__ et, const int* __restrict__ rowptr,
    const int* __restrict__ eidx, const float* __restrict__ bmsg,
    __half* __restrict__ sH, __half* __restrict__ aH) {
    int d = blockIdx.x;
    int t = threadIdx.x;
    int beg = rowptr[d], end = rowptr[d + 1];
    int c = t * 4;
    const bool active = COMPACT ? (c < 256) : true;
    float4 acc[KT];
#pragma unroll
    for (int k = 0; k < KT; k++) acc[k] = make_float4(0.f, 0.f, 0.f, 0.f);
    int cn[KT] = {0, 0, 0, 0};

    __shared__ int ssrc[128];
    __shared__ int sket[128];
    for (int base = beg; base < end; base += 128) {
        int jj = base + t;
        if (jj < end) {
            int e = eidx[jj];
            ssrc[t] = src[e];
            sket[t] = et[e];
        }
        __syncthreads();
        int m = min(128, end - base);
#pragma unroll 2
        for (int q = 0; q < m; q++) {
            int k = sket[q];
#pragma unroll
            for (int kk = 0; kk < KT; kk++)
                if (k == kk) cn[kk]++;
            if (active) {
                int s = ssrc[q];
                uint2 u = *(const uint2*)(ahH + (size_t)s * 1024 + 512 + c);
                float2 f0 = __half22float2(*(__half2*)&u.x);
                float2 f1 = __half22float2(*(__half2*)&u.y);
#pragma unroll
                for (int kk = 0; kk < KT; kk++) {
                    if (k == kk) {
                        acc[kk].x += f0.x; acc[kk].y += f0.y;
                        acc[kk].z += f1.x; acc[kk].w += f1.y;
                    }
                }
            }
        }
        __syncthreads();
    }
    if (active) {
#pragma unroll
        for (int k = 0; k < KT; k++) {
            size_t o = COMPACT ? ((size_t)d * 1024 + k * 256 + c)
                               : ((size_t)d * 2048 + k * 512 + c);
            *(__half2*)(sH + o) = h2rn(acc[k].x, acc[k].y);
            *(__half2*)(sH + o + 2) = h2rn(acc[k].z, acc[k].w);
        }
    }
    float f0 = (float)cn[0], f1 = (float)cn[1], f2 = (float)cn[2], f3 = (float)cn[3];
    float b0 = f0 * bmsg[c + 0] + f1 * bmsg[512 + c + 0] + f2 * bmsg[1024 + c + 0] + f3 * bmsg[1536 + c + 0];
    float b1 = f0 * bmsg[c + 1] + f1 * bmsg[512 + c + 1] + f2 * bmsg[1024 + c + 1] + f3 * bmsg[1536 + c + 1];
    float b2 = f0 * bmsg[c + 2] + f1 * bmsg[512 + c + 2] + f2 * bmsg[1024 + c + 2] + f3 * bmsg[1536 + c + 2];
    float b3 = f0 * bmsg[c + 3] + f1 * bmsg[512 + c + 3] + f2 * bmsg[1024 + c + 3] + f3 * bmsg[1536 + c + 3];
    *(__half2*)(aH + (size_t)d * 512 + c) = h2rn(b0, b1);
    *(__half2*)(aH + (size_t)d * 512 + c + 2) = h2rn(b2, b3);
}

__global__ __launch_bounds__(128)
void agg_gather(const __half* __restrict__ ahH, const int* __restrict__ src,
                const int* __restrict__ et, const int* __restrict__ rowptr,
                const int* __restrict__ eidx, const float* __restrict__ bmsg,
                __half* __restrict__ sH, __half* __restrict__ aH) {
    agg_core<0>(ahH, src, et, rowptr, eidx, bmsg, sH, aH);
}

__global__ __launch_bounds__(128)
void agg_gather0(const __half* __restrict__ ahH, const int* __restrict__ src,
                 const int* __restrict__ et, const int* __restrict__ rowptr,
                 const int* __restrict__ eidx, const float* __restrict__ bmsg,
                 __half* __restrict__ sH, __half* __restrict__ aH) {
    agg_core<1>(ahH, src, et, rowptr, eidx, bmsg, sH, aH);
}

// GRU pointwise: reads fp16 P (1024), Qi/Qh (512), old h from ahH; writes h fp16
__global__ void gru_kernel(const __half* __restrict__ PH, const __half* __restrict__ QiH,
                           const __half* __restrict__ QhH,
                           const float* __restrict__ b_ih, const float* __restrict__ b_hh,
                           __half* __restrict__ ahH) {
    int i = blockIdx.x * blockDim.x + threadIdx.x;
    int st = gridDim.x * blockDim.x;
    int tot = NN * 256;
    for (; i < tot; i += st) {
        int n = i >> 8;
        int c = (i & 255) * 2;
        float2 pr = __half22float2(*(const __half2*)(PH + (size_t)n * 1024 + c));
        float2 pz = __half22float2(*(const __half2*)(PH + (size_t)n * 1024 + 512 + c));
        float2 qi = __half22float2(*(const __half2*)(QiH + (size_t)n * 512 + c));
        float2 qh = __half22float2(*(const __half2*)(QhH + (size_t)n * 512 + c));
        __half2* hp = (__half2*)(ahH + (size_t)n * 1024 + 512 + c);
        float2 ho = __half22float2(*hp);
        float prr[2] = {pr.x, pr.y}, pzz[2] = {pz.x, pz.y};
        float qii[2] = {qi.x, qi.y}, qhh[2] = {qh.x, qh.y};
        float hoo[2] = {ho.x, ho.y};
        float hv[2];
#pragma unroll
        for (int u = 0; u < 2; u++) {
            int cc = c + u;
            float r = sigm(prr[u] + b_ih[cc] + b_hh[cc]);
            float z = sigm(pzz[u] + b_ih[512 + cc] + b_hh[512 + cc]);
            float nn = tanhf(qii[u] + b_ih[1024 + cc] + r * (qhh[u] + b_hh[1024 + cc]));
            hv[u] = (1.f - z) * nn + z * hoo[u];
        }
        *hp = h2rn(hv[0], hv[1]);
    }
}

// L2-normalize + sigmoid over h fp16 (in place)
__global__ void norm_sig_kernel(__half* __restrict__ ahH) {
    int n = blockIdx.x;
    int t = threadIdx.x;  // 128
    __half2* row = (__half2*)(ahH + (size_t)n * 1024 + 512);
    __half2 a = row[2 * t], b = row[2 * t + 1];
    float2 f0 = __half22float2(a), f1 = __half22float2(b);
    float s = f0.x * f0.x + f0.y * f0.y + f1.x * f1.x + f1.y * f1.y;
    __shared__ float sm[128];
    sm[t] = s;
    __syncthreads();
    for (int o = 64; o > 0; o >>= 1) {
        if (t < o) sm[t] += sm[t + o];
        __syncthreads();
    }
    float inv = 1.f / fmaxf(sqrtf(sm[0]), 1e-12f);
    row[2 * t] = h2rn(sigm(f0.x * inv), sigm(f0.y * inv));
    row[2 * t + 1] = h2rn(sigm(f1.x * inv), sigm(f1.y * inv));
}

__global__ void elr_kernel(const __half* __restrict__ featH, const float* __restrict__ attn_l,
                           const float* __restrict__ attn_r,
                           float* __restrict__ el, float* __restrict__ er) {
    int n = blockIdx.x;
    int t = threadIdx.x;  // 256
    float f0 = __half2float(featH[(size_t)n * H1 + t]);
    float f1 = __half2float(featH[(size_t)n * H1 + H2C + t]);
    float vals[4] = {f0 * attn_l[t], f0 * attn_r[t], f1 * attn_l[H2C + t], f1 * attn_r[H2C + t]};
    float outp[4];
    __shared__ float sm[256];
#pragma unroll
    for (int q = 0; q < 4; q++) {
        sm[t] = vals[q];
        __syncthreads();
        for (int o = 128; o > 0; o >>= 1) {
            if (t < o) sm[t] += sm[t + o];
            __syncthreads();
        }
        outp[q] = sm[0];
        __syncthreads();
    }
    if (t == 0) {
        el[n * 2] = outp[0];
        er[n * 2] = outp[1];
        el[n * 2 + 1] = outp[2];
        er[n * 2 + 1] = outp[3];
    }
}

// ================= single-pass fused GAT per-dst =================
__global__ __launch_bounds__(128)
void gat_fused(const int* __restrict__ src, const int* __restrict__ rowptr,
               const int* __restrict__ eidx, const float* __restrict__ el,
               const float* __restrict__ er, const __half* __restrict__ featH,
               const int* __restrict__ gid, const float* __restrict__ gat_bias,
               float* __restrict__ hg, float* __restrict__ gcnt) {
    int d = blockIdx.x;
    int t = threadIdx.x;
    int beg = rowptr[d], end = rowptr[d + 1];
    float er0 = er[2 * d], er1 = er[2 * d + 1];

    __shared__ float sal0[128], sal1[128];
    __shared__ int ssrc[128];
    int c = t * 4;
    bool head0 = c < H2C;
    float4 acc = make_float4(0.f, 0.f, 0.f, 0.f);
    float dsum = 0.f;
    for (int base = beg; base < end; base += 128) {
        int jj = base + t;
        if (jj < end) {
            int s = src[eidx[jj]];
            float v0 = el[2 * s] + er0;      v0 = v0 > 0.f ? v0 : 0.2f * v0;
            float v1 = el[2 * s + 1] + er1;  v1 = v1 > 0.f ? v1 : 0.2f * v1;
            sal0[t] = expf(v0);
            sal1[t] = expf(v1);
            ssrc[t] = s;
        }
        __syncthreads();
        int m = min(128, end - base);
        for (int q = 0; q < m; q++) {
            float w = head0 ? sal0[q] : sal1[q];
            dsum += w;
            uint2 u = *(const uint2*)(featH + (size_t)ssrc[q] * 512 + c);
            float2 f0 = __half22float2(*(__half2*)&u.x);
            float2 f1 = __half22float2(*(__half2*)&u.y);
            acc.x += w * f0.x; acc.y += w * f0.y;
            acc.z += w * f1.x; acc.w += w * f1.y;
        }
        __syncthreads();
    }
    float invd = (dsum > 0.f) ? 1.f / dsum : 0.f;
    float4 b = *(const float4*)(gat_bias + c);
    int g = gid[d];
    atomicAdd(&hg[(size_t)g * 512 + c + 0], fmaxf(acc.x * invd + b.x, 0.f));
    atomicAdd(&hg[(size_t)g * 512 + c + 1], fmaxf(acc.y * invd + b.y, 0.f));
    atomicAdd(&hg[(size_t)g * 512 + c + 2], fmaxf(acc.z * invd + b.z, 0.f));
    atomicAdd(&hg[(size_t)g * 512 + c + 3], fmaxf(acc.w * invd + b.w, 0.f));
    if (t == 0) atomicAdd(&gcnt[g], 1.f);
}

__global__ void final_kernel(const float* __restrict__ hg, const float* __restrict__ gcnt,
                             const float* __restrict__ cw, const float* __restrict__ cb,
                             float* __restrict__ out) {
    int g = blockIdx.x >> 1, hd = blockIdx.x & 1;
    int t = threadIdx.x;  // 256
    __shared__ float row[H2C];
    float inv = 1.f / fmaxf(gcnt[g], 1.f);
    row[t] = hg[(size_t)g * H1 + hd * H2C + t] * inv;
    __syncthreads();
    if (t < CC) {
        float s = cb[t];
        for (int j = 0; j < H2C; j++) s += row[j] * cw[t * H2C + j];
        out[((size_t)g * HEADS + hd) * CC + t] = s;
    }
}

// ================= launch =================
extern "C" void kernel_launch(void* const* d_in, const int* in_sizes, int n_in,
                              void* d_out, int out_size) {
    const float* in_feat  = (const float*)d_in[0];
    const int*   src      = (const int*)d_in[1];
    const int*   dst      = (const int*)d_in[2];
    const int*   etype    = (const int*)d_in[3];
    const int*   gid      = (const int*)d_in[4];
    const float* Wmsg     = (const float*)d_in[5];
    const float* bmsg     = (const float*)d_in[6];
    const float* w_ih     = (const float*)d_in[7];
    const float* w_hh     = (const float*)d_in[8];
    const float* b_ih     = (const float*)d_in[9];
    const float* b_hh     = (const float*)d_in[10];
    const float* fc_w     = (const float*)d_in[11];
    const float* attn_l   = (const float*)d_in[12];
    const float* attn_r   = (const float*)d_in[13];
    const float* gat_bias = (const float*)d_in[14];
    const float* cw       = (const float*)d_in[15];
    const float* cb       = (const float*)d_in[16];
    float* out = (float*)d_out;

    cudaFuncSetAttribute(gemm_add, cudaFuncAttributeMaxDynamicSharedMemorySize, SMEM_BYTES);
    cudaFuncSetAttribute(gemm_p, cudaFuncAttributeMaxDynamicSharedMemorySize, SMEM_BYTES);
    cudaFuncSetAttribute(gemm_pq, cudaFuncAttributeMaxDynamicSharedMemorySize, SMEM_BYTES);

    static cudaStream_t s2 = nullptr;
    static cudaEvent_t evFork = nullptr, evJoin = nullptr;
    if (!s2) {
        cudaStreamCreateWithFlags(&s2, cudaStreamNonBlocking);
        cudaEventCreateWithFlags(&evFork, cudaEventDisableTiming);
        cudaEventCreateWithFlags(&evJoin, cudaEventDisableTiming);
    }

    float* base = nullptr;
    cudaGetSymbolAddress((void**)&base, g_buf);

    __half* aH    = (__half*)(base + OFF_AH);
    __half* PH    = (__half*)(base + OFF_PH);
    __half* QiH   = (__half*)(base + OFF_QIH);
    __half* QhH   = (__half*)(base + OFF_QHH);
    __half* featH = (__half*)(base + OFF_FEATH);
    __half* ahH   = (__half*)(base + OFF_AHH);
    __half* sH    = (__half*)(base + OFF_SAGH);
    __half* WmH   = (__half*)(base + OFF_WMH);
    __half* WmH0  = (__half*)(base + OFF_WMH0);
    __half* B1H   = (__half*)(base + OFF_B1H);
    __half* WihTn = (__half*)(base + OFF_WIHTN);
    __half* WhhTn = (__half*)(base + OFF_WHHTN);
    __half* FcH   = (__half*)(base + OFF_FCH);
    float*  el    = base + OFF_EL;
    float*  er    = base + OFF_ER;
    float*  hg    = base + OFF_HG;
    float*  gcnt  = base + OFF_GCNT;
    int*    deg   = (int*)(base + OFF_DEG);
    int*    rptr  = (int*)(base + OFF_RPTR);
    int*    cur   = (int*)(base + OFF_CUR);
    int*    eidx  = (int*)(base + OFF_EIDX);

    conv_h<<<512, 256>>>(Wmsg, WmH, (size_t)2048 * 512 / 2);
    prep_wm0<<<256, 256>>>(Wmsg, WmH0);
    prep_b1_h<<<512, 256>>>(w_ih, w_hh, B1H);
    prep_t512_h<<<256, 256>>>(w_ih, 1024, WihTn);
    prep_t512_h<<<256, 256>>>(w_hh, 1024, WhhTn);
    prep_t512_h<<<256, 256>>>(fc_w, 0, FcH);
    pad_kernel<<<4096, 256>>>(in_feat, ahH);

    zero_f4<<<32, 256>>>((float4*)deg, NN / 4);
    csr_count<<<(EE + 255) / 256, 256>>>(dst, deg);
    csr_scan<<<1, 1024>>>(deg, rptr, cur);
    csr_scatter<<<(EE + 255) / 256, 256>>>(dst, cur, eidx);

    const int GM = (NN + 127) / 128;  // 157

    for (int step = 0; step < NSTEPS; step++) {
        // fork: Qh = h @ w_hh_n^T (depends on h only; step 0: K=256)
        cudaEventRecord(evFork, 0);
        cudaStreamWaitEvent(s2, evFork, 0);
        gemm_p<<<dim3(GM, 4), 256, SMEM_BYTES, s2>>>(ahH + 512, 1024, WhhTn, 512, QhH, 512,
                                                     NN, step == 0 ? 256 : 512);
        cudaEventRecord(evJoin, s2);

        // main stream: aggregate, a-GEMM, merged P+Qi
        if (step == 0) {
            agg_gather0<<<NN, 128>>>(ahH, src, etype, rptr, eidx, bmsg, sH, aH);
            gemm_add<<<dim3(GM, 4), 256, SMEM_BYTES>>>(sH, 1024, WmH0, 512, aH, 512, ahH, 1024,
                                                       NN, 1024);
        } else {
            agg_gather<<<NN, 128>>>(ahH, src, etype, rptr, eidx, bmsg, sH, aH);
            gemm_add<<<dim3(GM, 4), 256, SMEM_BYTES>>>(sH, 2048, WmH, 512, aH, 512, ahH, 1024,
                                                       NN, 2048);
        }
        // merged: P (y<8, K=768/1024) + Qi (y>=8, K=512) in one launch
        gemm_pq<<<dim3(GM, 12), 256, SMEM_BYTES>>>(ahH, B1H, WihTn, PH, QiH, NN,
                                                   step == 0 ? 768 : 1024);

        cudaStreamWaitEvent(0, evJoin, 0);
        gru_kernel<<<4096, 256>>>(PH, QiH, QhH, b_ih, b_hh, ahH);
    }

    norm_sig_kernel<<<NN, 128>>>(ahH);
    gemm_p<<<dim3(GM, 4), 256, SMEM_BYTES>>>(ahH + 512, 1024, FcH, 512, featH, 512, NN, 512);
    elr_kernel<<<NN, 256>>>(featH, attn_l, attn_r, el, er);

    zero_f4<<<32, 256>>>((float4*)hg, ((size_t)GG * 512 + GG) / 4);
    gat_fused<<<NN, 128>>>(src, rptr, eidx, el, er, featH, gid, gat_bias, hg, gcnt);
    final_kernel<<<GG * HEADS, 256>>>(hg, gcnt, cw, cb, out);
}